// round 10
// baseline (speedup 1.0000x reference)
#include <cuda_runtime.h>
#include <cuda_bf16.h>
#include <math.h>
#include <stdint.h>

#define Bn 512
#define Ln 50
#define Nn 64
#define En 16
#define Hn 128
#define Dn 256
#define ITEMN 100000
#define ITEMP 100096
#define EPS 1e-12f

// ------------------------- scratch (no allocs allowed) -------------------------
// NOTE: device globals are ONLY referenced inside device code. Never passed as
// kernel arguments from host (that was the R5/R6 bug).
__device__ float g_nh_f32[32768 * 128];
__device__ __nv_bfloat16 g_eagg_hi[8192 * 128], g_eagg_lo[8192 * 128];
__device__ float g_eh_f32[8192 * 128];
__device__ __nv_bfloat16 g_nagg_hi[32768 * 128], g_nagg_lo[32768 * 128];
__device__ float g_seq_f32[25600 * 256];
__device__ __nv_bfloat16 g_seq_hi[25600 * 256], g_seq_lo[25600 * 256];
__device__ float g_q2[25600 * 256];
__device__ __nv_bfloat16 g_wet_hi[128 * 128], g_wet_lo[128 * 128];
__device__ __nv_bfloat16 g_wnt_hi[128 * 128], g_wnt_lo[128 * 128];
__device__ __nv_bfloat16 g_q2t_hi[256 * 256], g_q2t_lo[256 * 256];
__device__ __nv_bfloat16 g_so_hi[Bn * Dn], g_so_lo[Bn * Dn];
__device__ __nv_bfloat16 g_item_hi[(size_t)ITEMP * Dn];
__device__ __nv_bfloat16 g_item_lo[(size_t)ITEMP * Dn];

// ============================= PTX helpers =============================
__device__ __forceinline__ uint32_t smem_u32(const void* p) {
    uint32_t a;
    asm("{ .reg .u64 t; cvta.to.shared.u64 t, %1; cvt.u32.u64 %0, t; }" : "=r"(a) : "l"(p));
    return a;
}
__device__ __forceinline__ void cp16(uint32_t dst, const void* src) {
    asm volatile("cp.async.cg.shared.global [%0], [%1], 16;" :: "r"(dst), "l"(src));
}
#define CP_COMMIT() asm volatile("cp.async.commit_group;" ::: "memory")
#define CP_WAIT(n)  asm volatile("cp.async.wait_group %0;" :: "n"(n) : "memory")

__device__ __forceinline__ void ldsm4(uint32_t* r, uint32_t addr) {
    asm volatile("ldmatrix.sync.aligned.m8n8.x4.shared.b16 {%0,%1,%2,%3}, [%4];"
                 : "=r"(r[0]), "=r"(r[1]), "=r"(r[2]), "=r"(r[3]) : "r"(addr));
}
__device__ __forceinline__ void mma16816(float* d, const uint32_t* a, const uint32_t* b) {
    asm volatile(
        "mma.sync.aligned.m16n8k16.row.col.f32.bf16.bf16.f32 "
        "{%0,%1,%2,%3}, {%4,%5,%6,%7}, {%8,%9}, {%0,%1,%2,%3};"
        : "+f"(d[0]), "+f"(d[1]), "+f"(d[2]), "+f"(d[3])
        : "r"(a[0]), "r"(a[1]), "r"(a[2]), "r"(a[3]), "r"(b[0]), "r"(b[1]));
}
__device__ __forceinline__ void sthilo(__nv_bfloat16* hi, __nv_bfloat16* lo,
                                       size_t idx, float v) {
    __nv_bfloat16 h = __float2bfloat16_rn(v);
    hi[idx] = h;
    lo[idx] = __float2bfloat16_rn(v - __bfloat162float(h));
}
__device__ __forceinline__ void store4_hilo(__nv_bfloat16* hi, __nv_bfloat16* lo,
                                            int c, float4 v) {
    __nv_bfloat16 h0 = __float2bfloat16_rn(v.x), h1 = __float2bfloat16_rn(v.y);
    __nv_bfloat16 h2 = __float2bfloat16_rn(v.z), h3 = __float2bfloat16_rn(v.w);
    *(__nv_bfloat162*)(hi + c)     = __halves2bfloat162(h0, h1);
    *(__nv_bfloat162*)(hi + c + 2) = __halves2bfloat162(h2, h3);
    __nv_bfloat16 l0 = __float2bfloat16_rn(v.x - __bfloat162float(h0));
    __nv_bfloat16 l1 = __float2bfloat16_rn(v.y - __bfloat162float(h1));
    __nv_bfloat16 l2 = __float2bfloat16_rn(v.z - __bfloat162float(h2));
    __nv_bfloat16 l3 = __float2bfloat16_rn(v.w - __bfloat162float(h3));
    *(__nv_bfloat162*)(lo + c)     = __halves2bfloat162(l0, l1);
    *(__nv_bfloat162*)(lo + c + 2) = __halves2bfloat162(l2, l3);
}

// =============================================================================
// Shared split-bf16 HMMA GEMM body: C[M,N] = Ahi/lo[M,K] . (Whi/lo[N,K])^T
// 3-term. CTA tile 128x128, K chunks of 32, cp.async double-buffered.
// All pointers supplied by device-side wrappers (never from host).
// =============================================================================
#define ROWB 80
#define MATB (128 * ROWB)
#define BUFB (4 * MATB)
#define SC_SMEM (2 * BUFB)

template<int KTOT, int N>
__device__ __forceinline__ void gemm3_body(
    const __nv_bfloat16* __restrict__ Ahi, const __nv_bfloat16* __restrict__ Alo,
    const __nv_bfloat16* __restrict__ Whi, const __nv_bfloat16* __restrict__ Wlo,
    float* __restrict__ C) {
    extern __shared__ char smc[];
    const uint32_t sb = smem_u32(smc);
    const int t = threadIdx.x;
    const int w = t >> 5, lane = t & 31;
    const int m0 = blockIdx.x * 128;
    const int n0 = blockIdx.y * 128;
    const int warp_m = w & 3;
    const int warp_n = w >> 2;

    const __nv_bfloat16* srcs[4] = {
        Ahi + (size_t)m0 * KTOT, Alo + (size_t)m0 * KTOT,
        Whi + (size_t)n0 * KTOT, Wlo + (size_t)n0 * KTOT
    };
    const int ld_row0 = t >> 2,  ld_row1 = 64 + (t >> 2), ld_seg = t & 3;

    float acc[2][8][4];
    #pragma unroll
    for (int i = 0; i < 2; i++)
        #pragma unroll
        for (int j = 0; j < 8; j++)
            #pragma unroll
            for (int r = 0; r < 4; r++) acc[i][j][r] = 0.f;

    const uint32_t aA_lane = (uint32_t)((lane & 15) * ROWB + (lane >> 4) * 16);
    const uint32_t aB_lane = (uint32_t)(((lane & 7) + ((lane >> 4) & 1) * 8) * ROWB
                                        + ((lane >> 3) & 1) * 16);

    #pragma unroll
    for (int mat = 0; mat < 4; mat++) {
        cp16(sb + 0 * BUFB + mat * MATB + ld_row0 * ROWB + ld_seg * 16,
             srcs[mat] + (size_t)ld_row0 * KTOT + ld_seg * 8);
        cp16(sb + 0 * BUFB + mat * MATB + ld_row1 * ROWB + ld_seg * 16,
             srcs[mat] + (size_t)ld_row1 * KTOT + ld_seg * 8);
    }
    CP_COMMIT();

    const int NCH = KTOT / 32;
    for (int kc = 0; kc < NCH; kc++) {
        const int buf = kc & 1;
        if (kc < NCH - 1) {
            const int k0 = (kc + 1) * 32;
            const int nbuf = (kc + 1) & 1;
            #pragma unroll
            for (int mat = 0; mat < 4; mat++) {
                cp16(sb + nbuf * BUFB + mat * MATB + ld_row0 * ROWB + ld_seg * 16,
                     srcs[mat] + (size_t)ld_row0 * KTOT + k0 + ld_seg * 8);
                cp16(sb + nbuf * BUFB + mat * MATB + ld_row1 * ROWB + ld_seg * 16,
                     srcs[mat] + (size_t)ld_row1 * KTOT + k0 + ld_seg * 8);
            }
            CP_COMMIT();
            CP_WAIT(1);
        } else {
            CP_WAIT(0);
        }
        __syncthreads();

        const uint32_t baseA = sb + buf * BUFB + (uint32_t)(warp_m * 32) * ROWB + aA_lane;
        const uint32_t baseB = sb + buf * BUFB + (uint32_t)(warp_n * 64) * ROWB + aB_lane;

        #pragma unroll
        for (int ks = 0; ks < 2; ks++) {
            const uint32_t koff = (uint32_t)ks * 32;
            uint32_t ahi[2][4], alo[2][4];
            #pragma unroll
            for (int i = 0; i < 2; i++) {
                ldsm4(ahi[i], baseA + 0 * MATB + (uint32_t)(i * 16) * ROWB + koff);
                ldsm4(alo[i], baseA + 1 * MATB + (uint32_t)(i * 16) * ROWB + koff);
            }
            #pragma unroll
            for (int jg = 0; jg < 2; jg++) {
                uint32_t bhi[2][4], blo[2][4];
                #pragma unroll
                for (int j4 = 0; j4 < 2; j4++) {
                    const uint32_t off = (uint32_t)((jg * 2 + j4) * 16) * ROWB + koff;
                    ldsm4(bhi[j4], baseB + 2 * MATB + off);
                    ldsm4(blo[j4], baseB + 3 * MATB + off);
                }
                #pragma unroll
                for (int i = 0; i < 2; i++)
                    #pragma unroll
                    for (int jj = 0; jj < 4; jj++) {
                        const int j = jg * 4 + jj;
                        const uint32_t* bh = &bhi[jj >> 1][(jj & 1) * 2];
                        const uint32_t* bl = &blo[jj >> 1][(jj & 1) * 2];
                        mma16816(acc[i][j], ahi[i], bh);
                        mma16816(acc[i][j], ahi[i], bl);
                        mma16816(acc[i][j], alo[i], bh);
                    }
            }
        }
        __syncthreads();
    }

    const int mrow = m0 + warp_m * 32 + (lane >> 2);
    const int ncol = n0 + warp_n * 64 + (lane & 3) * 2;
    #pragma unroll
    for (int i = 0; i < 2; i++) {
        #pragma unroll
        for (int j = 0; j < 8; j++) {
            const int m = mrow + i * 16;
            const int n = ncol + j * 8;
            *(float2*)(C + (size_t)m * N + n)       = make_float2(acc[i][j][0], acc[i][j][1]);
            *(float2*)(C + (size_t)(m + 8) * N + n) = make_float2(acc[i][j][2], acc[i][j][3]);
        }
    }
}

// device-side wrappers (globals referenced IN device code)
__global__ void __launch_bounds__(256, 2) gemm3_eh() {
    gemm3_body<128, 128>(g_eagg_hi, g_eagg_lo, g_wet_hi, g_wet_lo, g_eh_f32);
}
__global__ void __launch_bounds__(256, 2) gemm3_nh() {
    gemm3_body<128, 128>(g_nagg_hi, g_nagg_lo, g_wnt_hi, g_wnt_lo, g_nh_f32);
}
__global__ void __launch_bounds__(256, 2) gemm3_q2() {
    gemm3_body<256, 256>(g_seq_hi, g_seq_lo, g_q2t_hi, g_q2t_lo, g_q2);
}

// =============================================================================
// prep_w: transpose + split w_edge/w_node [128,128] and q2_w [256,256]
// =============================================================================
__global__ void __launch_bounds__(256)
prep_w(const float* __restrict__ w_edge, const float* __restrict__ w_node,
       const float* __restrict__ q2_w) {
    const int idx = blockIdx.x * 256 + threadIdx.x;
    if (idx < 16384) {
        const int k = idx >> 7, n = idx & 127;
        sthilo(g_wet_hi, g_wet_lo, (size_t)n * 128 + k, w_edge[idx]);
    } else if (idx < 32768) {
        const int i2 = idx - 16384;
        const int k = i2 >> 7, n = i2 & 127;
        sthilo(g_wnt_hi, g_wnt_lo, (size_t)n * 128 + k, w_node[i2]);
    } else if (idx < 98304) {
        const int i2 = idx - 32768;
        const int k = i2 >> 8, n = i2 & 255;
        sthilo(g_q2t_hi, g_q2t_lo, (size_t)n * 256 + k, q2_w[i2]);
    }
}

// =============================================================================
// init_norm: n_h0 = l2norm(embedding[nodes]) (warp per row, fp32)
// =============================================================================
__global__ void __launch_bounds__(256)
init_norm(const int* __restrict__ nodes, const float* __restrict__ embedding) {
    const int r = blockIdx.x * 8 + (threadIdx.x >> 5);
    const int lane = threadIdx.x & 31;
    if (r >= Bn * Nn) return;
    const int idx = nodes[r];
    const float4 v = ((const float4*)(embedding + (size_t)idx * Hn))[lane];
    float ss = v.x * v.x + v.y * v.y + v.z * v.z + v.w * v.w;
    #pragma unroll
    for (int o = 16; o > 0; o >>= 1) ss += __shfl_xor_sync(0xffffffffu, ss, o);
    const float inv = 1.0f / fmaxf(sqrtf(ss), EPS);
    ((float4*)(g_nh_f32 + (size_t)r * Hn))[lane] =
        make_float4(v.x * inv, v.y * inv, v.z * inv, v.w * inv);
}

// =============================================================================
// agg_e: eagg[(b,e),d] = (sum_n adj[b,n,e]*nh[(b,n),d]) / deg_e -> bf16 hi/lo
// =============================================================================
__global__ void __launch_bounds__(256, 2)
agg_e_kernel(const float* __restrict__ hn_adj) {
    __shared__ float s_nh[64 * 132];
    __shared__ float s_adj[Nn * En];
    __shared__ float s_dege[En];
    const int b = blockIdx.x;
    const int t = threadIdx.x;

    {
        const float* adjb = hn_adj + (size_t)b * Nn * En;
        for (int i = t; i < Nn * En; i += 256) s_adj[i] = adjb[i];
        const float4* src = (const float4*)(g_nh_f32 + (size_t)b * Nn * Hn);
        for (int f = t; f < Nn * Hn / 4; f += 256) {
            const int row = f >> 5, c4 = f & 31;
            ((float4*)(s_nh + row * 132))[c4] = src[f];
        }
    }
    __syncthreads();
    if (t < En) {
        float s = 0.f;
        #pragma unroll 8
        for (int n = 0; n < Nn; n++) s += s_adj[n * En + t];
        s_dege[t] = fmaxf(s, 1.0f);
    }
    __syncthreads();

    const int d = t & 127;
    for (int e = t >> 7; e < En; e += 2) {
        float acc = 0.f;
        #pragma unroll 8
        for (int n = 0; n < Nn; n++) acc += s_adj[n * En + e] * s_nh[n * 132 + d];
        sthilo(g_eagg_hi, g_eagg_lo, (size_t)(b * En + e) * Hn + d, acc / s_dege[e]);
    }
}

// =============================================================================
// agg_n: nagg[(b,n),d] = (sum_e adj[b,n,e]*eh[(b,e),d]) / deg_n -> bf16 hi/lo
// =============================================================================
__global__ void __launch_bounds__(256, 2)
agg_n_kernel(const float* __restrict__ hn_adj) {
    __shared__ float s_eh[En * 132];
    __shared__ float s_adj[Nn * En];
    __shared__ float s_degn[Nn];
    const int b = blockIdx.x;
    const int t = threadIdx.x;

    {
        const float* adjb = hn_adj + (size_t)b * Nn * En;
        for (int i = t; i < Nn * En; i += 256) s_adj[i] = adjb[i];
        const float4* src = (const float4*)(g_eh_f32 + (size_t)b * En * Hn);
        for (int f = t; f < En * Hn / 4; f += 256) {
            const int row = f >> 5, c4 = f & 31;
            ((float4*)(s_eh + row * 132))[c4] = src[f];
        }
    }
    __syncthreads();
    if (t < Nn) {
        float s = 0.f;
        #pragma unroll
        for (int e = 0; e < En; e++) s += s_adj[t * En + e];
        s_degn[t] = fmaxf(s, 1.0f);
    }
    __syncthreads();

    const int d = t & 127;
    for (int n = t >> 7; n < Nn; n += 2) {
        float acc = 0.f;
        #pragma unroll
        for (int e = 0; e < En; e++) acc += s_adj[n * En + e] * s_eh[e * 132 + d];
        sthilo(g_nagg_hi, g_nagg_lo, (size_t)(b * Nn + n) * Hn + d, acc / s_degn[n]);
    }
}

// =============================================================================
// seqbuild: seq[(b,l)] = l2norm(concat(nh[b,ai], nh[b,ac])) -> fp32 + hi/lo
// =============================================================================
__global__ void __launch_bounds__(256)
seqbuild(const int* __restrict__ alias_item, const int* __restrict__ alias_cate) {
    const int rr = blockIdx.x * 8 + (threadIdx.x >> 5);
    const int lane = threadIdx.x & 31;
    if (rr >= Bn * Ln) return;
    const int b = rr / Ln;
    const int ai = alias_item[rr];
    const int ac = alias_cate[rr];
    const float4 vi = ((const float4*)(g_nh_f32 + (size_t)(b * Nn + ai) * Hn))[lane];
    const float4 vc = ((const float4*)(g_nh_f32 + (size_t)(b * Nn + ac) * Hn))[lane];
    float ss = vi.x*vi.x + vi.y*vi.y + vi.z*vi.z + vi.w*vi.w
             + vc.x*vc.x + vc.y*vc.y + vc.z*vc.z + vc.w*vc.w;
    #pragma unroll
    for (int o = 16; o > 0; o >>= 1) ss += __shfl_xor_sync(0xffffffffu, ss, o);
    const float inv = 1.0f / fmaxf(sqrtf(ss), EPS);
    const float4 ni = make_float4(vi.x*inv, vi.y*inv, vi.z*inv, vi.w*inv);
    const float4 nc = make_float4(vc.x*inv, vc.y*inv, vc.z*inv, vc.w*inv);
    ((float4*)(g_seq_f32 + (size_t)rr * Dn))[lane]      = ni;
    ((float4*)(g_seq_f32 + (size_t)rr * Dn))[lane + 32] = nc;
    store4_hilo(g_seq_hi + (size_t)rr * Dn, g_seq_lo + (size_t)rr * Dn, lane * 4, ni);
    store4_hilo(g_seq_hi + (size_t)rr * Dn, g_seq_lo + (size_t)rr * Dn, 128 + lane * 4, nc);
}

// =============================================================================
// attn_lite (R7 proven)
// =============================================================================
__global__ void __launch_bounds__(256, 2)
attn_lite(const int* __restrict__ item_seq,
          const float* __restrict__ q1_w, const float* __restrict__ q1_b,
          const float* __restrict__ v_w) {
    __shared__ float s_ht[Dn];
    __shared__ float s_part[Ln * 8];
    __shared__ float s_alpha[Ln + 2];
    __shared__ float s_mask[Ln + 2];
    __shared__ float s_red[8];
    __shared__ float s_bcast;
    __shared__ int   s_last;

    const int b = blockIdx.x;
    const int t = threadIdx.x;
    const int lane = t & 31, wid = t >> 5;

    if (t < Ln) s_mask[t] = (item_seq[b * Ln + t] > 0) ? 1.0f : 0.0f;
    if (t == 0) {
        int cnt = 0;
        for (int l = 0; l < Ln; l++) cnt += (item_seq[b * Ln + l] > 0) ? 1 : 0;
        s_last = max(cnt - 1, 0);
    }
    __syncthreads();
    s_ht[t] = g_seq_f32[((size_t)b * Ln + s_last) * Dn + t];
    __syncthreads();

    float q1v = 0.f;
    #pragma unroll 4
    for (int d = 0; d < Dn; d++) q1v += s_ht[d] * q1_w[d * Dn + t];
    q1v += q1_b[t];

    const float vw = v_w[t];
    for (int l = 0; l < Ln; l++) {
        const float x = q1v + g_q2[((size_t)b * Ln + l) * Dn + t];
        float c = vw / (1.0f + expf(-x));
        #pragma unroll
        for (int o = 16; o > 0; o >>= 1) c += __shfl_xor_sync(0xffffffffu, c, o);
        if (lane == 0) s_part[l * 8 + wid] = c;
    }
    __syncthreads();
    if (t < Ln) {
        float a = 0.f;
        #pragma unroll
        for (int w = 0; w < 8; w++) a += s_part[t * 8 + w];
        s_alpha[t] = a * s_mask[t];
    }
    __syncthreads();

    float outacc = 0.f;
    #pragma unroll 5
    for (int l = 0; l < Ln; l++)
        outacc += s_alpha[l] * g_seq_f32[((size_t)b * Ln + l) * Dn + t];

    float ss = outacc * outacc;
    #pragma unroll
    for (int o = 16; o > 0; o >>= 1) ss += __shfl_xor_sync(0xffffffffu, ss, o);
    if (lane == 0) s_red[wid] = ss;
    __syncthreads();
    if (t == 0) {
        float a = 0.f;
        #pragma unroll
        for (int w = 0; w < 8; w++) a += s_red[w];
        s_bcast = a;
    }
    __syncthreads();
    const float inv = 1.0f / fmaxf(sqrtf(s_bcast), EPS);
    sthilo(g_so_hi, g_so_lo, (size_t)b * Dn + t, outacc * inv);
}

// =============================================================================
// itemnorm (R4 proven)
// =============================================================================
__global__ void __launch_bounds__(256)
itemnorm_kernel(const float* __restrict__ embedding, const int* __restrict__ item_cates) {
    const int i = blockIdx.x * 8 + (threadIdx.x >> 5);
    const int lane = threadIdx.x & 31;
    if (i >= ITEMN) return;
    const int c = item_cates[i];
    const float4 vi = ((const float4*)(embedding + (size_t)i * Hn))[lane];
    const float4 vc = ((const float4*)(embedding + (size_t)c * Hn))[lane];
    float ss = vi.x*vi.x + vi.y*vi.y + vi.z*vi.z + vi.w*vi.w
             + vc.x*vc.x + vc.y*vc.y + vc.z*vc.z + vc.w*vc.w;
    #pragma unroll
    for (int o = 16; o > 0; o >>= 1) ss += __shfl_xor_sync(0xffffffffu, ss, o);
    const float inv = 1.0f / fmaxf(sqrtf(ss), EPS);
    __nv_bfloat16* hi = g_item_hi + (size_t)i * Dn;
    __nv_bfloat16* lo = g_item_lo + (size_t)i * Dn;
    store4_hilo(hi, lo, lane * 4, make_float4(vi.x*inv, vi.y*inv, vi.z*inv, vi.w*inv));
    store4_hilo(hi, lo, 128 + lane * 4, make_float4(vc.x*inv, vc.y*inv, vc.z*inv, vc.w*inv));
}

// =============================================================================
// scores via HMMA split-bf16 (R7 PROVEN — C from d_out, srcs in-kernel)
// =============================================================================
__global__ void __launch_bounds__(256, 2)
scores_mma(float* __restrict__ C) {
    extern __shared__ char smc[];
    const uint32_t sb = smem_u32(smc);

    const int t = threadIdx.x;
    const int w = t >> 5, lane = t & 31;
    const int b0 = blockIdx.x * 128;
    const int i0 = blockIdx.y * 128;
    const int warp_m = w & 3;
    const int warp_n = w >> 2;

    const __nv_bfloat16* srcs[4] = {
        g_item_hi + (size_t)i0 * Dn, g_item_lo + (size_t)i0 * Dn,
        g_so_hi  + (size_t)b0 * Dn, g_so_lo  + (size_t)b0 * Dn
    };
    const int ld_row0 = t >> 2, ld_row1 = 64 + (t >> 2), ld_seg = t & 3;

    float acc[2][8][4];
    #pragma unroll
    for (int i = 0; i < 2; i++)
        #pragma unroll
        for (int j = 0; j < 8; j++)
            #pragma unroll
            for (int r = 0; r < 4; r++) acc[i][j][r] = 0.f;

    const uint32_t aA_lane = (uint32_t)((lane & 15) * ROWB + (lane >> 4) * 16);
    const uint32_t aB_lane = (uint32_t)(((lane & 7) + ((lane >> 4) & 1) * 8) * ROWB
                                        + ((lane >> 3) & 1) * 16);

    #pragma unroll
    for (int mat = 0; mat < 4; mat++) {
        cp16(sb + 0 * BUFB + mat * MATB + ld_row0 * ROWB + ld_seg * 16,
             srcs[mat] + (size_t)ld_row0 * Dn + ld_seg * 8);
        cp16(sb + 0 * BUFB + mat * MATB + ld_row1 * ROWB + ld_seg * 16,
             srcs[mat] + (size_t)ld_row1 * Dn + ld_seg * 8);
    }
    CP_COMMIT();

    for (int kc = 0; kc < 8; kc++) {
        const int buf = kc & 1;
        if (kc < 7) {
            const int k0 = (kc + 1) * 32;
            const int nbuf = (kc + 1) & 1;
            #pragma unroll
            for (int mat = 0; mat < 4; mat++) {
                cp16(sb + nbuf * BUFB + mat * MATB + ld_row0 * ROWB + ld_seg * 16,
                     srcs[mat] + (size_t)ld_row0 * Dn + k0 + ld_seg * 8);
                cp16(sb + nbuf * BUFB + mat * MATB + ld_row1 * ROWB + ld_seg * 16,
                     srcs[mat] + (size_t)ld_row1 * Dn + k0 + ld_seg * 8);
            }
            CP_COMMIT();
            CP_WAIT(1);
        } else {
            CP_WAIT(0);
        }
        __syncthreads();

        const uint32_t baseA = sb + buf * BUFB + (uint32_t)(warp_m * 32) * ROWB + aA_lane;
        const uint32_t baseB = sb + buf * BUFB + (uint32_t)(warp_n * 64) * ROWB + aB_lane;

        #pragma unroll
        for (int ks = 0; ks < 2; ks++) {
            const uint32_t koff = (uint32_t)ks * 32;
            uint32_t ahi[2][4], alo[2][4];
            #pragma unroll
            for (int i = 0; i < 2; i++) {
                ldsm4(ahi[i], baseA + 0 * MATB + (uint32_t)(i * 16) * ROWB + koff);
                ldsm4(alo[i], baseA + 1 * MATB + (uint32_t)(i * 16) * ROWB + koff);
            }
            #pragma unroll
            for (int jg = 0; jg < 2; jg++) {
                uint32_t bhi[2][4], blo[2][4];
                #pragma unroll
                for (int j4 = 0; j4 < 2; j4++) {
                    const uint32_t off = (uint32_t)((jg * 2 + j4) * 16) * ROWB + koff;
                    ldsm4(bhi[j4], baseB + 2 * MATB + off);
                    ldsm4(blo[j4], baseB + 3 * MATB + off);
                }
                #pragma unroll
                for (int i = 0; i < 2; i++)
                    #pragma unroll
                    for (int jj = 0; jj < 4; jj++) {
                        const int j = jg * 4 + jj;
                        const uint32_t* bh = &bhi[jj >> 1][(jj & 1) * 2];
                        const uint32_t* bl = &blo[jj >> 1][(jj & 1) * 2];
                        mma16816(acc[i][j], ahi[i], bh);
                        mma16816(acc[i][j], ahi[i], bl);
                        mma16816(acc[i][j], alo[i], bh);
                    }
            }
        }
        __syncthreads();
    }

    const int mrow = i0 + warp_m * 32 + (lane >> 2);
    const int ncol = b0 + warp_n * 64 + (lane & 3) * 2;
    #pragma unroll
    for (int i = 0; i < 2; i++) {
        #pragma unroll
        for (int j = 0; j < 8; j++) {
            const int n = ncol + j * 8;
            const int m = mrow + i * 16;
            if (m < ITEMN) {
                C[(size_t)n       * ITEMN + m]     = 16.f * acc[i][j][0];
                C[(size_t)(n + 1) * ITEMN + m]     = 16.f * acc[i][j][1];
            }
            if (m + 8 < ITEMN) {
                C[(size_t)n       * ITEMN + m + 8] = 16.f * acc[i][j][2];
                C[(size_t)(n + 1) * ITEMN + m + 8] = 16.f * acc[i][j][3];
            }
        }
    }
}

// =============================================================================
// launch — NO device symbols passed as kernel arguments, only d_in/d_out.
// =============================================================================
extern "C" void kernel_launch(void* const* d_in, const int* in_sizes, int n_in,
                              void* d_out, int out_size) {
    const int*   item_seq   = (const int*)  d_in[0];
    /* label d_in[1] unused */
    const int*   nodes      = (const int*)  d_in[2];
    const float* hn_adj     = (const float*)d_in[3];
    const int*   alias_item = (const int*)  d_in[4];
    const int*   alias_cate = (const int*)  d_in[5];
    const float* embedding  = (const float*)d_in[6];
    const int*   item_cates = (const int*)  d_in[7];
    const float* w_edge     = (const float*)d_in[8];
    const float* w_node     = (const float*)d_in[9];
    const float* q1_w       = (const float*)d_in[10];
    const float* q1_b       = (const float*)d_in[11];
    const float* q2_w       = (const float*)d_in[12];
    const float* v_w        = (const float*)d_in[13];
    float* out = (float*)d_out;

    cudaFuncSetAttribute(gemm3_eh, cudaFuncAttributeMaxDynamicSharedMemorySize, SC_SMEM);
    cudaFuncSetAttribute(gemm3_nh, cudaFuncAttributeMaxDynamicSharedMemorySize, SC_SMEM);
    cudaFuncSetAttribute(gemm3_q2, cudaFuncAttributeMaxDynamicSharedMemorySize, SC_SMEM);
    cudaFuncSetAttribute(scores_mma, cudaFuncAttributeMaxDynamicSharedMemorySize, SC_SMEM);

    prep_w<<<384, 256>>>(w_edge, w_node, q2_w);
    itemnorm_kernel<<<(ITEMN + 7) / 8, 256>>>(embedding, item_cates);
    init_norm<<<(Bn * Nn) / 8, 256>>>(nodes, embedding);

    for (int step = 0; step < 2; step++) {
        agg_e_kernel<<<Bn, 256>>>(hn_adj);
        gemm3_eh<<<dim3(Bn * En / 128, 1), 256, SC_SMEM>>>();
        agg_n_kernel<<<Bn, 256>>>(hn_adj);
        gemm3_nh<<<dim3(Bn * Nn / 128, 1), 256, SC_SMEM>>>();
    }

    seqbuild<<<Bn * Ln / 8, 256>>>(alias_item, alias_cate);
    gemm3_q2<<<dim3(Bn * Ln / 128, 2), 256, SC_SMEM>>>();
    attn_lite<<<Bn, 256>>>(item_seq, q1_w, q1_b, v_w);

    scores_mma<<<dim3(4, ITEMP / 128), 256, SC_SMEM>>>(out);
}

// round 11
// speedup vs baseline: 1.3339x; 1.3339x over previous
#include <cuda_runtime.h>
#include <cuda_bf16.h>
#include <math.h>
#include <stdint.h>

#define Bn 512
#define Ln 50
#define Nn 64
#define En 16
#define Hn 128
#define Dn 256
#define ITEMN 100000
#define ITEMP 100096
#define EPS 1e-12f
#define SP 136         // padded smem row stride (floats) for hgnn

// ------------------------- scratch (no allocs allowed) -------------------------
// Device globals are ONLY referenced inside device code (never host kernel args).
__device__ float g_nodes_h[Bn * Nn * Hn];                    // 16.8 MB
__device__ float g_seq_f32[25600 * 256];                     // 26.2 MB
__device__ __nv_bfloat16 g_seq_hi[25600 * 256];              // 13.1 MB
__device__ __nv_bfloat16 g_seq_lo[25600 * 256];              // 13.1 MB
__device__ float g_q2[25600 * 256];                          // 26.2 MB
__device__ __nv_bfloat16 g_q2t_hi[256 * 256], g_q2t_lo[256 * 256];
__device__ __nv_bfloat16 g_so_hi[Bn * Dn], g_so_lo[Bn * Dn];
__device__ __nv_bfloat16 g_item_hi[(size_t)ITEMP * Dn];      // 51.2 MB
__device__ __nv_bfloat16 g_item_lo[(size_t)ITEMP * Dn];      // 51.2 MB

// ============================= PTX helpers =============================
__device__ __forceinline__ uint32_t smem_u32(const void* p) {
    uint32_t a;
    asm("{ .reg .u64 t; cvta.to.shared.u64 t, %1; cvt.u32.u64 %0, t; }" : "=r"(a) : "l"(p));
    return a;
}
__device__ __forceinline__ void cp16(uint32_t dst, const void* src) {
    asm volatile("cp.async.cg.shared.global [%0], [%1], 16;" :: "r"(dst), "l"(src));
}
#define CP_COMMIT() asm volatile("cp.async.commit_group;" ::: "memory")
#define CP_WAIT(n)  asm volatile("cp.async.wait_group %0;" :: "n"(n) : "memory")

__device__ __forceinline__ void ldsm4(uint32_t* r, uint32_t addr) {
    asm volatile("ldmatrix.sync.aligned.m8n8.x4.shared.b16 {%0,%1,%2,%3}, [%4];"
                 : "=r"(r[0]), "=r"(r[1]), "=r"(r[2]), "=r"(r[3]) : "r"(addr));
}
__device__ __forceinline__ void mma16816(float* d, const uint32_t* a, const uint32_t* b) {
    asm volatile(
        "mma.sync.aligned.m16n8k16.row.col.f32.bf16.bf16.f32 "
        "{%0,%1,%2,%3}, {%4,%5,%6,%7}, {%8,%9}, {%0,%1,%2,%3};"
        : "+f"(d[0]), "+f"(d[1]), "+f"(d[2]), "+f"(d[3])
        : "r"(a[0]), "r"(a[1]), "r"(a[2]), "r"(a[3]), "r"(b[0]), "r"(b[1]));
}
__device__ __forceinline__ void sthilo(__nv_bfloat16* hi, __nv_bfloat16* lo,
                                       size_t idx, float v) {
    __nv_bfloat16 h = __float2bfloat16_rn(v);
    hi[idx] = h;
    lo[idx] = __float2bfloat16_rn(v - __bfloat162float(h));
}
__device__ __forceinline__ void store4_hilo(__nv_bfloat16* hi, __nv_bfloat16* lo,
                                            int c, float4 v) {
    __nv_bfloat16 h0 = __float2bfloat16_rn(v.x), h1 = __float2bfloat16_rn(v.y);
    __nv_bfloat16 h2 = __float2bfloat16_rn(v.z), h3 = __float2bfloat16_rn(v.w);
    *(__nv_bfloat162*)(hi + c)     = __halves2bfloat162(h0, h1);
    *(__nv_bfloat162*)(hi + c + 2) = __halves2bfloat162(h2, h3);
    __nv_bfloat16 l0 = __float2bfloat16_rn(v.x - __bfloat162float(h0));
    __nv_bfloat16 l1 = __float2bfloat16_rn(v.y - __bfloat162float(h1));
    __nv_bfloat16 l2 = __float2bfloat16_rn(v.z - __bfloat162float(h2));
    __nv_bfloat16 l3 = __float2bfloat16_rn(v.w - __bfloat162float(h3));
    *(__nv_bfloat162*)(lo + c)     = __halves2bfloat162(l0, l1);
    *(__nv_bfloat162*)(lo + c + 2) = __halves2bfloat162(l2, l3);
}

// =============================================================================
// Shared split-bf16 HMMA GEMM body (R10 PROVEN): C[M,N] = A . W^T, 3-term.
// =============================================================================
#define ROWB 80
#define MATB (128 * ROWB)
#define BUFB (4 * MATB)
#define SC_SMEM (2 * BUFB)

template<int KTOT, int N>
__device__ __forceinline__ void gemm3_body(
    const __nv_bfloat16* __restrict__ Ahi, const __nv_bfloat16* __restrict__ Alo,
    const __nv_bfloat16* __restrict__ Whi, const __nv_bfloat16* __restrict__ Wlo,
    float* __restrict__ C) {
    extern __shared__ char smc[];
    const uint32_t sb = smem_u32(smc);
    const int t = threadIdx.x;
    const int w = t >> 5, lane = t & 31;
    const int m0 = blockIdx.x * 128;
    const int n0 = blockIdx.y * 128;
    const int warp_m = w & 3;
    const int warp_n = w >> 2;

    const __nv_bfloat16* srcs[4] = {
        Ahi + (size_t)m0 * KTOT, Alo + (size_t)m0 * KTOT,
        Whi + (size_t)n0 * KTOT, Wlo + (size_t)n0 * KTOT
    };
    const int ld_row0 = t >> 2,  ld_row1 = 64 + (t >> 2), ld_seg = t & 3;

    float acc[2][8][4];
    #pragma unroll
    for (int i = 0; i < 2; i++)
        #pragma unroll
        for (int j = 0; j < 8; j++)
            #pragma unroll
            for (int r = 0; r < 4; r++) acc[i][j][r] = 0.f;

    const uint32_t aA_lane = (uint32_t)((lane & 15) * ROWB + (lane >> 4) * 16);
    const uint32_t aB_lane = (uint32_t)(((lane & 7) + ((lane >> 4) & 1) * 8) * ROWB
                                        + ((lane >> 3) & 1) * 16);

    #pragma unroll
    for (int mat = 0; mat < 4; mat++) {
        cp16(sb + 0 * BUFB + mat * MATB + ld_row0 * ROWB + ld_seg * 16,
             srcs[mat] + (size_t)ld_row0 * KTOT + ld_seg * 8);
        cp16(sb + 0 * BUFB + mat * MATB + ld_row1 * ROWB + ld_seg * 16,
             srcs[mat] + (size_t)ld_row1 * KTOT + ld_seg * 8);
    }
    CP_COMMIT();

    const int NCH = KTOT / 32;
    for (int kc = 0; kc < NCH; kc++) {
        const int buf = kc & 1;
        if (kc < NCH - 1) {
            const int k0 = (kc + 1) * 32;
            const int nbuf = (kc + 1) & 1;
            #pragma unroll
            for (int mat = 0; mat < 4; mat++) {
                cp16(sb + nbuf * BUFB + mat * MATB + ld_row0 * ROWB + ld_seg * 16,
                     srcs[mat] + (size_t)ld_row0 * KTOT + k0 + ld_seg * 8);
                cp16(sb + nbuf * BUFB + mat * MATB + ld_row1 * ROWB + ld_seg * 16,
                     srcs[mat] + (size_t)ld_row1 * KTOT + k0 + ld_seg * 8);
            }
            CP_COMMIT();
            CP_WAIT(1);
        } else {
            CP_WAIT(0);
        }
        __syncthreads();

        const uint32_t baseA = sb + buf * BUFB + (uint32_t)(warp_m * 32) * ROWB + aA_lane;
        const uint32_t baseB = sb + buf * BUFB + (uint32_t)(warp_n * 64) * ROWB + aB_lane;

        #pragma unroll
        for (int ks = 0; ks < 2; ks++) {
            const uint32_t koff = (uint32_t)ks * 32;
            uint32_t ahi[2][4], alo[2][4];
            #pragma unroll
            for (int i = 0; i < 2; i++) {
                ldsm4(ahi[i], baseA + 0 * MATB + (uint32_t)(i * 16) * ROWB + koff);
                ldsm4(alo[i], baseA + 1 * MATB + (uint32_t)(i * 16) * ROWB + koff);
            }
            #pragma unroll
            for (int jg = 0; jg < 2; jg++) {
                uint32_t bhi[2][4], blo[2][4];
                #pragma unroll
                for (int j4 = 0; j4 < 2; j4++) {
                    const uint32_t off = (uint32_t)((jg * 2 + j4) * 16) * ROWB + koff;
                    ldsm4(bhi[j4], baseB + 2 * MATB + off);
                    ldsm4(blo[j4], baseB + 3 * MATB + off);
                }
                #pragma unroll
                for (int i = 0; i < 2; i++)
                    #pragma unroll
                    for (int jj = 0; jj < 4; jj++) {
                        const int j = jg * 4 + jj;
                        const uint32_t* bh = &bhi[jj >> 1][(jj & 1) * 2];
                        const uint32_t* bl = &blo[jj >> 1][(jj & 1) * 2];
                        mma16816(acc[i][j], ahi[i], bh);
                        mma16816(acc[i][j], ahi[i], bl);
                        mma16816(acc[i][j], alo[i], bh);
                    }
            }
        }
        __syncthreads();
    }

    const int mrow = m0 + warp_m * 32 + (lane >> 2);
    const int ncol = n0 + warp_n * 64 + (lane & 3) * 2;
    #pragma unroll
    for (int i = 0; i < 2; i++) {
        #pragma unroll
        for (int j = 0; j < 8; j++) {
            const int m = mrow + i * 16;
            const int n = ncol + j * 8;
            *(float2*)(C + (size_t)m * N + n)       = make_float2(acc[i][j][0], acc[i][j][1]);
            *(float2*)(C + (size_t)(m + 8) * N + n) = make_float2(acc[i][j][2], acc[i][j][3]);
        }
    }
}

// device-side wrapper: q2 = seq . q2t^T  (R10 PROVEN)
__global__ void __launch_bounds__(256, 2) gemm3_q2() {
    gemm3_body<256, 256>(g_seq_hi, g_seq_lo, g_q2t_hi, g_q2t_lo, g_q2);
}

// =============================================================================
// Kernel: fused per-batch hypergraph GNN (R4 PROVEN).
// =============================================================================
__global__ void __launch_bounds__(256, 2)
hgnn_kernel(const int* __restrict__ nodes, const float* __restrict__ hn_adj,
            const float* __restrict__ embedding,
            const float* __restrict__ w_edge, const float* __restrict__ w_node) {
    extern __shared__ float sm[];
    float* s_nh   = sm;
    float* s_tmp  = s_nh  + 64 * SP;
    float* s_eh   = s_tmp + 64 * SP;
    float* s_adj  = s_eh  + 16 * SP;
    float* s_dege = s_adj + 1024;
    float* s_degn = s_dege + 16;
    int*   s_idx  = (int*)(s_degn + 64);

    const int b = blockIdx.x;
    const int t = threadIdx.x;
    const int lane = t & 31, wid = t >> 5;

    {
        const float* adjb = hn_adj + (size_t)b * Nn * En;
        for (int i = t; i < Nn * En; i += 256) s_adj[i] = adjb[i];
        if (t < Nn) s_idx[t] = nodes[b * Nn + t];
    }
    __syncthreads();

    if (t < En) {
        float s = 0.f;
        #pragma unroll 8
        for (int n = 0; n < Nn; n++) s += s_adj[n * En + t];
        s_dege[t] = fmaxf(s, 1.0f);
    }
    if (t >= 32 && t < 32 + Nn) {
        int n = t - 32;
        float s = 0.f;
        #pragma unroll
        for (int e = 0; e < En; e++) s += s_adj[n * En + e];
        s_degn[n] = fmaxf(s, 1.0f);
    }

    for (int n = wid; n < Nn; n += 8) {
        const float4 v = ((const float4*)(embedding + (size_t)s_idx[n] * Hn))[lane];
        float ss = v.x * v.x + v.y * v.y + v.z * v.z + v.w * v.w;
        #pragma unroll
        for (int o = 16; o > 0; o >>= 1) ss += __shfl_xor_sync(0xffffffffu, ss, o);
        const float inv = 1.0f / fmaxf(sqrtf(ss), EPS);
        ((float4*)(s_nh + n * SP))[lane] = make_float4(v.x * inv, v.y * inv, v.z * inv, v.w * inv);
    }
    __syncthreads();

    const int cw = wid * 16 + (lane & 3) * 4;
    const int rg = lane >> 2;

    for (int step = 0; step < 2; step++) {
        {
            const int d = t & 127;
            for (int e = t >> 7; e < En; e += 2) {
                float acc = 0.f;
                #pragma unroll 8
                for (int n = 0; n < Nn; n++) acc += s_adj[n * En + e] * s_nh[n * SP + d];
                s_tmp[e * SP + d] = acc / s_dege[e];
            }
        }
        __syncthreads();
        {
            float4 a0 = make_float4(0.f,0.f,0.f,0.f), a1 = make_float4(0.f,0.f,0.f,0.f);
            #pragma unroll 4
            for (int d = 0; d < Hn; d++) {
                const float4 wv = __ldg((const float4*)(w_edge + d * Hn + cw));
                const float t0 = s_tmp[rg * SP + d];
                const float t1 = s_tmp[(rg + 8) * SP + d];
                a0.x += t0 * wv.x; a0.y += t0 * wv.y; a0.z += t0 * wv.z; a0.w += t0 * wv.w;
                a1.x += t1 * wv.x; a1.y += t1 * wv.y; a1.z += t1 * wv.z; a1.w += t1 * wv.w;
            }
            *(float4*)(s_eh + rg * SP + cw)       = a0;
            *(float4*)(s_eh + (rg + 8) * SP + cw) = a1;
        }
        __syncthreads();
        {
            const int d = t & 127;
            for (int n = t >> 7; n < Nn; n += 2) {
                float acc = 0.f;
                #pragma unroll
                for (int e = 0; e < En; e++) acc += s_adj[n * En + e] * s_eh[e * SP + d];
                s_tmp[n * SP + d] = acc / s_degn[n];
            }
        }
        __syncthreads();
        {
            float acc[8][4];
            #pragma unroll
            for (int k = 0; k < 8; k++) { acc[k][0]=0; acc[k][1]=0; acc[k][2]=0; acc[k][3]=0; }
            #pragma unroll 4
            for (int d = 0; d < Hn; d++) {
                const float4 wv = __ldg((const float4*)(w_node + d * Hn + cw));
                #pragma unroll
                for (int k = 0; k < 8; k++) {
                    const float tv = s_tmp[(rg + 8 * k) * SP + d];
                    acc[k][0] += tv * wv.x; acc[k][1] += tv * wv.y;
                    acc[k][2] += tv * wv.z; acc[k][3] += tv * wv.w;
                }
            }
            #pragma unroll
            for (int k = 0; k < 8; k++)
                *(float4*)(s_nh + (rg + 8 * k) * SP + cw) =
                    make_float4(acc[k][0], acc[k][1], acc[k][2], acc[k][3]);
        }
        __syncthreads();
    }

    {
        float4* out4 = (float4*)(g_nodes_h + (size_t)b * Nn * Hn);
        for (int f = t; f < Nn * Hn / 4; f += 256) {
            const int row = f >> 5, c4 = f & 31;
            out4[f] = *(const float4*)(s_nh + row * SP + c4 * 4);
        }
    }
}

// =============================================================================
// prep_q2: transpose + split q2_w [256,256] (R10 proven pattern)
// =============================================================================
__global__ void __launch_bounds__(256)
prep_q2(const float* __restrict__ q2_w) {
    const int idx = blockIdx.x * 256 + threadIdx.x;   // 65536 total
    const int k = idx >> 8, n = idx & 255;
    sthilo(g_q2t_hi, g_q2t_lo, (size_t)n * 256 + k, q2_w[idx]);
}

// =============================================================================
// seqbuild: seq[(b,l)] = l2norm(concat(nh[b,ai], nh[b,ac])) -> fp32 + hi/lo
// =============================================================================
__global__ void __launch_bounds__(256)
seqbuild(const int* __restrict__ alias_item, const int* __restrict__ alias_cate) {
    const int rr = blockIdx.x * 8 + (threadIdx.x >> 5);
    const int lane = threadIdx.x & 31;
    if (rr >= Bn * Ln) return;
    const int b = rr / Ln;
    const int ai = alias_item[rr];
    const int ac = alias_cate[rr];
    const float4 vi = ((const float4*)(g_nodes_h + (size_t)(b * Nn + ai) * Hn))[lane];
    const float4 vc = ((const float4*)(g_nodes_h + (size_t)(b * Nn + ac) * Hn))[lane];
    float ss = vi.x*vi.x + vi.y*vi.y + vi.z*vi.z + vi.w*vi.w
             + vc.x*vc.x + vc.y*vc.y + vc.z*vc.z + vc.w*vc.w;
    #pragma unroll
    for (int o = 16; o > 0; o >>= 1) ss += __shfl_xor_sync(0xffffffffu, ss, o);
    const float inv = 1.0f / fmaxf(sqrtf(ss), EPS);
    const float4 ni = make_float4(vi.x*inv, vi.y*inv, vi.z*inv, vi.w*inv);
    const float4 nc = make_float4(vc.x*inv, vc.y*inv, vc.z*inv, vc.w*inv);
    ((float4*)(g_seq_f32 + (size_t)rr * Dn))[lane]      = ni;
    ((float4*)(g_seq_f32 + (size_t)rr * Dn))[lane + 32] = nc;
    store4_hilo(g_seq_hi + (size_t)rr * Dn, g_seq_lo + (size_t)rr * Dn, lane * 4, ni);
    store4_hilo(g_seq_hi + (size_t)rr * Dn, g_seq_lo + (size_t)rr * Dn, 128 + lane * 4, nc);
}

// =============================================================================
// attn_lite (R7 proven)
// =============================================================================
__global__ void __launch_bounds__(256, 2)
attn_lite(const int* __restrict__ item_seq,
          const float* __restrict__ q1_w, const float* __restrict__ q1_b,
          const float* __restrict__ v_w) {
    __shared__ float s_ht[Dn];
    __shared__ float s_part[Ln * 8];
    __shared__ float s_alpha[Ln + 2];
    __shared__ float s_mask[Ln + 2];
    __shared__ float s_red[8];
    __shared__ float s_bcast;
    __shared__ int   s_last;

    const int b = blockIdx.x;
    const int t = threadIdx.x;
    const int lane = t & 31, wid = t >> 5;

    if (t < Ln) s_mask[t] = (item_seq[b * Ln + t] > 0) ? 1.0f : 0.0f;
    if (t == 0) {
        int cnt = 0;
        for (int l = 0; l < Ln; l++) cnt += (item_seq[b * Ln + l] > 0) ? 1 : 0;
        s_last = max(cnt - 1, 0);
    }
    __syncthreads();
    s_ht[t] = g_seq_f32[((size_t)b * Ln + s_last) * Dn + t];
    __syncthreads();

    float q1v = 0.f;
    #pragma unroll 4
    for (int d = 0; d < Dn; d++) q1v += s_ht[d] * q1_w[d * Dn + t];
    q1v += q1_b[t];

    const float vw = v_w[t];
    for (int l = 0; l < Ln; l++) {
        const float x = q1v + g_q2[((size_t)b * Ln + l) * Dn + t];
        float c = vw / (1.0f + expf(-x));
        #pragma unroll
        for (int o = 16; o > 0; o >>= 1) c += __shfl_xor_sync(0xffffffffu, c, o);
        if (lane == 0) s_part[l * 8 + wid] = c;
    }
    __syncthreads();
    if (t < Ln) {
        float a = 0.f;
        #pragma unroll
        for (int w = 0; w < 8; w++) a += s_part[t * 8 + w];
        s_alpha[t] = a * s_mask[t];
    }
    __syncthreads();

    float outacc = 0.f;
    #pragma unroll 5
    for (int l = 0; l < Ln; l++)
        outacc += s_alpha[l] * g_seq_f32[((size_t)b * Ln + l) * Dn + t];

    float ss = outacc * outacc;
    #pragma unroll
    for (int o = 16; o > 0; o >>= 1) ss += __shfl_xor_sync(0xffffffffu, ss, o);
    if (lane == 0) s_red[wid] = ss;
    __syncthreads();
    if (t == 0) {
        float a = 0.f;
        #pragma unroll
        for (int w = 0; w < 8; w++) a += s_red[w];
        s_bcast = a;
    }
    __syncthreads();
    const float inv = 1.0f / fmaxf(sqrtf(s_bcast), EPS);
    sthilo(g_so_hi, g_so_lo, (size_t)b * Dn + t, outacc * inv);
}

// =============================================================================
// itemnorm (R4 proven)
// =============================================================================
__global__ void __launch_bounds__(256)
itemnorm_kernel(const float* __restrict__ embedding, const int* __restrict__ item_cates) {
    const int i = blockIdx.x * 8 + (threadIdx.x >> 5);
    const int lane = threadIdx.x & 31;
    if (i >= ITEMN) return;
    const int c = item_cates[i];
    const float4 vi = ((const float4*)(embedding + (size_t)i * Hn))[lane];
    const float4 vc = ((const float4*)(embedding + (size_t)c * Hn))[lane];
    float ss = vi.x*vi.x + vi.y*vi.y + vi.z*vi.z + vi.w*vi.w
             + vc.x*vc.x + vc.y*vc.y + vc.z*vc.z + vc.w*vc.w;
    #pragma unroll
    for (int o = 16; o > 0; o >>= 1) ss += __shfl_xor_sync(0xffffffffu, ss, o);
    const float inv = 1.0f / fmaxf(sqrtf(ss), EPS);
    __nv_bfloat16* hi = g_item_hi + (size_t)i * Dn;
    __nv_bfloat16* lo = g_item_lo + (size_t)i * Dn;
    store4_hilo(hi, lo, lane * 4, make_float4(vi.x*inv, vi.y*inv, vi.z*inv, vi.w*inv));
    store4_hilo(hi, lo, 128 + lane * 4, make_float4(vc.x*inv, vc.y*inv, vc.z*inv, vc.w*inv));
}

// =============================================================================
// scores via HMMA split-bf16 (R7 PROVEN)
// =============================================================================
__global__ void __launch_bounds__(256, 2)
scores_mma(float* __restrict__ C) {
    extern __shared__ char smc[];
    const uint32_t sb = smem_u32(smc);

    const int t = threadIdx.x;
    const int w = t >> 5, lane = t & 31;
    const int b0 = blockIdx.x * 128;
    const int i0 = blockIdx.y * 128;
    const int warp_m = w & 3;
    const int warp_n = w >> 2;

    const __nv_bfloat16* srcs[4] = {
        g_item_hi + (size_t)i0 * Dn, g_item_lo + (size_t)i0 * Dn,
        g_so_hi  + (size_t)b0 * Dn, g_so_lo  + (size_t)b0 * Dn
    };
    const int ld_row0 = t >> 2, ld_row1 = 64 + (t >> 2), ld_seg = t & 3;

    float acc[2][8][4];
    #pragma unroll
    for (int i = 0; i < 2; i++)
        #pragma unroll
        for (int j = 0; j < 8; j++)
            #pragma unroll
            for (int r = 0; r < 4; r++) acc[i][j][r] = 0.f;

    const uint32_t aA_lane = (uint32_t)((lane & 15) * ROWB + (lane >> 4) * 16);
    const uint32_t aB_lane = (uint32_t)(((lane & 7) + ((lane >> 4) & 1) * 8) * ROWB
                                        + ((lane >> 3) & 1) * 16);

    #pragma unroll
    for (int mat = 0; mat < 4; mat++) {
        cp16(sb + 0 * BUFB + mat * MATB + ld_row0 * ROWB + ld_seg * 16,
             srcs[mat] + (size_t)ld_row0 * Dn + ld_seg * 8);
        cp16(sb + 0 * BUFB + mat * MATB + ld_row1 * ROWB + ld_seg * 16,
             srcs[mat] + (size_t)ld_row1 * Dn + ld_seg * 8);
    }
    CP_COMMIT();

    for (int kc = 0; kc < 8; kc++) {
        const int buf = kc & 1;
        if (kc < 7) {
            const int k0 = (kc + 1) * 32;
            const int nbuf = (kc + 1) & 1;
            #pragma unroll
            for (int mat = 0; mat < 4; mat++) {
                cp16(sb + nbuf * BUFB + mat * MATB + ld_row0 * ROWB + ld_seg * 16,
                     srcs[mat] + (size_t)ld_row0 * Dn + k0 + ld_seg * 8);
                cp16(sb + nbuf * BUFB + mat * MATB + ld_row1 * ROWB + ld_seg * 16,
                     srcs[mat] + (size_t)ld_row1 * Dn + k0 + ld_seg * 8);
            }
            CP_COMMIT();
            CP_WAIT(1);
        } else {
            CP_WAIT(0);
        }
        __syncthreads();

        const uint32_t baseA = sb + buf * BUFB + (uint32_t)(warp_m * 32) * ROWB + aA_lane;
        const uint32_t baseB = sb + buf * BUFB + (uint32_t)(warp_n * 64) * ROWB + aB_lane;

        #pragma unroll
        for (int ks = 0; ks < 2; ks++) {
            const uint32_t koff = (uint32_t)ks * 32;
            uint32_t ahi[2][4], alo[2][4];
            #pragma unroll
            for (int i = 0; i < 2; i++) {
                ldsm4(ahi[i], baseA + 0 * MATB + (uint32_t)(i * 16) * ROWB + koff);
                ldsm4(alo[i], baseA + 1 * MATB + (uint32_t)(i * 16) * ROWB + koff);
            }
            #pragma unroll
            for (int jg = 0; jg < 2; jg++) {
                uint32_t bhi[2][4], blo[2][4];
                #pragma unroll
                for (int j4 = 0; j4 < 2; j4++) {
                    const uint32_t off = (uint32_t)((jg * 2 + j4) * 16) * ROWB + koff;
                    ldsm4(bhi[j4], baseB + 2 * MATB + off);
                    ldsm4(blo[j4], baseB + 3 * MATB + off);
                }
                #pragma unroll
                for (int i = 0; i < 2; i++)
                    #pragma unroll
                    for (int jj = 0; jj < 4; jj++) {
                        const int j = jg * 4 + jj;
                        const uint32_t* bh = &bhi[jj >> 1][(jj & 1) * 2];
                        const uint32_t* bl = &blo[jj >> 1][(jj & 1) * 2];
                        mma16816(acc[i][j], ahi[i], bh);
                        mma16816(acc[i][j], ahi[i], bl);
                        mma16816(acc[i][j], alo[i], bh);
                    }
            }
        }
        __syncthreads();
    }

    const int mrow = i0 + warp_m * 32 + (lane >> 2);
    const int ncol = b0 + warp_n * 64 + (lane & 3) * 2;
    #pragma unroll
    for (int i = 0; i < 2; i++) {
        #pragma unroll
        for (int j = 0; j < 8; j++) {
            const int n = ncol + j * 8;
            const int m = mrow + i * 16;
            if (m < ITEMN) {
                C[(size_t)n       * ITEMN + m]     = 16.f * acc[i][j][0];
                C[(size_t)(n + 1) * ITEMN + m]     = 16.f * acc[i][j][1];
            }
            if (m + 8 < ITEMN) {
                C[(size_t)n       * ITEMN + m + 8] = 16.f * acc[i][j][2];
                C[(size_t)(n + 1) * ITEMN + m + 8] = 16.f * acc[i][j][3];
            }
        }
    }
}

// =============================================================================
// launch — no device symbols passed as kernel args.
// =============================================================================
extern "C" void kernel_launch(void* const* d_in, const int* in_sizes, int n_in,
                              void* d_out, int out_size) {
    const int*   item_seq   = (const int*)  d_in[0];
    /* label d_in[1] unused */
    const int*   nodes      = (const int*)  d_in[2];
    const float* hn_adj     = (const float*)d_in[3];
    const int*   alias_item = (const int*)  d_in[4];
    const int*   alias_cate = (const int*)  d_in[5];
    const float* embedding  = (const float*)d_in[6];
    const int*   item_cates = (const int*)  d_in[7];
    const float* w_edge     = (const float*)d_in[8];
    const float* w_node     = (const float*)d_in[9];
    const float* q1_w       = (const float*)d_in[10];
    const float* q1_b       = (const float*)d_in[11];
    const float* q2_w       = (const float*)d_in[12];
    const float* v_w        = (const float*)d_in[13];
    float* out = (float*)d_out;

    const int hg_smem = (64 * SP + 64 * SP + 16 * SP + 1024 + 16 + 64 + 64) * 4;
    cudaFuncSetAttribute(hgnn_kernel, cudaFuncAttributeMaxDynamicSharedMemorySize, hg_smem);
    cudaFuncSetAttribute(gemm3_q2,  cudaFuncAttributeMaxDynamicSharedMemorySize, SC_SMEM);
    cudaFuncSetAttribute(scores_mma, cudaFuncAttributeMaxDynamicSharedMemorySize, SC_SMEM);

    prep_q2<<<256, 256>>>(q2_w);
    itemnorm_kernel<<<(ITEMN + 7) / 8, 256>>>(embedding, item_cates);
    hgnn_kernel<<<Bn, 256, hg_smem>>>(nodes, hn_adj, embedding, w_edge, w_node);

    seqbuild<<<Bn * Ln / 8, 256>>>(alias_item, alias_cate);
    gemm3_q2<<<dim3(Bn * Ln / 128, 2), 256, SC_SMEM>>>();
    attn_lite<<<Bn, 256>>>(item_seq, q1_w, q1_b, v_w);

    scores_mma<<<dim3(4, ITEMP / 128), 256, SC_SMEM>>>(out);
}

// round 12
// speedup vs baseline: 1.4657x; 1.0988x over previous
#include <cuda_runtime.h>
#include <cuda_bf16.h>
#include <math.h>
#include <stdint.h>

#define Bn 512
#define Ln 50
#define Nn 64
#define En 16
#define Hn 128
#define Dn 256
#define ITEMN 100000
#define ITEMP 100096
#define EPS 1e-12f

// ------------------------- scratch (no allocs allowed) -------------------------
// Device globals are ONLY referenced inside device code (never host kernel args).
__device__ float g_nodes_h[Bn * Nn * Hn];                    // 16.8 MB
__device__ float g_seq_f32[25600 * 256];                     // 26.2 MB
__device__ __nv_bfloat16 g_seq_hi[25600 * 256];
__device__ __nv_bfloat16 g_seq_lo[25600 * 256];
__device__ float g_q2[25600 * 256];
__device__ __nv_bfloat16 g_wet_hi[128 * 128], g_wet_lo[128 * 128];   // w_edge^T
__device__ __nv_bfloat16 g_wnt_hi[128 * 128], g_wnt_lo[128 * 128];   // w_node^T
__device__ __nv_bfloat16 g_q2t_hi[256 * 256], g_q2t_lo[256 * 256];
__device__ __nv_bfloat16 g_so_hi[Bn * Dn], g_so_lo[Bn * Dn];
__device__ __nv_bfloat16 g_item_hi[(size_t)ITEMP * Dn];
__device__ __nv_bfloat16 g_item_lo[(size_t)ITEMP * Dn];

// ============================= PTX helpers =============================
__device__ __forceinline__ uint32_t smem_u32(const void* p) {
    uint32_t a;
    asm("{ .reg .u64 t; cvta.to.shared.u64 t, %1; cvt.u32.u64 %0, t; }" : "=r"(a) : "l"(p));
    return a;
}
__device__ __forceinline__ void cp16(uint32_t dst, const void* src) {
    asm volatile("cp.async.cg.shared.global [%0], [%1], 16;" :: "r"(dst), "l"(src));
}
#define CP_COMMIT() asm volatile("cp.async.commit_group;" ::: "memory")
#define CP_WAIT(n)  asm volatile("cp.async.wait_group %0;" :: "n"(n) : "memory")

__device__ __forceinline__ void ldsm4(uint32_t* r, uint32_t addr) {
    asm volatile("ldmatrix.sync.aligned.m8n8.x4.shared.b16 {%0,%1,%2,%3}, [%4];"
                 : "=r"(r[0]), "=r"(r[1]), "=r"(r[2]), "=r"(r[3]) : "r"(addr));
}
__device__ __forceinline__ void mma16816(float* d, const uint32_t* a, const uint32_t* b) {
    asm volatile(
        "mma.sync.aligned.m16n8k16.row.col.f32.bf16.bf16.f32 "
        "{%0,%1,%2,%3}, {%4,%5,%6,%7}, {%8,%9}, {%0,%1,%2,%3};"
        : "+f"(d[0]), "+f"(d[1]), "+f"(d[2]), "+f"(d[3])
        : "r"(a[0]), "r"(a[1]), "r"(a[2]), "r"(a[3]), "r"(b[0]), "r"(b[1]));
}
__device__ __forceinline__ void sthilo(__nv_bfloat16* hi, __nv_bfloat16* lo,
                                       size_t idx, float v) {
    __nv_bfloat16 h = __float2bfloat16_rn(v);
    hi[idx] = h;
    lo[idx] = __float2bfloat16_rn(v - __bfloat162float(h));
}
__device__ __forceinline__ void store4_hilo(__nv_bfloat16* hi, __nv_bfloat16* lo,
                                            int c, float4 v) {
    __nv_bfloat16 h0 = __float2bfloat16_rn(v.x), h1 = __float2bfloat16_rn(v.y);
    __nv_bfloat16 h2 = __float2bfloat16_rn(v.z), h3 = __float2bfloat16_rn(v.w);
    *(__nv_bfloat162*)(hi + c)     = __halves2bfloat162(h0, h1);
    *(__nv_bfloat162*)(hi + c + 2) = __halves2bfloat162(h2, h3);
    __nv_bfloat16 l0 = __float2bfloat16_rn(v.x - __bfloat162float(h0));
    __nv_bfloat16 l1 = __float2bfloat16_rn(v.y - __bfloat162float(h1));
    __nv_bfloat16 l2 = __float2bfloat16_rn(v.z - __bfloat162float(h2));
    __nv_bfloat16 l3 = __float2bfloat16_rn(v.w - __bfloat162float(h3));
    *(__nv_bfloat162*)(lo + c)     = __halves2bfloat162(l0, l1);
    *(__nv_bfloat162*)(lo + c + 2) = __halves2bfloat162(l2, l3);
}

// =============================================================================
// Shared split-bf16 HMMA GEMM body (R10/R11 PROVEN)
// =============================================================================
#define ROWB 80
#define MATB (128 * ROWB)
#define BUFB (4 * MATB)
#define SC_SMEM (2 * BUFB)

template<int KTOT, int N>
__device__ __forceinline__ void gemm3_body(
    const __nv_bfloat16* __restrict__ Ahi, const __nv_bfloat16* __restrict__ Alo,
    const __nv_bfloat16* __restrict__ Whi, const __nv_bfloat16* __restrict__ Wlo,
    float* __restrict__ C) {
    extern __shared__ char smc[];
    const uint32_t sb = smem_u32(smc);
    const int t = threadIdx.x;
    const int w = t >> 5, lane = t & 31;
    const int m0 = blockIdx.x * 128;
    const int n0 = blockIdx.y * 128;
    const int warp_m = w & 3;
    const int warp_n = w >> 2;

    const __nv_bfloat16* srcs[4] = {
        Ahi + (size_t)m0 * KTOT, Alo + (size_t)m0 * KTOT,
        Whi + (size_t)n0 * KTOT, Wlo + (size_t)n0 * KTOT
    };
    const int ld_row0 = t >> 2,  ld_row1 = 64 + (t >> 2), ld_seg = t & 3;

    float acc[2][8][4];
    #pragma unroll
    for (int i = 0; i < 2; i++)
        #pragma unroll
        for (int j = 0; j < 8; j++)
            #pragma unroll
            for (int r = 0; r < 4; r++) acc[i][j][r] = 0.f;

    const uint32_t aA_lane = (uint32_t)((lane & 15) * ROWB + (lane >> 4) * 16);
    const uint32_t aB_lane = (uint32_t)(((lane & 7) + ((lane >> 4) & 1) * 8) * ROWB
                                        + ((lane >> 3) & 1) * 16);

    #pragma unroll
    for (int mat = 0; mat < 4; mat++) {
        cp16(sb + 0 * BUFB + mat * MATB + ld_row0 * ROWB + ld_seg * 16,
             srcs[mat] + (size_t)ld_row0 * KTOT + ld_seg * 8);
        cp16(sb + 0 * BUFB + mat * MATB + ld_row1 * ROWB + ld_seg * 16,
             srcs[mat] + (size_t)ld_row1 * KTOT + ld_seg * 8);
    }
    CP_COMMIT();

    const int NCH = KTOT / 32;
    for (int kc = 0; kc < NCH; kc++) {
        const int buf = kc & 1;
        if (kc < NCH - 1) {
            const int k0 = (kc + 1) * 32;
            const int nbuf = (kc + 1) & 1;
            #pragma unroll
            for (int mat = 0; mat < 4; mat++) {
                cp16(sb + nbuf * BUFB + mat * MATB + ld_row0 * ROWB + ld_seg * 16,
                     srcs[mat] + (size_t)ld_row0 * KTOT + k0 + ld_seg * 8);
                cp16(sb + nbuf * BUFB + mat * MATB + ld_row1 * ROWB + ld_seg * 16,
                     srcs[mat] + (size_t)ld_row1 * KTOT + k0 + ld_seg * 8);
            }
            CP_COMMIT();
            CP_WAIT(1);
        } else {
            CP_WAIT(0);
        }
        __syncthreads();

        const uint32_t baseA = sb + buf * BUFB + (uint32_t)(warp_m * 32) * ROWB + aA_lane;
        const uint32_t baseB = sb + buf * BUFB + (uint32_t)(warp_n * 64) * ROWB + aB_lane;

        #pragma unroll
        for (int ks = 0; ks < 2; ks++) {
            const uint32_t koff = (uint32_t)ks * 32;
            uint32_t ahi[2][4], alo[2][4];
            #pragma unroll
            for (int i = 0; i < 2; i++) {
                ldsm4(ahi[i], baseA + 0 * MATB + (uint32_t)(i * 16) * ROWB + koff);
                ldsm4(alo[i], baseA + 1 * MATB + (uint32_t)(i * 16) * ROWB + koff);
            }
            #pragma unroll
            for (int jg = 0; jg < 2; jg++) {
                uint32_t bhi[2][4], blo[2][4];
                #pragma unroll
                for (int j4 = 0; j4 < 2; j4++) {
                    const uint32_t off = (uint32_t)((jg * 2 + j4) * 16) * ROWB + koff;
                    ldsm4(bhi[j4], baseB + 2 * MATB + off);
                    ldsm4(blo[j4], baseB + 3 * MATB + off);
                }
                #pragma unroll
                for (int i = 0; i < 2; i++)
                    #pragma unroll
                    for (int jj = 0; jj < 4; jj++) {
                        const int j = jg * 4 + jj;
                        const uint32_t* bh = &bhi[jj >> 1][(jj & 1) * 2];
                        const uint32_t* bl = &blo[jj >> 1][(jj & 1) * 2];
                        mma16816(acc[i][j], ahi[i], bh);
                        mma16816(acc[i][j], ahi[i], bl);
                        mma16816(acc[i][j], alo[i], bh);
                    }
            }
        }
        __syncthreads();
    }

    const int mrow = m0 + warp_m * 32 + (lane >> 2);
    const int ncol = n0 + warp_n * 64 + (lane & 3) * 2;
    #pragma unroll
    for (int i = 0; i < 2; i++) {
        #pragma unroll
        for (int j = 0; j < 8; j++) {
            const int m = mrow + i * 16;
            const int n = ncol + j * 8;
            *(float2*)(C + (size_t)m * N + n)       = make_float2(acc[i][j][0], acc[i][j][1]);
            *(float2*)(C + (size_t)(m + 8) * N + n) = make_float2(acc[i][j][2], acc[i][j][3]);
        }
    }
}

__global__ void __launch_bounds__(256, 2) gemm3_q2() {
    gemm3_body<256, 256>(g_seq_hi, g_seq_lo, g_q2t_hi, g_q2t_lo, g_q2);
}

// =============================================================================
// hgnn_mma: fused per-batch GNN with in-kernel HMMA GEMMs.
// Smem map (bytes):
//  A region   [4 kc][hi/lo][64 rows x 80B]  : 0      .. 40960
//  EAGG       [4 kc][hi/lo][16 rows x 80B]  : 40960  .. 51200
//  EH fp32    [16 x 132]                    : 51200  .. 59648
//  W dbl-buf  [2][hi/lo][128 x 80B]         : 59648  .. 100608
//  ADJ fp32   [64 x 16]                     : 100608 .. 104704
//  deg_e[16], deg_n[64], idx[64]            : 104704 .. 105280
// =============================================================================
#define ACH 5120
#define ECH 1280
#define HG_A(kc, mat)    (((kc) * 2 + (mat)) * ACH)
#define HG_EAGG(kc, mat) (40960 + ((kc) * 2 + (mat)) * ECH)
#define HG_EH            51200
#define HG_W(buf, mat)   (59648 + (buf) * 20480 + (mat) * 10240)
#define HG_ADJ           100608
#define HG_DEGE          104704
#define HG_DEGN          (104704 + 64)
#define HG_IDX           (104704 + 64 + 256)
#define HGM_SMEM         105472

__device__ __forceinline__ void hg_load_wchunk(uint32_t sb, int buf,
    const __nv_bfloat16* Whi, const __nv_bfloat16* Wlo, int kc, int t) {
    #pragma unroll
    for (int h = 0; h < 2; h++) {
        const int e = h * 256 + t;      // 0..511
        const int row = e >> 2, seg = e & 3;
        cp16(sb + HG_W(buf, 0) + row * 80 + seg * 16,
             Whi + (size_t)row * 128 + kc * 32 + seg * 8);
        cp16(sb + HG_W(buf, 1) + row * 80 + seg * 16,
             Wlo + (size_t)row * 128 + kc * 32 + seg * 8);
    }
}

__global__ void __launch_bounds__(256, 2)
hgnn_mma(const int* __restrict__ nodes, const float* __restrict__ hn_adj,
         const float* __restrict__ embedding) {
    extern __shared__ char smx[];
    const uint32_t sb = smem_u32(smx);
    float* s_adj  = (float*)(smx + HG_ADJ);
    float* s_eh   = (float*)(smx + HG_EH);
    float* s_dege = (float*)(smx + HG_DEGE);
    float* s_degn = (float*)(smx + HG_DEGN);
    int*   s_idx  = (int*)(smx + HG_IDX);

    const int b = blockIdx.x;
    const int t = threadIdx.x;
    const int lane = t & 31, wid = t >> 5;

    {
        const float* adjb = hn_adj + (size_t)b * Nn * En;
        for (int i = t; i < Nn * En; i += 256) s_adj[i] = adjb[i];
        if (t < Nn) s_idx[t] = nodes[b * Nn + t];
    }
    __syncthreads();

    if (t < En) {
        float s = 0.f;
        #pragma unroll 8
        for (int n = 0; n < Nn; n++) s += s_adj[n * En + t];
        s_dege[t] = fmaxf(s, 1.0f);
    }
    if (t >= 32 && t < 32 + Nn) {
        const int n = t - 32;
        float s = 0.f;
        #pragma unroll
        for (int e = 0; e < En; e++) s += s_adj[n * En + e];
        s_degn[n] = fmaxf(s, 1.0f);
    }

    // init: n_h = l2norm(embedding[nodes]) -> A region (hi/lo chunked)
    for (int n = wid; n < Nn; n += 8) {
        const float4 v = ((const float4*)(embedding + (size_t)s_idx[n] * Hn))[lane];
        float ss = v.x * v.x + v.y * v.y + v.z * v.z + v.w * v.w;
        #pragma unroll
        for (int o = 16; o > 0; o >>= 1) ss += __shfl_xor_sync(0xffffffffu, ss, o);
        const float inv = 1.0f / fmaxf(sqrtf(ss), EPS);
        const float4 nv = make_float4(v.x * inv, v.y * inv, v.z * inv, v.w * inv);
        const int chunk = lane >> 3;
        const int c = (lane & 7) * 4;
        __nv_bfloat16 h0 = __float2bfloat16_rn(nv.x), h1 = __float2bfloat16_rn(nv.y);
        __nv_bfloat16 h2 = __float2bfloat16_rn(nv.z), h3 = __float2bfloat16_rn(nv.w);
        char* hip = smx + HG_A(chunk, 0) + n * 80 + c * 2;
        char* lop = smx + HG_A(chunk, 1) + n * 80 + c * 2;
        *(__nv_bfloat162*)(hip)     = __halves2bfloat162(h0, h1);
        *(__nv_bfloat162*)(hip + 4) = __halves2bfloat162(h2, h3);
        *(__nv_bfloat162*)(lop) = __halves2bfloat162(
            __float2bfloat16_rn(nv.x - __bfloat162float(h0)),
            __float2bfloat16_rn(nv.y - __bfloat162float(h1)));
        *(__nv_bfloat162*)(lop + 4) = __halves2bfloat162(
            __float2bfloat16_rn(nv.z - __bfloat162float(h2)),
            __float2bfloat16_rn(nv.w - __bfloat162float(h3)));
    }
    __syncthreads();

    const uint32_t aA_lane = (uint32_t)((lane & 15) * 80 + (lane >> 4) * 16);
    const uint32_t aB_lane = (uint32_t)(((lane & 7) + ((lane >> 4) & 1) * 8) * 80
                                        + ((lane >> 3) & 1) * 16);
    const int m2 = wid & 1, n2 = wid >> 1;   // GEMM2 warp tiling

    for (int step = 0; step < 2; step++) {
        // ---- agg_e: reads A (hi+lo), writes EAGG hi/lo
        {
            const int d = t & 127;
            const int ch = d >> 5, co = (d & 31) * 2;
            const char* hip = smx + HG_A(ch, 0) + co;
            const char* lop = smx + HG_A(ch, 1) + co;
            for (int e = t >> 7; e < En; e += 2) {
                float acc = 0.f;
                #pragma unroll 8
                for (int n = 0; n < Nn; n++) {
                    const float val = __bfloat162float(*(const __nv_bfloat16*)(hip + n * 80))
                                    + __bfloat162float(*(const __nv_bfloat16*)(lop + n * 80));
                    acc += s_adj[n * En + e] * val;
                }
                const float v = acc / s_dege[e];
                const __nv_bfloat16 h = __float2bfloat16_rn(v);
                *(__nv_bfloat16*)(smx + HG_EAGG(ch, 0) + e * 80 + co) = h;
                *(__nv_bfloat16*)(smx + HG_EAGG(ch, 1) + e * 80 + co) =
                    __float2bfloat16_rn(v - __bfloat162float(h));
            }
        }
        hg_load_wchunk(sb, 0, g_wet_hi, g_wet_lo, 0, t);
        CP_COMMIT();
        __syncthreads();

        // ---- GEMM1: e_h[16,128] = eagg . w_edge^T (3-term HMMA)
        {
            float acc1[2][4];
            #pragma unroll
            for (int j = 0; j < 2; j++)
                #pragma unroll
                for (int r = 0; r < 4; r++) acc1[j][r] = 0.f;

            for (int kc = 0; kc < 4; kc++) {
                const int buf = kc & 1;
                if (kc < 3) {
                    hg_load_wchunk(sb, buf ^ 1, g_wet_hi, g_wet_lo, kc + 1, t);
                    CP_COMMIT();
                    CP_WAIT(1);
                } else {
                    CP_WAIT(0);
                }
                __syncthreads();
                const uint32_t baseA = sb + HG_EAGG(kc, 0) + aA_lane;
                const uint32_t baseB = sb + HG_W(buf, 0) + (uint32_t)(wid * 16) * 80 + aB_lane;
                #pragma unroll
                for (int ks = 0; ks < 2; ks++) {
                    const uint32_t koff = (uint32_t)ks * 32;
                    uint32_t ah[4], al[4], bh4[4], bl4[4];
                    ldsm4(ah, baseA + koff);
                    ldsm4(al, baseA + ECH + koff);
                    ldsm4(bh4, baseB + koff);
                    ldsm4(bl4, baseB + 10240 + koff);
                    #pragma unroll
                    for (int jj = 0; jj < 2; jj++) {
                        const uint32_t* bh = &bh4[jj * 2];
                        const uint32_t* bl = &bl4[jj * 2];
                        mma16816(acc1[jj], ah, bh);
                        mma16816(acc1[jj], ah, bl);
                        mma16816(acc1[jj], al, bh);
                    }
                }
                __syncthreads();
            }
            // epilogue -> s_eh fp32 [16][132]
            const int r0 = lane >> 2;
            const int colb = wid * 16 + (lane & 3) * 2;
            #pragma unroll
            for (int jj = 0; jj < 2; jj++) {
                const int col = colb + jj * 8;
                *(float2*)&s_eh[r0 * 132 + col]       = make_float2(acc1[jj][0], acc1[jj][1]);
                *(float2*)&s_eh[(r0 + 8) * 132 + col] = make_float2(acc1[jj][2], acc1[jj][3]);
            }
        }
        __syncthreads();

        // prefetch GEMM2 weight chunk 0 (overlaps agg_n)
        hg_load_wchunk(sb, 0, g_wnt_hi, g_wnt_lo, 0, t);
        CP_COMMIT();

        // ---- agg_n: reads s_eh fp32, writes A region (nagg hi/lo, overwrites n_h)
        {
            const int d = t & 127;
            const int ch = d >> 5, co = (d & 31) * 2;
            for (int n = t >> 7; n < Nn; n += 2) {
                float acc = 0.f;
                #pragma unroll
                for (int e = 0; e < En; e++) acc += s_adj[n * En + e] * s_eh[e * 132 + d];
                const float v = acc / s_degn[n];
                const __nv_bfloat16 h = __float2bfloat16_rn(v);
                *(__nv_bfloat16*)(smx + HG_A(ch, 0) + n * 80 + co) = h;
                *(__nv_bfloat16*)(smx + HG_A(ch, 1) + n * 80 + co) =
                    __float2bfloat16_rn(v - __bfloat162float(h));
            }
        }
        __syncthreads();

        // ---- GEMM2: n_h[64,128] = nagg . w_node^T (3-term HMMA), in-place epilogue
        {
            float acc2[2][4][4];
            #pragma unroll
            for (int i = 0; i < 2; i++)
                #pragma unroll
                for (int j = 0; j < 4; j++)
                    #pragma unroll
                    for (int r = 0; r < 4; r++) acc2[i][j][r] = 0.f;

            for (int kc = 0; kc < 4; kc++) {
                const int buf = kc & 1;
                if (kc < 3) {
                    hg_load_wchunk(sb, buf ^ 1, g_wnt_hi, g_wnt_lo, kc + 1, t);
                    CP_COMMIT();
                    CP_WAIT(1);
                } else {
                    CP_WAIT(0);
                }
                __syncthreads();
                const uint32_t baseA = sb + HG_A(kc, 0) + (uint32_t)(m2 * 32) * 80 + aA_lane;
                const uint32_t baseB = sb + HG_W(buf, 0) + (uint32_t)(n2 * 32) * 80 + aB_lane;
                #pragma unroll
                for (int ks = 0; ks < 2; ks++) {
                    const uint32_t koff = (uint32_t)ks * 32;
                    uint32_t ah[2][4], al[2][4], bh4[2][4], bl4[2][4];
                    #pragma unroll
                    for (int i = 0; i < 2; i++) {
                        ldsm4(ah[i], baseA + (uint32_t)(i * 16) * 80 + koff);
                        ldsm4(al[i], baseA + ACH + (uint32_t)(i * 16) * 80 + koff);
                    }
                    #pragma unroll
                    for (int j4 = 0; j4 < 2; j4++) {
                        ldsm4(bh4[j4], baseB + (uint32_t)(j4 * 16) * 80 + koff);
                        ldsm4(bl4[j4], baseB + 10240 + (uint32_t)(j4 * 16) * 80 + koff);
                    }
                    #pragma unroll
                    for (int i = 0; i < 2; i++)
                        #pragma unroll
                        for (int jj = 0; jj < 4; jj++) {
                            const uint32_t* bh = &bh4[jj >> 1][(jj & 1) * 2];
                            const uint32_t* bl = &bl4[jj >> 1][(jj & 1) * 2];
                            mma16816(acc2[i][jj], ah[i], bh);
                            mma16816(acc2[i][jj], ah[i], bl);
                            mma16816(acc2[i][jj], al[i], bh);
                        }
                }
                __syncthreads();
            }
            // epilogue: write n_h hi/lo back into A region (chunk = n2)
            #pragma unroll
            for (int i = 0; i < 2; i++)
                #pragma unroll
                for (int jj = 0; jj < 4; jj++) {
                    const int r = m2 * 32 + 16 * i + (lane >> 2);
                    const int c = jj * 8 + (lane & 3) * 2;   // within chunk n2
                    const float a0 = acc2[i][jj][0], a1 = acc2[i][jj][1];
                    const float a2 = acc2[i][jj][2], a3 = acc2[i][jj][3];
                    __nv_bfloat16 h0 = __float2bfloat16_rn(a0), h1 = __float2bfloat16_rn(a1);
                    __nv_bfloat16 h2 = __float2bfloat16_rn(a2), h3 = __float2bfloat16_rn(a3);
                    char* hip = smx + HG_A(n2, 0);
                    char* lop = smx + HG_A(n2, 1);
                    *(__nv_bfloat162*)(hip + r * 80 + c * 2) = __halves2bfloat162(h0, h1);
                    *(__nv_bfloat162*)(hip + (r + 8) * 80 + c * 2) = __halves2bfloat162(h2, h3);
                    *(__nv_bfloat162*)(lop + r * 80 + c * 2) = __halves2bfloat162(
                        __float2bfloat16_rn(a0 - __bfloat162float(h0)),
                        __float2bfloat16_rn(a1 - __bfloat162float(h1)));
                    *(__nv_bfloat162*)(lop + (r + 8) * 80 + c * 2) = __halves2bfloat162(
                        __float2bfloat16_rn(a2 - __bfloat162float(h2)),
                        __float2bfloat16_rn(a3 - __bfloat162float(h3)));
                }
        }
        __syncthreads();
    }

    // final: g_nodes_h fp32 = hi + lo
    for (int f = t; f < Nn * Hn; f += 256) {
        const int n = f >> 7, d = f & 127;
        const int ch = d >> 5, co = (d & 31) * 2;
        const float val =
            __bfloat162float(*(const __nv_bfloat16*)(smx + HG_A(ch, 0) + n * 80 + co))
          + __bfloat162float(*(const __nv_bfloat16*)(smx + HG_A(ch, 1) + n * 80 + co));
        g_nodes_h[(size_t)b * Nn * Hn + f] = val;
    }
}

// =============================================================================
// prep_w: transpose + split w_edge/w_node [128,128] + q2_w [256,256] (R10 proven)
// =============================================================================
__global__ void __launch_bounds__(256)
prep_w(const float* __restrict__ w_edge, const float* __restrict__ w_node,
       const float* __restrict__ q2_w) {
    const int idx = blockIdx.x * 256 + threadIdx.x;
    if (idx < 16384) {
        const int k = idx >> 7, n = idx & 127;
        sthilo(g_wet_hi, g_wet_lo, (size_t)n * 128 + k, w_edge[idx]);
    } else if (idx < 32768) {
        const int i2 = idx - 16384;
        const int k = i2 >> 7, n = i2 & 127;
        sthilo(g_wnt_hi, g_wnt_lo, (size_t)n * 128 + k, w_node[i2]);
    } else if (idx < 98304) {
        const int i2 = idx - 32768;
        const int k = i2 >> 8, n = i2 & 255;
        sthilo(g_q2t_hi, g_q2t_lo, (size_t)n * 256 + k, q2_w[i2]);
    }
}

// =============================================================================
// seqbuild (R7/R11 proven)
// =============================================================================
__global__ void __launch_bounds__(256)
seqbuild(const int* __restrict__ alias_item, const int* __restrict__ alias_cate) {
    const int rr = blockIdx.x * 8 + (threadIdx.x >> 5);
    const int lane = threadIdx.x & 31;
    if (rr >= Bn * Ln) return;
    const int b = rr / Ln;
    const int ai = alias_item[rr];
    const int ac = alias_cate[rr];
    const float4 vi = ((const float4*)(g_nodes_h + (size_t)(b * Nn + ai) * Hn))[lane];
    const float4 vc = ((const float4*)(g_nodes_h + (size_t)(b * Nn + ac) * Hn))[lane];
    float ss = vi.x*vi.x + vi.y*vi.y + vi.z*vi.z + vi.w*vi.w
             + vc.x*vc.x + vc.y*vc.y + vc.z*vc.z + vc.w*vc.w;
    #pragma unroll
    for (int o = 16; o > 0; o >>= 1) ss += __shfl_xor_sync(0xffffffffu, ss, o);
    const float inv = 1.0f / fmaxf(sqrtf(ss), EPS);
    const float4 ni = make_float4(vi.x*inv, vi.y*inv, vi.z*inv, vi.w*inv);
    const float4 nc = make_float4(vc.x*inv, vc.y*inv, vc.z*inv, vc.w*inv);
    ((float4*)(g_seq_f32 + (size_t)rr * Dn))[lane]      = ni;
    ((float4*)(g_seq_f32 + (size_t)rr * Dn))[lane + 32] = nc;
    store4_hilo(g_seq_hi + (size_t)rr * Dn, g_seq_lo + (size_t)rr * Dn, lane * 4, ni);
    store4_hilo(g_seq_hi + (size_t)rr * Dn, g_seq_lo + (size_t)rr * Dn, 128 + lane * 4, nc);
}

// =============================================================================
// attn_lite (R7 proven)
// =============================================================================
__global__ void __launch_bounds__(256, 2)
attn_lite(const int* __restrict__ item_seq,
          const float* __restrict__ q1_w, const float* __restrict__ q1_b,
          const float* __restrict__ v_w) {
    __shared__ float s_ht[Dn];
    __shared__ float s_part[Ln * 8];
    __shared__ float s_alpha[Ln + 2];
    __shared__ float s_mask[Ln + 2];
    __shared__ float s_red[8];
    __shared__ float s_bcast;
    __shared__ int   s_last;

    const int b = blockIdx.x;
    const int t = threadIdx.x;
    const int lane = t & 31, wid = t >> 5;

    if (t < Ln) s_mask[t] = (item_seq[b * Ln + t] > 0) ? 1.0f : 0.0f;
    if (t == 0) {
        int cnt = 0;
        for (int l = 0; l < Ln; l++) cnt += (item_seq[b * Ln + l] > 0) ? 1 : 0;
        s_last = max(cnt - 1, 0);
    }
    __syncthreads();
    s_ht[t] = g_seq_f32[((size_t)b * Ln + s_last) * Dn + t];
    __syncthreads();

    float q1v = 0.f;
    #pragma unroll 4
    for (int d = 0; d < Dn; d++) q1v += s_ht[d] * q1_w[d * Dn + t];
    q1v += q1_b[t];

    const float vw = v_w[t];
    for (int l = 0; l < Ln; l++) {
        const float x = q1v + g_q2[((size_t)b * Ln + l) * Dn + t];
        float c = vw / (1.0f + expf(-x));
        #pragma unroll
        for (int o = 16; o > 0; o >>= 1) c += __shfl_xor_sync(0xffffffffu, c, o);
        if (lane == 0) s_part[l * 8 + wid] = c;
    }
    __syncthreads();
    if (t < Ln) {
        float a = 0.f;
        #pragma unroll
        for (int w = 0; w < 8; w++) a += s_part[t * 8 + w];
        s_alpha[t] = a * s_mask[t];
    }
    __syncthreads();

    float outacc = 0.f;
    #pragma unroll 5
    for (int l = 0; l < Ln; l++)
        outacc += s_alpha[l] * g_seq_f32[((size_t)b * Ln + l) * Dn + t];

    float ss = outacc * outacc;
    #pragma unroll
    for (int o = 16; o > 0; o >>= 1) ss += __shfl_xor_sync(0xffffffffu, ss, o);
    if (lane == 0) s_red[wid] = ss;
    __syncthreads();
    if (t == 0) {
        float a = 0.f;
        #pragma unroll
        for (int w = 0; w < 8; w++) a += s_red[w];
        s_bcast = a;
    }
    __syncthreads();
    const float inv = 1.0f / fmaxf(sqrtf(s_bcast), EPS);
    sthilo(g_so_hi, g_so_lo, (size_t)b * Dn + t, outacc * inv);
}

// =============================================================================
// itemnorm (R4 proven)
// =============================================================================
__global__ void __launch_bounds__(256)
itemnorm_kernel(const float* __restrict__ embedding, const int* __restrict__ item_cates) {
    const int i = blockIdx.x * 8 + (threadIdx.x >> 5);
    const int lane = threadIdx.x & 31;
    if (i >= ITEMN) return;
    const int c = item_cates[i];
    const float4 vi = ((const float4*)(embedding + (size_t)i * Hn))[lane];
    const float4 vc = ((const float4*)(embedding + (size_t)c * Hn))[lane];
    float ss = vi.x*vi.x + vi.y*vi.y + vi.z*vi.z + vi.w*vi.w
             + vc.x*vc.x + vc.y*vc.y + vc.z*vc.z + vc.w*vc.w;
    #pragma unroll
    for (int o = 16; o > 0; o >>= 1) ss += __shfl_xor_sync(0xffffffffu, ss, o);
    const float inv = 1.0f / fmaxf(sqrtf(ss), EPS);
    __nv_bfloat16* hi = g_item_hi + (size_t)i * Dn;
    __nv_bfloat16* lo = g_item_lo + (size_t)i * Dn;
    store4_hilo(hi, lo, lane * 4, make_float4(vi.x*inv, vi.y*inv, vi.z*inv, vi.w*inv));
    store4_hilo(hi, lo, 128 + lane * 4, make_float4(vc.x*inv, vc.y*inv, vc.z*inv, vc.w*inv));
}

// =============================================================================
// scores via HMMA split-bf16 (R7 proven)
// =============================================================================
__global__ void __launch_bounds__(256, 2)
scores_mma(float* __restrict__ C) {
    extern __shared__ char smc[];
    const uint32_t sb = smem_u32(smc);

    const int t = threadIdx.x;
    const int w = t >> 5, lane = t & 31;
    const int b0 = blockIdx.x * 128;
    const int i0 = blockIdx.y * 128;
    const int warp_m = w & 3;
    const int warp_n = w >> 2;

    const __nv_bfloat16* srcs[4] = {
        g_item_hi + (size_t)i0 * Dn, g_item_lo + (size_t)i0 * Dn,
        g_so_hi  + (size_t)b0 * Dn, g_so_lo  + (size_t)b0 * Dn
    };
    const int ld_row0 = t >> 2, ld_row1 = 64 + (t >> 2), ld_seg = t & 3;

    float acc[2][8][4];
    #pragma unroll
    for (int i = 0; i < 2; i++)
        #pragma unroll
        for (int j = 0; j < 8; j++)
            #pragma unroll
            for (int r = 0; r < 4; r++) acc[i][j][r] = 0.f;

    const uint32_t aA_lane = (uint32_t)((lane & 15) * ROWB + (lane >> 4) * 16);
    const uint32_t aB_lane = (uint32_t)(((lane & 7) + ((lane >> 4) & 1) * 8) * ROWB
                                        + ((lane >> 3) & 1) * 16);

    #pragma unroll
    for (int mat = 0; mat < 4; mat++) {
        cp16(sb + 0 * BUFB + mat * MATB + ld_row0 * ROWB + ld_seg * 16,
             srcs[mat] + (size_t)ld_row0 * Dn + ld_seg * 8);
        cp16(sb + 0 * BUFB + mat * MATB + ld_row1 * ROWB + ld_seg * 16,
             srcs[mat] + (size_t)ld_row1 * Dn + ld_seg * 8);
    }
    CP_COMMIT();

    for (int kc = 0; kc < 8; kc++) {
        const int buf = kc & 1;
        if (kc < 7) {
            const int k0 = (kc + 1) * 32;
            const int nbuf = (kc + 1) & 1;
            #pragma unroll
            for (int mat = 0; mat < 4; mat++) {
                cp16(sb + nbuf * BUFB + mat * MATB + ld_row0 * ROWB + ld_seg * 16,
                     srcs[mat] + (size_t)ld_row0 * Dn + k0 + ld_seg * 8);
                cp16(sb + nbuf * BUFB + mat * MATB + ld_row1 * ROWB + ld_seg * 16,
                     srcs[mat] + (size_t)ld_row1 * Dn + k0 + ld_seg * 8);
            }
            CP_COMMIT();
            CP_WAIT(1);
        } else {
            CP_WAIT(0);
        }
        __syncthreads();

        const uint32_t baseA = sb + buf * BUFB + (uint32_t)(warp_m * 32) * ROWB + aA_lane;
        const uint32_t baseB = sb + buf * BUFB + (uint32_t)(warp_n * 64) * ROWB + aB_lane;

        #pragma unroll
        for (int ks = 0; ks < 2; ks++) {
            const uint32_t koff = (uint32_t)ks * 32;
            uint32_t ahi[2][4], alo[2][4];
            #pragma unroll
            for (int i = 0; i < 2; i++) {
                ldsm4(ahi[i], baseA + 0 * MATB + (uint32_t)(i * 16) * ROWB + koff);
                ldsm4(alo[i], baseA + 1 * MATB + (uint32_t)(i * 16) * ROWB + koff);
            }
            #pragma unroll
            for (int jg = 0; jg < 2; jg++) {
                uint32_t bhi[2][4], blo[2][4];
                #pragma unroll
                for (int j4 = 0; j4 < 2; j4++) {
                    const uint32_t off = (uint32_t)((jg * 2 + j4) * 16) * ROWB + koff;
                    ldsm4(bhi[j4], baseB + 2 * MATB + off);
                    ldsm4(blo[j4], baseB + 3 * MATB + off);
                }
                #pragma unroll
                for (int i = 0; i < 2; i++)
                    #pragma unroll
                    for (int jj = 0; jj < 4; jj++) {
                        const int j = jg * 4 + jj;
                        const uint32_t* bh = &bhi[jj >> 1][(jj & 1) * 2];
                        const uint32_t* bl = &blo[jj >> 1][(jj & 1) * 2];
                        mma16816(acc[i][j], ahi[i], bh);
                        mma16816(acc[i][j], ahi[i], bl);
                        mma16816(acc[i][j], alo[i], bh);
                    }
            }
        }
        __syncthreads();
    }

    const int mrow = i0 + warp_m * 32 + (lane >> 2);
    const int ncol = b0 + warp_n * 64 + (lane & 3) * 2;
    #pragma unroll
    for (int i = 0; i < 2; i++) {
        #pragma unroll
        for (int j = 0; j < 8; j++) {
            const int n = ncol + j * 8;
            const int m = mrow + i * 16;
            if (m < ITEMN) {
                C[(size_t)n       * ITEMN + m]     = 16.f * acc[i][j][0];
                C[(size_t)(n + 1) * ITEMN + m]     = 16.f * acc[i][j][1];
            }
            if (m + 8 < ITEMN) {
                C[(size_t)n       * ITEMN + m + 8] = 16.f * acc[i][j][2];
                C[(size_t)(n + 1) * ITEMN + m + 8] = 16.f * acc[i][j][3];
            }
        }
    }
}

// =============================================================================
// launch — no device symbols passed as kernel args.
// =============================================================================
extern "C" void kernel_launch(void* const* d_in, const int* in_sizes, int n_in,
                              void* d_out, int out_size) {
    const int*   item_seq   = (const int*)  d_in[0];
    /* label d_in[1] unused */
    const int*   nodes      = (const int*)  d_in[2];
    const float* hn_adj     = (const float*)d_in[3];
    const int*   alias_item = (const int*)  d_in[4];
    const int*   alias_cate = (const int*)  d_in[5];
    const float* embedding  = (const float*)d_in[6];
    const int*   item_cates = (const int*)  d_in[7];
    const float* w_edge     = (const float*)d_in[8];
    const float* w_node     = (const float*)d_in[9];
    const float* q1_w       = (const float*)d_in[10];
    const float* q1_b       = (const float*)d_in[11];
    const float* q2_w       = (const float*)d_in[12];
    const float* v_w        = (const float*)d_in[13];
    float* out = (float*)d_out;

    cudaFuncSetAttribute(hgnn_mma,  cudaFuncAttributeMaxDynamicSharedMemorySize, HGM_SMEM);
    cudaFuncSetAttribute(gemm3_q2,  cudaFuncAttributeMaxDynamicSharedMemorySize, SC_SMEM);
    cudaFuncSetAttribute(scores_mma, cudaFuncAttributeMaxDynamicSharedMemorySize, SC_SMEM);

    prep_w<<<384, 256>>>(w_edge, w_node, q2_w);
    itemnorm_kernel<<<(ITEMN + 7) / 8, 256>>>(embedding, item_cates);
    hgnn_mma<<<Bn, 256, HGM_SMEM>>>(nodes, hn_adj, embedding);

    seqbuild<<<Bn * Ln / 8, 256>>>(alias_item, alias_cate);
    gemm3_q2<<<dim3(Bn * Ln / 128, 2), 256, SC_SMEM>>>();
    attn_lite<<<Bn, 256>>>(item_seq, q1_w, q1_b, v_w);

    scores_mma<<<dim3(4, ITEMP / 128), 256, SC_SMEM>>>(out);
}

// round 13
// speedup vs baseline: 1.6835x; 1.1486x over previous
#include <cuda_runtime.h>
#include <cuda_bf16.h>
#include <cuda_fp16.h>
#include <math.h>
#include <stdint.h>

#define Bn 512
#define Ln 50
#define Nn 64
#define En 16
#define Hn 128
#define Dn 256
#define ITEMN 100000
#define ITEMP 100096
#define EPS 1e-12f

// ------------------------- scratch (no allocs allowed) -------------------------
// Device globals are ONLY referenced inside device code (never host kernel args).
__device__ float g_nodes_h[Bn * Nn * Hn];
__device__ float g_seq_f32[25600 * 256];
__device__ __nv_bfloat16 g_seq_hi[25600 * 256];
__device__ __nv_bfloat16 g_seq_lo[25600 * 256];
__device__ float g_q2[25600 * 256];
__device__ __nv_bfloat16 g_wet_hi[128 * 128], g_wet_lo[128 * 128];
__device__ __nv_bfloat16 g_wnt_hi[128 * 128], g_wnt_lo[128 * 128];
__device__ __nv_bfloat16 g_q2t_hi[256 * 256], g_q2t_lo[256 * 256];
__device__ __half g_so_hi[Bn * Dn], g_so_lo[Bn * Dn];        // fp16 hi/lo
__device__ __half g_item_f16[(size_t)ITEMP * Dn];            // fp16 single, 51.2 MB

// ============================= PTX helpers =============================
__device__ __forceinline__ uint32_t smem_u32(const void* p) {
    uint32_t a;
    asm("{ .reg .u64 t; cvta.to.shared.u64 t, %1; cvt.u32.u64 %0, t; }" : "=r"(a) : "l"(p));
    return a;
}
__device__ __forceinline__ void cp16(uint32_t dst, const void* src) {
    asm volatile("cp.async.cg.shared.global [%0], [%1], 16;" :: "r"(dst), "l"(src));
}
#define CP_COMMIT() asm volatile("cp.async.commit_group;" ::: "memory")
#define CP_WAIT(n)  asm volatile("cp.async.wait_group %0;" :: "n"(n) : "memory")

__device__ __forceinline__ void ldsm4(uint32_t* r, uint32_t addr) {
    asm volatile("ldmatrix.sync.aligned.m8n8.x4.shared.b16 {%0,%1,%2,%3}, [%4];"
                 : "=r"(r[0]), "=r"(r[1]), "=r"(r[2]), "=r"(r[3]) : "r"(addr));
}
__device__ __forceinline__ void mma16816(float* d, const uint32_t* a, const uint32_t* b) {
    asm volatile(
        "mma.sync.aligned.m16n8k16.row.col.f32.bf16.bf16.f32 "
        "{%0,%1,%2,%3}, {%4,%5,%6,%7}, {%8,%9}, {%0,%1,%2,%3};"
        : "+f"(d[0]), "+f"(d[1]), "+f"(d[2]), "+f"(d[3])
        : "r"(a[0]), "r"(a[1]), "r"(a[2]), "r"(a[3]), "r"(b[0]), "r"(b[1]));
}
__device__ __forceinline__ void mma16816h(float* d, const uint32_t* a, const uint32_t* b) {
    asm volatile(
        "mma.sync.aligned.m16n8k16.row.col.f32.f16.f16.f32 "
        "{%0,%1,%2,%3}, {%4,%5,%6,%7}, {%8,%9}, {%0,%1,%2,%3};"
        : "+f"(d[0]), "+f"(d[1]), "+f"(d[2]), "+f"(d[3])
        : "r"(a[0]), "r"(a[1]), "r"(a[2]), "r"(a[3]), "r"(b[0]), "r"(b[1]));
}
__device__ __forceinline__ void sthilo(__nv_bfloat16* hi, __nv_bfloat16* lo,
                                       size_t idx, float v) {
    __nv_bfloat16 h = __float2bfloat16_rn(v);
    hi[idx] = h;
    lo[idx] = __float2bfloat16_rn(v - __bfloat162float(h));
}
__device__ __forceinline__ void sthilo_h(__half* hi, __half* lo, size_t idx, float v) {
    __half h = __float2half_rn(v);
    hi[idx] = h;
    lo[idx] = __float2half_rn(v - __half2float(h));
}
__device__ __forceinline__ void store4_hilo(__nv_bfloat16* hi, __nv_bfloat16* lo,
                                            int c, float4 v) {
    __nv_bfloat16 h0 = __float2bfloat16_rn(v.x), h1 = __float2bfloat16_rn(v.y);
    __nv_bfloat16 h2 = __float2bfloat16_rn(v.z), h3 = __float2bfloat16_rn(v.w);
    *(__nv_bfloat162*)(hi + c)     = __halves2bfloat162(h0, h1);
    *(__nv_bfloat162*)(hi + c + 2) = __halves2bfloat162(h2, h3);
    __nv_bfloat16 l0 = __float2bfloat16_rn(v.x - __bfloat162float(h0));
    __nv_bfloat16 l1 = __float2bfloat16_rn(v.y - __bfloat162float(h1));
    __nv_bfloat16 l2 = __float2bfloat16_rn(v.z - __bfloat162float(h2));
    __nv_bfloat16 l3 = __float2bfloat16_rn(v.w - __bfloat162float(h3));
    *(__nv_bfloat162*)(lo + c)     = __halves2bfloat162(l0, l1);
    *(__nv_bfloat162*)(lo + c + 2) = __halves2bfloat162(l2, l3);
}

// =============================================================================
// Shared split-bf16 HMMA GEMM body (R10/R11 PROVEN) — used for q2
// =============================================================================
#define ROWB 80
#define MATB (128 * ROWB)
#define BUFB (4 * MATB)
#define SC_SMEM (2 * BUFB)

template<int KTOT, int N>
__device__ __forceinline__ void gemm3_body(
    const __nv_bfloat16* __restrict__ Ahi, const __nv_bfloat16* __restrict__ Alo,
    const __nv_bfloat16* __restrict__ Whi, const __nv_bfloat16* __restrict__ Wlo,
    float* __restrict__ C) {
    extern __shared__ char smc[];
    const uint32_t sb = smem_u32(smc);
    const int t = threadIdx.x;
    const int w = t >> 5, lane = t & 31;
    const int m0 = blockIdx.x * 128;
    const int n0 = blockIdx.y * 128;
    const int warp_m = w & 3;
    const int warp_n = w >> 2;

    const __nv_bfloat16* srcs[4] = {
        Ahi + (size_t)m0 * KTOT, Alo + (size_t)m0 * KTOT,
        Whi + (size_t)n0 * KTOT, Wlo + (size_t)n0 * KTOT
    };
    const int ld_row0 = t >> 2,  ld_row1 = 64 + (t >> 2), ld_seg = t & 3;

    float acc[2][8][4];
    #pragma unroll
    for (int i = 0; i < 2; i++)
        #pragma unroll
        for (int j = 0; j < 8; j++)
            #pragma unroll
            for (int r = 0; r < 4; r++) acc[i][j][r] = 0.f;

    const uint32_t aA_lane = (uint32_t)((lane & 15) * ROWB + (lane >> 4) * 16);
    const uint32_t aB_lane = (uint32_t)(((lane & 7) + ((lane >> 4) & 1) * 8) * ROWB
                                        + ((lane >> 3) & 1) * 16);

    #pragma unroll
    for (int mat = 0; mat < 4; mat++) {
        cp16(sb + 0 * BUFB + mat * MATB + ld_row0 * ROWB + ld_seg * 16,
             srcs[mat] + (size_t)ld_row0 * KTOT + ld_seg * 8);
        cp16(sb + 0 * BUFB + mat * MATB + ld_row1 * ROWB + ld_seg * 16,
             srcs[mat] + (size_t)ld_row1 * KTOT + ld_seg * 8);
    }
    CP_COMMIT();

    const int NCH = KTOT / 32;
    for (int kc = 0; kc < NCH; kc++) {
        const int buf = kc & 1;
        if (kc < NCH - 1) {
            const int k0 = (kc + 1) * 32;
            const int nbuf = (kc + 1) & 1;
            #pragma unroll
            for (int mat = 0; mat < 4; mat++) {
                cp16(sb + nbuf * BUFB + mat * MATB + ld_row0 * ROWB + ld_seg * 16,
                     srcs[mat] + (size_t)ld_row0 * KTOT + k0 + ld_seg * 8);
                cp16(sb + nbuf * BUFB + mat * MATB + ld_row1 * ROWB + ld_seg * 16,
                     srcs[mat] + (size_t)ld_row1 * KTOT + k0 + ld_seg * 8);
            }
            CP_COMMIT();
            CP_WAIT(1);
        } else {
            CP_WAIT(0);
        }
        __syncthreads();

        const uint32_t baseA = sb + buf * BUFB + (uint32_t)(warp_m * 32) * ROWB + aA_lane;
        const uint32_t baseB = sb + buf * BUFB + (uint32_t)(warp_n * 64) * ROWB + aB_lane;

        #pragma unroll
        for (int ks = 0; ks < 2; ks++) {
            const uint32_t koff = (uint32_t)ks * 32;
            uint32_t ahi[2][4], alo[2][4];
            #pragma unroll
            for (int i = 0; i < 2; i++) {
                ldsm4(ahi[i], baseA + 0 * MATB + (uint32_t)(i * 16) * ROWB + koff);
                ldsm4(alo[i], baseA + 1 * MATB + (uint32_t)(i * 16) * ROWB + koff);
            }
            #pragma unroll
            for (int jg = 0; jg < 2; jg++) {
                uint32_t bhi[2][4], blo[2][4];
                #pragma unroll
                for (int j4 = 0; j4 < 2; j4++) {
                    const uint32_t off = (uint32_t)((jg * 2 + j4) * 16) * ROWB + koff;
                    ldsm4(bhi[j4], baseB + 2 * MATB + off);
                    ldsm4(blo[j4], baseB + 3 * MATB + off);
                }
                #pragma unroll
                for (int i = 0; i < 2; i++)
                    #pragma unroll
                    for (int jj = 0; jj < 4; jj++) {
                        const int j = jg * 4 + jj;
                        const uint32_t* bh = &bhi[jj >> 1][(jj & 1) * 2];
                        const uint32_t* bl = &blo[jj >> 1][(jj & 1) * 2];
                        mma16816(acc[i][j], ahi[i], bh);
                        mma16816(acc[i][j], ahi[i], bl);
                        mma16816(acc[i][j], alo[i], bh);
                    }
            }
        }
        __syncthreads();
    }

    const int mrow = m0 + warp_m * 32 + (lane >> 2);
    const int ncol = n0 + warp_n * 64 + (lane & 3) * 2;
    #pragma unroll
    for (int i = 0; i < 2; i++) {
        #pragma unroll
        for (int j = 0; j < 8; j++) {
            const int m = mrow + i * 16;
            const int n = ncol + j * 8;
            *(float2*)(C + (size_t)m * N + n)       = make_float2(acc[i][j][0], acc[i][j][1]);
            *(float2*)(C + (size_t)(m + 8) * N + n) = make_float2(acc[i][j][2], acc[i][j][3]);
        }
    }
}

__global__ void __launch_bounds__(256, 2) gemm3_q2() {
    gemm3_body<256, 256>(g_seq_hi, g_seq_lo, g_q2t_hi, g_q2t_lo, g_q2);
}

// =============================================================================
// hgnn_mma: fused per-batch GNN with in-kernel HMMA GEMMs (R12 PROVEN).
// =============================================================================
#define ACH 5120
#define ECH 1280
#define HG_A(kc, mat)    (((kc) * 2 + (mat)) * ACH)
#define HG_EAGG(kc, mat) (40960 + ((kc) * 2 + (mat)) * ECH)
#define HG_EH            51200
#define HG_W(buf, mat)   (59648 + (buf) * 20480 + (mat) * 10240)
#define HG_ADJ           100608
#define HG_DEGE          104704
#define HG_DEGN          (104704 + 64)
#define HG_IDX           (104704 + 64 + 256)
#define HGM_SMEM         105472

__device__ __forceinline__ void hg_load_wchunk(uint32_t sb, int buf,
    const __nv_bfloat16* Whi, const __nv_bfloat16* Wlo, int kc, int t) {
    #pragma unroll
    for (int h = 0; h < 2; h++) {
        const int e = h * 256 + t;
        const int row = e >> 2, seg = e & 3;
        cp16(sb + HG_W(buf, 0) + row * 80 + seg * 16,
             Whi + (size_t)row * 128 + kc * 32 + seg * 8);
        cp16(sb + HG_W(buf, 1) + row * 80 + seg * 16,
             Wlo + (size_t)row * 128 + kc * 32 + seg * 8);
    }
}

__global__ void __launch_bounds__(256, 2)
hgnn_mma(const int* __restrict__ nodes, const float* __restrict__ hn_adj,
         const float* __restrict__ embedding) {
    extern __shared__ char smx[];
    const uint32_t sb = smem_u32(smx);
    float* s_adj  = (float*)(smx + HG_ADJ);
    float* s_eh   = (float*)(smx + HG_EH);
    float* s_dege = (float*)(smx + HG_DEGE);
    float* s_degn = (float*)(smx + HG_DEGN);
    int*   s_idx  = (int*)(smx + HG_IDX);

    const int b = blockIdx.x;
    const int t = threadIdx.x;
    const int lane = t & 31, wid = t >> 5;

    {
        const float* adjb = hn_adj + (size_t)b * Nn * En;
        for (int i = t; i < Nn * En; i += 256) s_adj[i] = adjb[i];
        if (t < Nn) s_idx[t] = nodes[b * Nn + t];
    }
    __syncthreads();

    if (t < En) {
        float s = 0.f;
        #pragma unroll 8
        for (int n = 0; n < Nn; n++) s += s_adj[n * En + t];
        s_dege[t] = fmaxf(s, 1.0f);
    }
    if (t >= 32 && t < 32 + Nn) {
        const int n = t - 32;
        float s = 0.f;
        #pragma unroll
        for (int e = 0; e < En; e++) s += s_adj[n * En + e];
        s_degn[n] = fmaxf(s, 1.0f);
    }

    for (int n = wid; n < Nn; n += 8) {
        const float4 v = ((const float4*)(embedding + (size_t)s_idx[n] * Hn))[lane];
        float ss = v.x * v.x + v.y * v.y + v.z * v.z + v.w * v.w;
        #pragma unroll
        for (int o = 16; o > 0; o >>= 1) ss += __shfl_xor_sync(0xffffffffu, ss, o);
        const float inv = 1.0f / fmaxf(sqrtf(ss), EPS);
        const float4 nv = make_float4(v.x * inv, v.y * inv, v.z * inv, v.w * inv);
        const int chunk = lane >> 3;
        const int c = (lane & 7) * 4;
        __nv_bfloat16 h0 = __float2bfloat16_rn(nv.x), h1 = __float2bfloat16_rn(nv.y);
        __nv_bfloat16 h2 = __float2bfloat16_rn(nv.z), h3 = __float2bfloat16_rn(nv.w);
        char* hip = smx + HG_A(chunk, 0) + n * 80 + c * 2;
        char* lop = smx + HG_A(chunk, 1) + n * 80 + c * 2;
        *(__nv_bfloat162*)(hip)     = __halves2bfloat162(h0, h1);
        *(__nv_bfloat162*)(hip + 4) = __halves2bfloat162(h2, h3);
        *(__nv_bfloat162*)(lop) = __halves2bfloat162(
            __float2bfloat16_rn(nv.x - __bfloat162float(h0)),
            __float2bfloat16_rn(nv.y - __bfloat162float(h1)));
        *(__nv_bfloat162*)(lop + 4) = __halves2bfloat162(
            __float2bfloat16_rn(nv.z - __bfloat162float(h2)),
            __float2bfloat16_rn(nv.w - __bfloat162float(h3)));
    }
    __syncthreads();

    const uint32_t aA_lane = (uint32_t)((lane & 15) * 80 + (lane >> 4) * 16);
    const uint32_t aB_lane = (uint32_t)(((lane & 7) + ((lane >> 4) & 1) * 8) * 80
                                        + ((lane >> 3) & 1) * 16);
    const int m2 = wid & 1, n2 = wid >> 1;

    for (int step = 0; step < 2; step++) {
        {
            const int d = t & 127;
            const int ch = d >> 5, co = (d & 31) * 2;
            const char* hip = smx + HG_A(ch, 0) + co;
            const char* lop = smx + HG_A(ch, 1) + co;
            for (int e = t >> 7; e < En; e += 2) {
                float acc = 0.f;
                #pragma unroll 8
                for (int n = 0; n < Nn; n++) {
                    const float val = __bfloat162float(*(const __nv_bfloat16*)(hip + n * 80))
                                    + __bfloat162float(*(const __nv_bfloat16*)(lop + n * 80));
                    acc += s_adj[n * En + e] * val;
                }
                const float v = acc / s_dege[e];
                const __nv_bfloat16 h = __float2bfloat16_rn(v);
                *(__nv_bfloat16*)(smx + HG_EAGG(ch, 0) + e * 80 + co) = h;
                *(__nv_bfloat16*)(smx + HG_EAGG(ch, 1) + e * 80 + co) =
                    __float2bfloat16_rn(v - __bfloat162float(h));
            }
        }
        hg_load_wchunk(sb, 0, g_wet_hi, g_wet_lo, 0, t);
        CP_COMMIT();
        __syncthreads();

        {
            float acc1[2][4];
            #pragma unroll
            for (int j = 0; j < 2; j++)
                #pragma unroll
                for (int r = 0; r < 4; r++) acc1[j][r] = 0.f;

            for (int kc = 0; kc < 4; kc++) {
                const int buf = kc & 1;
                if (kc < 3) {
                    hg_load_wchunk(sb, buf ^ 1, g_wet_hi, g_wet_lo, kc + 1, t);
                    CP_COMMIT();
                    CP_WAIT(1);
                } else {
                    CP_WAIT(0);
                }
                __syncthreads();
                const uint32_t baseA = sb + HG_EAGG(kc, 0) + aA_lane;
                const uint32_t baseB = sb + HG_W(buf, 0) + (uint32_t)(wid * 16) * 80 + aB_lane;
                #pragma unroll
                for (int ks = 0; ks < 2; ks++) {
                    const uint32_t koff = (uint32_t)ks * 32;
                    uint32_t ah[4], al[4], bh4[4], bl4[4];
                    ldsm4(ah, baseA + koff);
                    ldsm4(al, baseA + ECH + koff);
                    ldsm4(bh4, baseB + koff);
                    ldsm4(bl4, baseB + 10240 + koff);
                    #pragma unroll
                    for (int jj = 0; jj < 2; jj++) {
                        const uint32_t* bh = &bh4[jj * 2];
                        const uint32_t* bl = &bl4[jj * 2];
                        mma16816(acc1[jj], ah, bh);
                        mma16816(acc1[jj], ah, bl);
                        mma16816(acc1[jj], al, bh);
                    }
                }
                __syncthreads();
            }
            const int r0 = lane >> 2;
            const int colb = wid * 16 + (lane & 3) * 2;
            #pragma unroll
            for (int jj = 0; jj < 2; jj++) {
                const int col = colb + jj * 8;
                *(float2*)&s_eh[r0 * 132 + col]       = make_float2(acc1[jj][0], acc1[jj][1]);
                *(float2*)&s_eh[(r0 + 8) * 132 + col] = make_float2(acc1[jj][2], acc1[jj][3]);
            }
        }
        __syncthreads();

        hg_load_wchunk(sb, 0, g_wnt_hi, g_wnt_lo, 0, t);
        CP_COMMIT();

        {
            const int d = t & 127;
            const int ch = d >> 5, co = (d & 31) * 2;
            for (int n = t >> 7; n < Nn; n += 2) {
                float acc = 0.f;
                #pragma unroll
                for (int e = 0; e < En; e++) acc += s_adj[n * En + e] * s_eh[e * 132 + d];
                const float v = acc / s_degn[n];
                const __nv_bfloat16 h = __float2bfloat16_rn(v);
                *(__nv_bfloat16*)(smx + HG_A(ch, 0) + n * 80 + co) = h;
                *(__nv_bfloat16*)(smx + HG_A(ch, 1) + n * 80 + co) =
                    __float2bfloat16_rn(v - __bfloat162float(h));
            }
        }
        __syncthreads();

        {
            float acc2[2][4][4];
            #pragma unroll
            for (int i = 0; i < 2; i++)
                #pragma unroll
                for (int j = 0; j < 4; j++)
                    #pragma unroll
                    for (int r = 0; r < 4; r++) acc2[i][j][r] = 0.f;

            for (int kc = 0; kc < 4; kc++) {
                const int buf = kc & 1;
                if (kc < 3) {
                    hg_load_wchunk(sb, buf ^ 1, g_wnt_hi, g_wnt_lo, kc + 1, t);
                    CP_COMMIT();
                    CP_WAIT(1);
                } else {
                    CP_WAIT(0);
                }
                __syncthreads();
                const uint32_t baseA = sb + HG_A(kc, 0) + (uint32_t)(m2 * 32) * 80 + aA_lane;
                const uint32_t baseB = sb + HG_W(buf, 0) + (uint32_t)(n2 * 32) * 80 + aB_lane;
                #pragma unroll
                for (int ks = 0; ks < 2; ks++) {
                    const uint32_t koff = (uint32_t)ks * 32;
                    uint32_t ah[2][4], al[2][4], bh4[2][4], bl4[2][4];
                    #pragma unroll
                    for (int i = 0; i < 2; i++) {
                        ldsm4(ah[i], baseA + (uint32_t)(i * 16) * 80 + koff);
                        ldsm4(al[i], baseA + ACH + (uint32_t)(i * 16) * 80 + koff);
                    }
                    #pragma unroll
                    for (int j4 = 0; j4 < 2; j4++) {
                        ldsm4(bh4[j4], baseB + (uint32_t)(j4 * 16) * 80 + koff);
                        ldsm4(bl4[j4], baseB + 10240 + (uint32_t)(j4 * 16) * 80 + koff);
                    }
                    #pragma unroll
                    for (int i = 0; i < 2; i++)
                        #pragma unroll
                        for (int jj = 0; jj < 4; jj++) {
                            const uint32_t* bh = &bh4[jj >> 1][(jj & 1) * 2];
                            const uint32_t* bl = &bl4[jj >> 1][(jj & 1) * 2];
                            mma16816(acc2[i][jj], ah[i], bh);
                            mma16816(acc2[i][jj], ah[i], bl);
                            mma16816(acc2[i][jj], al[i], bh);
                        }
                }
                __syncthreads();
            }
            #pragma unroll
            for (int i = 0; i < 2; i++)
                #pragma unroll
                for (int jj = 0; jj < 4; jj++) {
                    const int r = m2 * 32 + 16 * i + (lane >> 2);
                    const int c = jj * 8 + (lane & 3) * 2;
                    const float a0 = acc2[i][jj][0], a1 = acc2[i][jj][1];
                    const float a2 = acc2[i][jj][2], a3 = acc2[i][jj][3];
                    __nv_bfloat16 h0 = __float2bfloat16_rn(a0), h1 = __float2bfloat16_rn(a1);
                    __nv_bfloat16 h2 = __float2bfloat16_rn(a2), h3 = __float2bfloat16_rn(a3);
                    char* hip = smx + HG_A(n2, 0);
                    char* lop = smx + HG_A(n2, 1);
                    *(__nv_bfloat162*)(hip + r * 80 + c * 2) = __halves2bfloat162(h0, h1);
                    *(__nv_bfloat162*)(hip + (r + 8) * 80 + c * 2) = __halves2bfloat162(h2, h3);
                    *(__nv_bfloat162*)(lop + r * 80 + c * 2) = __halves2bfloat162(
                        __float2bfloat16_rn(a0 - __bfloat162float(h0)),
                        __float2bfloat16_rn(a1 - __bfloat162float(h1)));
                    *(__nv_bfloat162*)(lop + (r + 8) * 80 + c * 2) = __halves2bfloat162(
                        __float2bfloat16_rn(a2 - __bfloat162float(h2)),
                        __float2bfloat16_rn(a3 - __bfloat162float(h3)));
                }
        }
        __syncthreads();
    }

    for (int f = t; f < Nn * Hn; f += 256) {
        const int n = f >> 7, d = f & 127;
        const int ch = d >> 5, co = (d & 31) * 2;
        const float val =
            __bfloat162float(*(const __nv_bfloat16*)(smx + HG_A(ch, 0) + n * 80 + co))
          + __bfloat162float(*(const __nv_bfloat16*)(smx + HG_A(ch, 1) + n * 80 + co));
        g_nodes_h[(size_t)b * Nn * Hn + f] = val;
    }
}

// =============================================================================
// prep_w (R10 proven)
// =============================================================================
__global__ void __launch_bounds__(256)
prep_w(const float* __restrict__ w_edge, const float* __restrict__ w_node,
       const float* __restrict__ q2_w) {
    const int idx = blockIdx.x * 256 + threadIdx.x;
    if (idx < 16384) {
        const int k = idx >> 7, n = idx & 127;
        sthilo(g_wet_hi, g_wet_lo, (size_t)n * 128 + k, w_edge[idx]);
    } else if (idx < 32768) {
        const int i2 = idx - 16384;
        const int k = i2 >> 7, n = i2 & 127;
        sthilo(g_wnt_hi, g_wnt_lo, (size_t)n * 128 + k, w_node[i2]);
    } else if (idx < 98304) {
        const int i2 = idx - 32768;
        const int k = i2 >> 8, n = i2 & 255;
        sthilo(g_q2t_hi, g_q2t_lo, (size_t)n * 256 + k, q2_w[i2]);
    }
}

// =============================================================================
// seqbuild (R7/R11 proven)
// =============================================================================
__global__ void __launch_bounds__(256)
seqbuild(const int* __restrict__ alias_item, const int* __restrict__ alias_cate) {
    const int rr = blockIdx.x * 8 + (threadIdx.x >> 5);
    const int lane = threadIdx.x & 31;
    if (rr >= Bn * Ln) return;
    const int b = rr / Ln;
    const int ai = alias_item[rr];
    const int ac = alias_cate[rr];
    const float4 vi = ((const float4*)(g_nodes_h + (size_t)(b * Nn + ai) * Hn))[lane];
    const float4 vc = ((const float4*)(g_nodes_h + (size_t)(b * Nn + ac) * Hn))[lane];
    float ss = vi.x*vi.x + vi.y*vi.y + vi.z*vi.z + vi.w*vi.w
             + vc.x*vc.x + vc.y*vc.y + vc.z*vc.z + vc.w*vc.w;
    #pragma unroll
    for (int o = 16; o > 0; o >>= 1) ss += __shfl_xor_sync(0xffffffffu, ss, o);
    const float inv = 1.0f / fmaxf(sqrtf(ss), EPS);
    const float4 ni = make_float4(vi.x*inv, vi.y*inv, vi.z*inv, vi.w*inv);
    const float4 nc = make_float4(vc.x*inv, vc.y*inv, vc.z*inv, vc.w*inv);
    ((float4*)(g_seq_f32 + (size_t)rr * Dn))[lane]      = ni;
    ((float4*)(g_seq_f32 + (size_t)rr * Dn))[lane + 32] = nc;
    store4_hilo(g_seq_hi + (size_t)rr * Dn, g_seq_lo + (size_t)rr * Dn, lane * 4, ni);
    store4_hilo(g_seq_hi + (size_t)rr * Dn, g_seq_lo + (size_t)rr * Dn, 128 + lane * 4, nc);
}

// =============================================================================
// attn_lite (R7 proven; output now fp16 hi/lo)
// =============================================================================
__global__ void __launch_bounds__(256, 2)
attn_lite(const int* __restrict__ item_seq,
          const float* __restrict__ q1_w, const float* __restrict__ q1_b,
          const float* __restrict__ v_w) {
    __shared__ float s_ht[Dn];
    __shared__ float s_part[Ln * 8];
    __shared__ float s_alpha[Ln + 2];
    __shared__ float s_mask[Ln + 2];
    __shared__ float s_red[8];
    __shared__ float s_bcast;
    __shared__ int   s_last;

    const int b = blockIdx.x;
    const int t = threadIdx.x;
    const int lane = t & 31, wid = t >> 5;

    if (t < Ln) s_mask[t] = (item_seq[b * Ln + t] > 0) ? 1.0f : 0.0f;
    if (t == 0) {
        int cnt = 0;
        for (int l = 0; l < Ln; l++) cnt += (item_seq[b * Ln + l] > 0) ? 1 : 0;
        s_last = max(cnt - 1, 0);
    }
    __syncthreads();
    s_ht[t] = g_seq_f32[((size_t)b * Ln + s_last) * Dn + t];
    __syncthreads();

    float q1v = 0.f;
    #pragma unroll 4
    for (int d = 0; d < Dn; d++) q1v += s_ht[d] * q1_w[d * Dn + t];
    q1v += q1_b[t];

    const float vw = v_w[t];
    for (int l = 0; l < Ln; l++) {
        const float x = q1v + g_q2[((size_t)b * Ln + l) * Dn + t];
        float c = vw / (1.0f + expf(-x));
        #pragma unroll
        for (int o = 16; o > 0; o >>= 1) c += __shfl_xor_sync(0xffffffffu, c, o);
        if (lane == 0) s_part[l * 8 + wid] = c;
    }
    __syncthreads();
    if (t < Ln) {
        float a = 0.f;
        #pragma unroll
        for (int w = 0; w < 8; w++) a += s_part[t * 8 + w];
        s_alpha[t] = a * s_mask[t];
    }
    __syncthreads();

    float outacc = 0.f;
    #pragma unroll 5
    for (int l = 0; l < Ln; l++)
        outacc += s_alpha[l] * g_seq_f32[((size_t)b * Ln + l) * Dn + t];

    float ss = outacc * outacc;
    #pragma unroll
    for (int o = 16; o > 0; o >>= 1) ss += __shfl_xor_sync(0xffffffffu, ss, o);
    if (lane == 0) s_red[wid] = ss;
    __syncthreads();
    if (t == 0) {
        float a = 0.f;
        #pragma unroll
        for (int w = 0; w < 8; w++) a += s_red[w];
        s_bcast = a;
    }
    __syncthreads();
    const float inv = 1.0f / fmaxf(sqrtf(s_bcast), EPS);
    sthilo_h(g_so_hi, g_so_lo, (size_t)b * Dn + t, outacc * inv);
}

// =============================================================================
// itemnorm: fp16 single output (no lo)
// =============================================================================
__global__ void __launch_bounds__(256)
itemnorm_kernel(const float* __restrict__ embedding, const int* __restrict__ item_cates) {
    const int i = blockIdx.x * 8 + (threadIdx.x >> 5);
    const int lane = threadIdx.x & 31;
    if (i >= ITEMN) return;
    const int c = item_cates[i];
    const float4 vi = ((const float4*)(embedding + (size_t)i * Hn))[lane];
    const float4 vc = ((const float4*)(embedding + (size_t)c * Hn))[lane];
    float ss = vi.x*vi.x + vi.y*vi.y + vi.z*vi.z + vi.w*vi.w
             + vc.x*vc.x + vc.y*vc.y + vc.z*vc.z + vc.w*vc.w;
    #pragma unroll
    for (int o = 16; o > 0; o >>= 1) ss += __shfl_xor_sync(0xffffffffu, ss, o);
    const float inv = 1.0f / fmaxf(sqrtf(ss), EPS);
    __half* dst = g_item_f16 + (size_t)i * Dn;
    *(__half2*)(dst + lane * 4)     = __floats2half2_rn(vi.x * inv, vi.y * inv);
    *(__half2*)(dst + lane * 4 + 2) = __floats2half2_rn(vi.z * inv, vi.w * inv);
    *(__half2*)(dst + 128 + lane * 4)     = __floats2half2_rn(vc.x * inv, vc.y * inv);
    *(__half2*)(dst + 128 + lane * 4 + 2) = __floats2half2_rn(vc.z * inv, vc.w * inv);
}

// =============================================================================
// scores: fp16 asymmetric split — A = item fp16 (single), B = so fp16 hi/lo.
// D = A·Bhi + A·Blo. Same tiling/addressing as proven kernel; 3 smem mats.
// =============================================================================
#define SBUF (3 * MATB)        // A, Bhi, Blo
#define SCF_SMEM (2 * SBUF)    // 61440

__global__ void __launch_bounds__(256, 2)
scores_f16(float* __restrict__ C) {
    extern __shared__ char smc[];
    const uint32_t sb = smem_u32(smc);

    const int t = threadIdx.x;
    const int w = t >> 5, lane = t & 31;
    const int b0 = blockIdx.x * 128;
    const int i0 = blockIdx.y * 128;
    const int warp_m = w & 3;
    const int warp_n = w >> 2;

    const __half* srcA  = g_item_f16 + (size_t)i0 * Dn;
    const __half* srcBh = g_so_hi + (size_t)b0 * Dn;
    const __half* srcBl = g_so_lo + (size_t)b0 * Dn;
    const int ld_row0 = t >> 2, ld_row1 = 64 + (t >> 2), ld_seg = t & 3;

    float acc[2][8][4];
    #pragma unroll
    for (int i = 0; i < 2; i++)
        #pragma unroll
        for (int j = 0; j < 8; j++)
            #pragma unroll
            for (int r = 0; r < 4; r++) acc[i][j][r] = 0.f;

    const uint32_t aA_lane = (uint32_t)((lane & 15) * ROWB + (lane >> 4) * 16);
    const uint32_t aB_lane = (uint32_t)(((lane & 7) + ((lane >> 4) & 1) * 8) * ROWB
                                        + ((lane >> 3) & 1) * 16);

    // prefetch chunk 0
    cp16(sb + 0 * SBUF + 0 * MATB + ld_row0 * ROWB + ld_seg * 16, srcA  + (size_t)ld_row0 * Dn + ld_seg * 8);
    cp16(sb + 0 * SBUF + 0 * MATB + ld_row1 * ROWB + ld_seg * 16, srcA  + (size_t)ld_row1 * Dn + ld_seg * 8);
    cp16(sb + 0 * SBUF + 1 * MATB + ld_row0 * ROWB + ld_seg * 16, srcBh + (size_t)ld_row0 * Dn + ld_seg * 8);
    cp16(sb + 0 * SBUF + 1 * MATB + ld_row1 * ROWB + ld_seg * 16, srcBh + (size_t)ld_row1 * Dn + ld_seg * 8);
    cp16(sb + 0 * SBUF + 2 * MATB + ld_row0 * ROWB + ld_seg * 16, srcBl + (size_t)ld_row0 * Dn + ld_seg * 8);
    cp16(sb + 0 * SBUF + 2 * MATB + ld_row1 * ROWB + ld_seg * 16, srcBl + (size_t)ld_row1 * Dn + ld_seg * 8);
    CP_COMMIT();

    for (int kc = 0; kc < 8; kc++) {
        const int buf = kc & 1;
        if (kc < 7) {
            const int k0 = (kc + 1) * 32;
            const uint32_t nb = sb + (uint32_t)((buf ^ 1)) * SBUF;
            cp16(nb + 0 * MATB + ld_row0 * ROWB + ld_seg * 16, srcA  + (size_t)ld_row0 * Dn + k0 + ld_seg * 8);
            cp16(nb + 0 * MATB + ld_row1 * ROWB + ld_seg * 16, srcA  + (size_t)ld_row1 * Dn + k0 + ld_seg * 8);
            cp16(nb + 1 * MATB + ld_row0 * ROWB + ld_seg * 16, srcBh + (size_t)ld_row0 * Dn + k0 + ld_seg * 8);
            cp16(nb + 1 * MATB + ld_row1 * ROWB + ld_seg * 16, srcBh + (size_t)ld_row1 * Dn + k0 + ld_seg * 8);
            cp16(nb + 2 * MATB + ld_row0 * ROWB + ld_seg * 16, srcBl + (size_t)ld_row0 * Dn + k0 + ld_seg * 8);
            cp16(nb + 2 * MATB + ld_row1 * ROWB + ld_seg * 16, srcBl + (size_t)ld_row1 * Dn + k0 + ld_seg * 8);
            CP_COMMIT();
            CP_WAIT(1);
        } else {
            CP_WAIT(0);
        }
        __syncthreads();

        const uint32_t baseA = sb + buf * SBUF + (uint32_t)(warp_m * 32) * ROWB + aA_lane;
        const uint32_t baseB = sb + buf * SBUF + (uint32_t)(warp_n * 64) * ROWB + aB_lane;

        #pragma unroll
        for (int ks = 0; ks < 2; ks++) {
            const uint32_t koff = (uint32_t)ks * 32;
            uint32_t af[2][4];
            #pragma unroll
            for (int i = 0; i < 2; i++)
                ldsm4(af[i], baseA + (uint32_t)(i * 16) * ROWB + koff);
            #pragma unroll
            for (int jg = 0; jg < 2; jg++) {
                uint32_t bhi[2][4], blo[2][4];
                #pragma unroll
                for (int j4 = 0; j4 < 2; j4++) {
                    const uint32_t off = (uint32_t)((jg * 2 + j4) * 16) * ROWB + koff;
                    ldsm4(bhi[j4], baseB + 1 * MATB + off);
                    ldsm4(blo[j4], baseB + 2 * MATB + off);
                }
                #pragma unroll
                for (int i = 0; i < 2; i++)
                    #pragma unroll
                    for (int jj = 0; jj < 4; jj++) {
                        const int j = jg * 4 + jj;
                        const uint32_t* bh = &bhi[jj >> 1][(jj & 1) * 2];
                        const uint32_t* bl = &blo[jj >> 1][(jj & 1) * 2];
                        mma16816h(acc[i][j], af[i], bh);
                        mma16816h(acc[i][j], af[i], bl);
                    }
            }
        }
        __syncthreads();
    }

    const int mrow = i0 + warp_m * 32 + (lane >> 2);
    const int ncol = b0 + warp_n * 64 + (lane & 3) * 2;
    #pragma unroll
    for (int i = 0; i < 2; i++) {
        #pragma unroll
        for (int j = 0; j < 8; j++) {
            const int n = ncol + j * 8;
            const int m = mrow + i * 16;
            if (m < ITEMN) {
                C[(size_t)n       * ITEMN + m]     = 16.f * acc[i][j][0];
                C[(size_t)(n + 1) * ITEMN + m]     = 16.f * acc[i][j][1];
            }
            if (m + 8 < ITEMN) {
                C[(size_t)n       * ITEMN + m + 8] = 16.f * acc[i][j][2];
                C[(size_t)(n + 1) * ITEMN + m + 8] = 16.f * acc[i][j][3];
            }
        }
    }
}

// =============================================================================
// launch — no device symbols passed as kernel args.
// =============================================================================
extern "C" void kernel_launch(void* const* d_in, const int* in_sizes, int n_in,
                              void* d_out, int out_size) {
    const int*   item_seq   = (const int*)  d_in[0];
    /* label d_in[1] unused */
    const int*   nodes      = (const int*)  d_in[2];
    const float* hn_adj     = (const float*)d_in[3];
    const int*   alias_item = (const int*)  d_in[4];
    const int*   alias_cate = (const int*)  d_in[5];
    const float* embedding  = (const float*)d_in[6];
    const int*   item_cates = (const int*)  d_in[7];
    const float* w_edge     = (const float*)d_in[8];
    const float* w_node     = (const float*)d_in[9];
    const float* q1_w       = (const float*)d_in[10];
    const float* q1_b       = (const float*)d_in[11];
    const float* q2_w       = (const float*)d_in[12];
    const float* v_w        = (const float*)d_in[13];
    float* out = (float*)d_out;

    cudaFuncSetAttribute(hgnn_mma,   cudaFuncAttributeMaxDynamicSharedMemorySize, HGM_SMEM);
    cudaFuncSetAttribute(gemm3_q2,   cudaFuncAttributeMaxDynamicSharedMemorySize, SC_SMEM);
    cudaFuncSetAttribute(scores_f16, cudaFuncAttributeMaxDynamicSharedMemorySize, SCF_SMEM);

    prep_w<<<384, 256>>>(w_edge, w_node, q2_w);
    itemnorm_kernel<<<(ITEMN + 7) / 8, 256>>>(embedding, item_cates);
    hgnn_mma<<<Bn, 256, HGM_SMEM>>>(nodes, hn_adj, embedding);

    seqbuild<<<Bn * Ln / 8, 256>>>(alias_item, alias_cate);
    gemm3_q2<<<dim3(Bn * Ln / 128, 2), 256, SC_SMEM>>>();
    attn_lite<<<Bn, 256>>>(item_seq, q1_w, q1_b, v_w);

    scores_f16<<<dim3(4, ITEMP / 128), 256, SCF_SMEM>>>(out);
}

// round 14
// speedup vs baseline: 2.0008x; 1.1885x over previous
#include <cuda_runtime.h>
#include <cuda_bf16.h>
#include <cuda_fp16.h>
#include <math.h>
#include <stdint.h>

#define Bn 512
#define Ln 50
#define Nn 64
#define En 16
#define Hn 128
#define Dn 256
#define ITEMN 100000
#define ITEMP 100096
#define EPS 1e-12f

// ------------------------- scratch (no allocs allowed) -------------------------
// Device globals are ONLY referenced inside device code (never host kernel args).
__device__ float g_nodes_h[Bn * Nn * Hn];
__device__ float g_seq_f32[25600 * 256];
__device__ __nv_bfloat16 g_seq_hi[25600 * 256];
__device__ __nv_bfloat16 g_seq_lo[25600 * 256];
__device__ float g_q2[25600 * 256];
__device__ __nv_bfloat16 g_wet_hi[128 * 128], g_wet_lo[128 * 128];
__device__ __nv_bfloat16 g_wnt_hi[128 * 128], g_wnt_lo[128 * 128];
__device__ __nv_bfloat16 g_q2t_hi[256 * 256], g_q2t_lo[256 * 256];
__device__ __half g_so_f16[Bn * Dn];                         // fp16 single
__device__ __half g_item_f16[(size_t)ITEMP * Dn];            // fp16 single

// ============================= PTX helpers =============================
__device__ __forceinline__ uint32_t smem_u32(const void* p) {
    uint32_t a;
    asm("{ .reg .u64 t; cvta.to.shared.u64 t, %1; cvt.u32.u64 %0, t; }" : "=r"(a) : "l"(p));
    return a;
}
__device__ __forceinline__ void cp16(uint32_t dst, const void* src) {
    asm volatile("cp.async.cg.shared.global [%0], [%1], 16;" :: "r"(dst), "l"(src));
}
#define CP_COMMIT() asm volatile("cp.async.commit_group;" ::: "memory")
#define CP_WAIT(n)  asm volatile("cp.async.wait_group %0;" :: "n"(n) : "memory")

__device__ __forceinline__ void ldsm4(uint32_t* r, uint32_t addr) {
    asm volatile("ldmatrix.sync.aligned.m8n8.x4.shared.b16 {%0,%1,%2,%3}, [%4];"
                 : "=r"(r[0]), "=r"(r[1]), "=r"(r[2]), "=r"(r[3]) : "r"(addr));
}
__device__ __forceinline__ void mma16816(float* d, const uint32_t* a, const uint32_t* b) {
    asm volatile(
        "mma.sync.aligned.m16n8k16.row.col.f32.bf16.bf16.f32 "
        "{%0,%1,%2,%3}, {%4,%5,%6,%7}, {%8,%9}, {%0,%1,%2,%3};"
        : "+f"(d[0]), "+f"(d[1]), "+f"(d[2]), "+f"(d[3])
        : "r"(a[0]), "r"(a[1]), "r"(a[2]), "r"(a[3]), "r"(b[0]), "r"(b[1]));
}
__device__ __forceinline__ void mma16816h(float* d, const uint32_t* a, const uint32_t* b) {
    asm volatile(
        "mma.sync.aligned.m16n8k16.row.col.f32.f16.f16.f32 "
        "{%0,%1,%2,%3}, {%4,%5,%6,%7}, {%8,%9}, {%0,%1,%2,%3};"
        : "+f"(d[0]), "+f"(d[1]), "+f"(d[2]), "+f"(d[3])
        : "r"(a[0]), "r"(a[1]), "r"(a[2]), "r"(a[3]), "r"(b[0]), "r"(b[1]));
}
__device__ __forceinline__ void sthilo(__nv_bfloat16* hi, __nv_bfloat16* lo,
                                       size_t idx, float v) {
    __nv_bfloat16 h = __float2bfloat16_rn(v);
    hi[idx] = h;
    lo[idx] = __float2bfloat16_rn(v - __bfloat162float(h));
}
__device__ __forceinline__ void store4_hilo(__nv_bfloat16* hi, __nv_bfloat16* lo,
                                            int c, float4 v) {
    __nv_bfloat16 h0 = __float2bfloat16_rn(v.x), h1 = __float2bfloat16_rn(v.y);
    __nv_bfloat16 h2 = __float2bfloat16_rn(v.z), h3 = __float2bfloat16_rn(v.w);
    *(__nv_bfloat162*)(hi + c)     = __halves2bfloat162(h0, h1);
    *(__nv_bfloat162*)(hi + c + 2) = __halves2bfloat162(h2, h3);
    __nv_bfloat16 l0 = __float2bfloat16_rn(v.x - __bfloat162float(h0));
    __nv_bfloat16 l1 = __float2bfloat16_rn(v.y - __bfloat162float(h1));
    __nv_bfloat16 l2 = __float2bfloat16_rn(v.z - __bfloat162float(h2));
    __nv_bfloat16 l3 = __float2bfloat16_rn(v.w - __bfloat162float(h3));
    *(__nv_bfloat162*)(lo + c)     = __halves2bfloat162(l0, l1);
    *(__nv_bfloat162*)(lo + c + 2) = __halves2bfloat162(l2, l3);
}

// =============================================================================
// Shared split-bf16 HMMA GEMM body (R10/R11 PROVEN) — used for q2
// =============================================================================
#define ROWB 80
#define MATB (128 * ROWB)
#define BUFB (4 * MATB)
#define SC_SMEM (2 * BUFB)

template<int KTOT, int N>
__device__ __forceinline__ void gemm3_body(
    const __nv_bfloat16* __restrict__ Ahi, const __nv_bfloat16* __restrict__ Alo,
    const __nv_bfloat16* __restrict__ Whi, const __nv_bfloat16* __restrict__ Wlo,
    float* __restrict__ C) {
    extern __shared__ char smc[];
    const uint32_t sb = smem_u32(smc);
    const int t = threadIdx.x;
    const int w = t >> 5, lane = t & 31;
    const int m0 = blockIdx.x * 128;
    const int n0 = blockIdx.y * 128;
    const int warp_m = w & 3;
    const int warp_n = w >> 2;

    const __nv_bfloat16* srcs[4] = {
        Ahi + (size_t)m0 * KTOT, Alo + (size_t)m0 * KTOT,
        Whi + (size_t)n0 * KTOT, Wlo + (size_t)n0 * KTOT
    };
    const int ld_row0 = t >> 2,  ld_row1 = 64 + (t >> 2), ld_seg = t & 3;

    float acc[2][8][4];
    #pragma unroll
    for (int i = 0; i < 2; i++)
        #pragma unroll
        for (int j = 0; j < 8; j++)
            #pragma unroll
            for (int r = 0; r < 4; r++) acc[i][j][r] = 0.f;

    const uint32_t aA_lane = (uint32_t)((lane & 15) * ROWB + (lane >> 4) * 16);
    const uint32_t aB_lane = (uint32_t)(((lane & 7) + ((lane >> 4) & 1) * 8) * ROWB
                                        + ((lane >> 3) & 1) * 16);

    #pragma unroll
    for (int mat = 0; mat < 4; mat++) {
        cp16(sb + 0 * BUFB + mat * MATB + ld_row0 * ROWB + ld_seg * 16,
             srcs[mat] + (size_t)ld_row0 * KTOT + ld_seg * 8);
        cp16(sb + 0 * BUFB + mat * MATB + ld_row1 * ROWB + ld_seg * 16,
             srcs[mat] + (size_t)ld_row1 * KTOT + ld_seg * 8);
    }
    CP_COMMIT();

    const int NCH = KTOT / 32;
    for (int kc = 0; kc < NCH; kc++) {
        const int buf = kc & 1;
        if (kc < NCH - 1) {
            const int k0 = (kc + 1) * 32;
            const int nbuf = (kc + 1) & 1;
            #pragma unroll
            for (int mat = 0; mat < 4; mat++) {
                cp16(sb + nbuf * BUFB + mat * MATB + ld_row0 * ROWB + ld_seg * 16,
                     srcs[mat] + (size_t)ld_row0 * KTOT + k0 + ld_seg * 8);
                cp16(sb + nbuf * BUFB + mat * MATB + ld_row1 * ROWB + ld_seg * 16,
                     srcs[mat] + (size_t)ld_row1 * KTOT + k0 + ld_seg * 8);
            }
            CP_COMMIT();
            CP_WAIT(1);
        } else {
            CP_WAIT(0);
        }
        __syncthreads();

        const uint32_t baseA = sb + buf * BUFB + (uint32_t)(warp_m * 32) * ROWB + aA_lane;
        const uint32_t baseB = sb + buf * BUFB + (uint32_t)(warp_n * 64) * ROWB + aB_lane;

        #pragma unroll
        for (int ks = 0; ks < 2; ks++) {
            const uint32_t koff = (uint32_t)ks * 32;
            uint32_t ahi[2][4], alo[2][4];
            #pragma unroll
            for (int i = 0; i < 2; i++) {
                ldsm4(ahi[i], baseA + 0 * MATB + (uint32_t)(i * 16) * ROWB + koff);
                ldsm4(alo[i], baseA + 1 * MATB + (uint32_t)(i * 16) * ROWB + koff);
            }
            #pragma unroll
            for (int jg = 0; jg < 2; jg++) {
                uint32_t bhi[2][4], blo[2][4];
                #pragma unroll
                for (int j4 = 0; j4 < 2; j4++) {
                    const uint32_t off = (uint32_t)((jg * 2 + j4) * 16) * ROWB + koff;
                    ldsm4(bhi[j4], baseB + 2 * MATB + off);
                    ldsm4(blo[j4], baseB + 3 * MATB + off);
                }
                #pragma unroll
                for (int i = 0; i < 2; i++)
                    #pragma unroll
                    for (int jj = 0; jj < 4; jj++) {
                        const int j = jg * 4 + jj;
                        const uint32_t* bh = &bhi[jj >> 1][(jj & 1) * 2];
                        const uint32_t* bl = &blo[jj >> 1][(jj & 1) * 2];
                        mma16816(acc[i][j], ahi[i], bh);
                        mma16816(acc[i][j], ahi[i], bl);
                        mma16816(acc[i][j], alo[i], bh);
                    }
            }
        }
        __syncthreads();
    }

    const int mrow = m0 + warp_m * 32 + (lane >> 2);
    const int ncol = n0 + warp_n * 64 + (lane & 3) * 2;
    #pragma unroll
    for (int i = 0; i < 2; i++) {
        #pragma unroll
        for (int j = 0; j < 8; j++) {
            const int m = mrow + i * 16;
            const int n = ncol + j * 8;
            *(float2*)(C + (size_t)m * N + n)       = make_float2(acc[i][j][0], acc[i][j][1]);
            *(float2*)(C + (size_t)(m + 8) * N + n) = make_float2(acc[i][j][2], acc[i][j][3]);
        }
    }
}

__global__ void __launch_bounds__(256, 2) gemm3_q2() {
    gemm3_body<256, 256>(g_seq_hi, g_seq_lo, g_q2t_hi, g_q2t_lo, g_q2);
}

// =============================================================================
// hgnn_mma: fused per-batch GNN with in-kernel HMMA GEMMs (R12 PROVEN).
// =============================================================================
#define ACH 5120
#define ECH 1280
#define HG_A(kc, mat)    (((kc) * 2 + (mat)) * ACH)
#define HG_EAGG(kc, mat) (40960 + ((kc) * 2 + (mat)) * ECH)
#define HG_EH            51200
#define HG_W(buf, mat)   (59648 + (buf) * 20480 + (mat) * 10240)
#define HG_ADJ           100608
#define HG_DEGE          104704
#define HG_DEGN          (104704 + 64)
#define HG_IDX           (104704 + 64 + 256)
#define HGM_SMEM         105472

__device__ __forceinline__ void hg_load_wchunk(uint32_t sb, int buf,
    const __nv_bfloat16* Whi, const __nv_bfloat16* Wlo, int kc, int t) {
    #pragma unroll
    for (int h = 0; h < 2; h++) {
        const int e = h * 256 + t;
        const int row = e >> 2, seg = e & 3;
        cp16(sb + HG_W(buf, 0) + row * 80 + seg * 16,
             Whi + (size_t)row * 128 + kc * 32 + seg * 8);
        cp16(sb + HG_W(buf, 1) + row * 80 + seg * 16,
             Wlo + (size_t)row * 128 + kc * 32 + seg * 8);
    }
}

__global__ void __launch_bounds__(256, 2)
hgnn_mma(const int* __restrict__ nodes, const float* __restrict__ hn_adj,
         const float* __restrict__ embedding) {
    extern __shared__ char smx[];
    const uint32_t sb = smem_u32(smx);
    float* s_adj  = (float*)(smx + HG_ADJ);
    float* s_eh   = (float*)(smx + HG_EH);
    float* s_dege = (float*)(smx + HG_DEGE);
    float* s_degn = (float*)(smx + HG_DEGN);
    int*   s_idx  = (int*)(smx + HG_IDX);

    const int b = blockIdx.x;
    const int t = threadIdx.x;
    const int lane = t & 31, wid = t >> 5;

    {
        const float* adjb = hn_adj + (size_t)b * Nn * En;
        for (int i = t; i < Nn * En; i += 256) s_adj[i] = adjb[i];
        if (t < Nn) s_idx[t] = nodes[b * Nn + t];
    }
    __syncthreads();

    if (t < En) {
        float s = 0.f;
        #pragma unroll 8
        for (int n = 0; n < Nn; n++) s += s_adj[n * En + t];
        s_dege[t] = fmaxf(s, 1.0f);
    }
    if (t >= 32 && t < 32 + Nn) {
        const int n = t - 32;
        float s = 0.f;
        #pragma unroll
        for (int e = 0; e < En; e++) s += s_adj[n * En + e];
        s_degn[n] = fmaxf(s, 1.0f);
    }

    for (int n = wid; n < Nn; n += 8) {
        const float4 v = ((const float4*)(embedding + (size_t)s_idx[n] * Hn))[lane];
        float ss = v.x * v.x + v.y * v.y + v.z * v.z + v.w * v.w;
        #pragma unroll
        for (int o = 16; o > 0; o >>= 1) ss += __shfl_xor_sync(0xffffffffu, ss, o);
        const float inv = 1.0f / fmaxf(sqrtf(ss), EPS);
        const float4 nv = make_float4(v.x * inv, v.y * inv, v.z * inv, v.w * inv);
        const int chunk = lane >> 3;
        const int c = (lane & 7) * 4;
        __nv_bfloat16 h0 = __float2bfloat16_rn(nv.x), h1 = __float2bfloat16_rn(nv.y);
        __nv_bfloat16 h2 = __float2bfloat16_rn(nv.z), h3 = __float2bfloat16_rn(nv.w);
        char* hip = smx + HG_A(chunk, 0) + n * 80 + c * 2;
        char* lop = smx + HG_A(chunk, 1) + n * 80 + c * 2;
        *(__nv_bfloat162*)(hip)     = __halves2bfloat162(h0, h1);
        *(__nv_bfloat162*)(hip + 4) = __halves2bfloat162(h2, h3);
        *(__nv_bfloat162*)(lop) = __halves2bfloat162(
            __float2bfloat16_rn(nv.x - __bfloat162float(h0)),
            __float2bfloat16_rn(nv.y - __bfloat162float(h1)));
        *(__nv_bfloat162*)(lop + 4) = __halves2bfloat162(
            __float2bfloat16_rn(nv.z - __bfloat162float(h2)),
            __float2bfloat16_rn(nv.w - __bfloat162float(h3)));
    }
    __syncthreads();

    const uint32_t aA_lane = (uint32_t)((lane & 15) * 80 + (lane >> 4) * 16);
    const uint32_t aB_lane = (uint32_t)(((lane & 7) + ((lane >> 4) & 1) * 8) * 80
                                        + ((lane >> 3) & 1) * 16);
    const int m2 = wid & 1, n2 = wid >> 1;

    for (int step = 0; step < 2; step++) {
        {
            const int d = t & 127;
            const int ch = d >> 5, co = (d & 31) * 2;
            const char* hip = smx + HG_A(ch, 0) + co;
            const char* lop = smx + HG_A(ch, 1) + co;
            for (int e = t >> 7; e < En; e += 2) {
                float acc = 0.f;
                #pragma unroll 8
                for (int n = 0; n < Nn; n++) {
                    const float val = __bfloat162float(*(const __nv_bfloat16*)(hip + n * 80))
                                    + __bfloat162float(*(const __nv_bfloat16*)(lop + n * 80));
                    acc += s_adj[n * En + e] * val;
                }
                const float v = acc / s_dege[e];
                const __nv_bfloat16 h = __float2bfloat16_rn(v);
                *(__nv_bfloat16*)(smx + HG_EAGG(ch, 0) + e * 80 + co) = h;
                *(__nv_bfloat16*)(smx + HG_EAGG(ch, 1) + e * 80 + co) =
                    __float2bfloat16_rn(v - __bfloat162float(h));
            }
        }
        hg_load_wchunk(sb, 0, g_wet_hi, g_wet_lo, 0, t);
        CP_COMMIT();
        __syncthreads();

        {
            float acc1[2][4];
            #pragma unroll
            for (int j = 0; j < 2; j++)
                #pragma unroll
                for (int r = 0; r < 4; r++) acc1[j][r] = 0.f;

            for (int kc = 0; kc < 4; kc++) {
                const int buf = kc & 1;
                if (kc < 3) {
                    hg_load_wchunk(sb, buf ^ 1, g_wet_hi, g_wet_lo, kc + 1, t);
                    CP_COMMIT();
                    CP_WAIT(1);
                } else {
                    CP_WAIT(0);
                }
                __syncthreads();
                const uint32_t baseA = sb + HG_EAGG(kc, 0) + aA_lane;
                const uint32_t baseB = sb + HG_W(buf, 0) + (uint32_t)(wid * 16) * 80 + aB_lane;
                #pragma unroll
                for (int ks = 0; ks < 2; ks++) {
                    const uint32_t koff = (uint32_t)ks * 32;
                    uint32_t ah[4], al[4], bh4[4], bl4[4];
                    ldsm4(ah, baseA + koff);
                    ldsm4(al, baseA + ECH + koff);
                    ldsm4(bh4, baseB + koff);
                    ldsm4(bl4, baseB + 10240 + koff);
                    #pragma unroll
                    for (int jj = 0; jj < 2; jj++) {
                        const uint32_t* bh = &bh4[jj * 2];
                        const uint32_t* bl = &bl4[jj * 2];
                        mma16816(acc1[jj], ah, bh);
                        mma16816(acc1[jj], ah, bl);
                        mma16816(acc1[jj], al, bh);
                    }
                }
                __syncthreads();
            }
            const int r0 = lane >> 2;
            const int colb = wid * 16 + (lane & 3) * 2;
            #pragma unroll
            for (int jj = 0; jj < 2; jj++) {
                const int col = colb + jj * 8;
                *(float2*)&s_eh[r0 * 132 + col]       = make_float2(acc1[jj][0], acc1[jj][1]);
                *(float2*)&s_eh[(r0 + 8) * 132 + col] = make_float2(acc1[jj][2], acc1[jj][3]);
            }
        }
        __syncthreads();

        hg_load_wchunk(sb, 0, g_wnt_hi, g_wnt_lo, 0, t);
        CP_COMMIT();

        {
            const int d = t & 127;
            const int ch = d >> 5, co = (d & 31) * 2;
            for (int n = t >> 7; n < Nn; n += 2) {
                float acc = 0.f;
                #pragma unroll
                for (int e = 0; e < En; e++) acc += s_adj[n * En + e] * s_eh[e * 132 + d];
                const float v = acc / s_degn[n];
                const __nv_bfloat16 h = __float2bfloat16_rn(v);
                *(__nv_bfloat16*)(smx + HG_A(ch, 0) + n * 80 + co) = h;
                *(__nv_bfloat16*)(smx + HG_A(ch, 1) + n * 80 + co) =
                    __float2bfloat16_rn(v - __bfloat162float(h));
            }
        }
        __syncthreads();

        {
            float acc2[2][4][4];
            #pragma unroll
            for (int i = 0; i < 2; i++)
                #pragma unroll
                for (int j = 0; j < 4; j++)
                    #pragma unroll
                    for (int r = 0; r < 4; r++) acc2[i][j][r] = 0.f;

            for (int kc = 0; kc < 4; kc++) {
                const int buf = kc & 1;
                if (kc < 3) {
                    hg_load_wchunk(sb, buf ^ 1, g_wnt_hi, g_wnt_lo, kc + 1, t);
                    CP_COMMIT();
                    CP_WAIT(1);
                } else {
                    CP_WAIT(0);
                }
                __syncthreads();
                const uint32_t baseA = sb + HG_A(kc, 0) + (uint32_t)(m2 * 32) * 80 + aA_lane;
                const uint32_t baseB = sb + HG_W(buf, 0) + (uint32_t)(n2 * 32) * 80 + aB_lane;
                #pragma unroll
                for (int ks = 0; ks < 2; ks++) {
                    const uint32_t koff = (uint32_t)ks * 32;
                    uint32_t ah[2][4], al[2][4], bh4[2][4], bl4[2][4];
                    #pragma unroll
                    for (int i = 0; i < 2; i++) {
                        ldsm4(ah[i], baseA + (uint32_t)(i * 16) * 80 + koff);
                        ldsm4(al[i], baseA + ACH + (uint32_t)(i * 16) * 80 + koff);
                    }
                    #pragma unroll
                    for (int j4 = 0; j4 < 2; j4++) {
                        ldsm4(bh4[j4], baseB + (uint32_t)(j4 * 16) * 80 + koff);
                        ldsm4(bl4[j4], baseB + 10240 + (uint32_t)(j4 * 16) * 80 + koff);
                    }
                    #pragma unroll
                    for (int i = 0; i < 2; i++)
                        #pragma unroll
                        for (int jj = 0; jj < 4; jj++) {
                            const uint32_t* bh = &bh4[jj >> 1][(jj & 1) * 2];
                            const uint32_t* bl = &bl4[jj >> 1][(jj & 1) * 2];
                            mma16816(acc2[i][jj], ah[i], bh);
                            mma16816(acc2[i][jj], ah[i], bl);
                            mma16816(acc2[i][jj], al[i], bh);
                        }
                }
                __syncthreads();
            }
            #pragma unroll
            for (int i = 0; i < 2; i++)
                #pragma unroll
                for (int jj = 0; jj < 4; jj++) {
                    const int r = m2 * 32 + 16 * i + (lane >> 2);
                    const int c = jj * 8 + (lane & 3) * 2;
                    const float a0 = acc2[i][jj][0], a1 = acc2[i][jj][1];
                    const float a2 = acc2[i][jj][2], a3 = acc2[i][jj][3];
                    __nv_bfloat16 h0 = __float2bfloat16_rn(a0), h1 = __float2bfloat16_rn(a1);
                    __nv_bfloat16 h2 = __float2bfloat16_rn(a2), h3 = __float2bfloat16_rn(a3);
                    char* hip = smx + HG_A(n2, 0);
                    char* lop = smx + HG_A(n2, 1);
                    *(__nv_bfloat162*)(hip + r * 80 + c * 2) = __halves2bfloat162(h0, h1);
                    *(__nv_bfloat162*)(hip + (r + 8) * 80 + c * 2) = __halves2bfloat162(h2, h3);
                    *(__nv_bfloat162*)(lop + r * 80 + c * 2) = __halves2bfloat162(
                        __float2bfloat16_rn(a0 - __bfloat162float(h0)),
                        __float2bfloat16_rn(a1 - __bfloat162float(h1)));
                    *(__nv_bfloat162*)(lop + (r + 8) * 80 + c * 2) = __halves2bfloat162(
                        __float2bfloat16_rn(a2 - __bfloat162float(h2)),
                        __float2bfloat16_rn(a3 - __bfloat162float(h3)));
                }
        }
        __syncthreads();
    }

    for (int f = t; f < Nn * Hn; f += 256) {
        const int n = f >> 7, d = f & 127;
        const int ch = d >> 5, co = (d & 31) * 2;
        const float val =
            __bfloat162float(*(const __nv_bfloat16*)(smx + HG_A(ch, 0) + n * 80 + co))
          + __bfloat162float(*(const __nv_bfloat16*)(smx + HG_A(ch, 1) + n * 80 + co));
        g_nodes_h[(size_t)b * Nn * Hn + f] = val;
    }
}

// =============================================================================
// prep_w (R10 proven)
// =============================================================================
__global__ void __launch_bounds__(256)
prep_w(const float* __restrict__ w_edge, const float* __restrict__ w_node,
       const float* __restrict__ q2_w) {
    const int idx = blockIdx.x * 256 + threadIdx.x;
    if (idx < 16384) {
        const int k = idx >> 7, n = idx & 127;
        sthilo(g_wet_hi, g_wet_lo, (size_t)n * 128 + k, w_edge[idx]);
    } else if (idx < 32768) {
        const int i2 = idx - 16384;
        const int k = i2 >> 7, n = i2 & 127;
        sthilo(g_wnt_hi, g_wnt_lo, (size_t)n * 128 + k, w_node[i2]);
    } else if (idx < 98304) {
        const int i2 = idx - 32768;
        const int k = i2 >> 8, n = i2 & 255;
        sthilo(g_q2t_hi, g_q2t_lo, (size_t)n * 256 + k, q2_w[i2]);
    }
}

// =============================================================================
// seqbuild (R7/R11 proven)
// =============================================================================
__global__ void __launch_bounds__(256)
seqbuild(const int* __restrict__ alias_item, const int* __restrict__ alias_cate) {
    const int rr = blockIdx.x * 8 + (threadIdx.x >> 5);
    const int lane = threadIdx.x & 31;
    if (rr >= Bn * Ln) return;
    const int b = rr / Ln;
    const int ai = alias_item[rr];
    const int ac = alias_cate[rr];
    const float4 vi = ((const float4*)(g_nodes_h + (size_t)(b * Nn + ai) * Hn))[lane];
    const float4 vc = ((const float4*)(g_nodes_h + (size_t)(b * Nn + ac) * Hn))[lane];
    float ss = vi.x*vi.x + vi.y*vi.y + vi.z*vi.z + vi.w*vi.w
             + vc.x*vc.x + vc.y*vc.y + vc.z*vc.z + vc.w*vc.w;
    #pragma unroll
    for (int o = 16; o > 0; o >>= 1) ss += __shfl_xor_sync(0xffffffffu, ss, o);
    const float inv = 1.0f / fmaxf(sqrtf(ss), EPS);
    const float4 ni = make_float4(vi.x*inv, vi.y*inv, vi.z*inv, vi.w*inv);
    const float4 nc = make_float4(vc.x*inv, vc.y*inv, vc.z*inv, vc.w*inv);
    ((float4*)(g_seq_f32 + (size_t)rr * Dn))[lane]      = ni;
    ((float4*)(g_seq_f32 + (size_t)rr * Dn))[lane + 32] = nc;
    store4_hilo(g_seq_hi + (size_t)rr * Dn, g_seq_lo + (size_t)rr * Dn, lane * 4, ni);
    store4_hilo(g_seq_hi + (size_t)rr * Dn, g_seq_lo + (size_t)rr * Dn, 128 + lane * 4, nc);
}

// =============================================================================
// attn_lite (R7 proven; output fp16 single)
// =============================================================================
__global__ void __launch_bounds__(256, 2)
attn_lite(const int* __restrict__ item_seq,
          const float* __restrict__ q1_w, const float* __restrict__ q1_b,
          const float* __restrict__ v_w) {
    __shared__ float s_ht[Dn];
    __shared__ float s_part[Ln * 8];
    __shared__ float s_alpha[Ln + 2];
    __shared__ float s_mask[Ln + 2];
    __shared__ float s_red[8];
    __shared__ float s_bcast;
    __shared__ int   s_last;

    const int b = blockIdx.x;
    const int t = threadIdx.x;
    const int lane = t & 31, wid = t >> 5;

    if (t < Ln) s_mask[t] = (item_seq[b * Ln + t] > 0) ? 1.0f : 0.0f;
    if (t == 0) {
        int cnt = 0;
        for (int l = 0; l < Ln; l++) cnt += (item_seq[b * Ln + l] > 0) ? 1 : 0;
        s_last = max(cnt - 1, 0);
    }
    __syncthreads();
    s_ht[t] = g_seq_f32[((size_t)b * Ln + s_last) * Dn + t];
    __syncthreads();

    float q1v = 0.f;
    #pragma unroll 4
    for (int d = 0; d < Dn; d++) q1v += s_ht[d] * q1_w[d * Dn + t];
    q1v += q1_b[t];

    const float vw = v_w[t];
    for (int l = 0; l < Ln; l++) {
        const float x = q1v + g_q2[((size_t)b * Ln + l) * Dn + t];
        float c = vw / (1.0f + expf(-x));
        #pragma unroll
        for (int o = 16; o > 0; o >>= 1) c += __shfl_xor_sync(0xffffffffu, c, o);
        if (lane == 0) s_part[l * 8 + wid] = c;
    }
    __syncthreads();
    if (t < Ln) {
        float a = 0.f;
        #pragma unroll
        for (int w = 0; w < 8; w++) a += s_part[t * 8 + w];
        s_alpha[t] = a * s_mask[t];
    }
    __syncthreads();

    float outacc = 0.f;
    #pragma unroll 5
    for (int l = 0; l < Ln; l++)
        outacc += s_alpha[l] * g_seq_f32[((size_t)b * Ln + l) * Dn + t];

    float ss = outacc * outacc;
    #pragma unroll
    for (int o = 16; o > 0; o >>= 1) ss += __shfl_xor_sync(0xffffffffu, ss, o);
    if (lane == 0) s_red[wid] = ss;
    __syncthreads();
    if (t == 0) {
        float a = 0.f;
        #pragma unroll
        for (int w = 0; w < 8; w++) a += s_red[w];
        s_bcast = a;
    }
    __syncthreads();
    const float inv = 1.0f / fmaxf(sqrtf(s_bcast), EPS);
    g_so_f16[(size_t)b * Dn + t] = __float2half_rn(outacc * inv);
}

// =============================================================================
// itemnorm: fp16 single output (R13 proven)
// =============================================================================
__global__ void __launch_bounds__(256)
itemnorm_kernel(const float* __restrict__ embedding, const int* __restrict__ item_cates) {
    const int i = blockIdx.x * 8 + (threadIdx.x >> 5);
    const int lane = threadIdx.x & 31;
    if (i >= ITEMN) return;
    const int c = item_cates[i];
    const float4 vi = ((const float4*)(embedding + (size_t)i * Hn))[lane];
    const float4 vc = ((const float4*)(embedding + (size_t)c * Hn))[lane];
    float ss = vi.x*vi.x + vi.y*vi.y + vi.z*vi.z + vi.w*vi.w
             + vc.x*vc.x + vc.y*vc.y + vc.z*vc.z + vc.w*vc.w;
    #pragma unroll
    for (int o = 16; o > 0; o >>= 1) ss += __shfl_xor_sync(0xffffffffu, ss, o);
    const float inv = 1.0f / fmaxf(sqrtf(ss), EPS);
    __half* dst = g_item_f16 + (size_t)i * Dn;
    *(__half2*)(dst + lane * 4)     = __floats2half2_rn(vi.x * inv, vi.y * inv);
    *(__half2*)(dst + lane * 4 + 2) = __floats2half2_rn(vi.z * inv, vi.w * inv);
    *(__half2*)(dst + 128 + lane * 4)     = __floats2half2_rn(vc.x * inv, vc.y * inv);
    *(__half2*)(dst + 128 + lane * 4 + 2) = __floats2half2_rn(vc.z * inv, vc.w * inv);
}

// =============================================================================
// scores: pure fp16 x fp16. D = A·B. 2 smem mats per buffer, 16 MMAs/warp-chunk.
// Tiling/addressing identical to the proven kernel.
// =============================================================================
#define SBUF (2 * MATB)        // A, B
#define SCF_SMEM (2 * SBUF)    // 40960

__global__ void __launch_bounds__(256, 2)
scores_f16(float* __restrict__ C) {
    extern __shared__ char smc[];
    const uint32_t sb = smem_u32(smc);

    const int t = threadIdx.x;
    const int w = t >> 5, lane = t & 31;
    const int b0 = blockIdx.x * 128;
    const int i0 = blockIdx.y * 128;
    const int warp_m = w & 3;
    const int warp_n = w >> 2;

    const __half* srcA = g_item_f16 + (size_t)i0 * Dn;
    const __half* srcB = g_so_f16 + (size_t)b0 * Dn;
    const int ld_row0 = t >> 2, ld_row1 = 64 + (t >> 2), ld_seg = t & 3;

    float acc[2][8][4];
    #pragma unroll
    for (int i = 0; i < 2; i++)
        #pragma unroll
        for (int j = 0; j < 8; j++)
            #pragma unroll
            for (int r = 0; r < 4; r++) acc[i][j][r] = 0.f;

    const uint32_t aA_lane = (uint32_t)((lane & 15) * ROWB + (lane >> 4) * 16);
    const uint32_t aB_lane = (uint32_t)(((lane & 7) + ((lane >> 4) & 1) * 8) * ROWB
                                        + ((lane >> 3) & 1) * 16);

    cp16(sb + 0 * SBUF + 0 * MATB + ld_row0 * ROWB + ld_seg * 16, srcA + (size_t)ld_row0 * Dn + ld_seg * 8);
    cp16(sb + 0 * SBUF + 0 * MATB + ld_row1 * ROWB + ld_seg * 16, srcA + (size_t)ld_row1 * Dn + ld_seg * 8);
    cp16(sb + 0 * SBUF + 1 * MATB + ld_row0 * ROWB + ld_seg * 16, srcB + (size_t)ld_row0 * Dn + ld_seg * 8);
    cp16(sb + 0 * SBUF + 1 * MATB + ld_row1 * ROWB + ld_seg * 16, srcB + (size_t)ld_row1 * Dn + ld_seg * 8);
    CP_COMMIT();

    for (int kc = 0; kc < 8; kc++) {
        const int buf = kc & 1;
        if (kc < 7) {
            const int k0 = (kc + 1) * 32;
            const uint32_t nb = sb + (uint32_t)((buf ^ 1)) * SBUF;
            cp16(nb + 0 * MATB + ld_row0 * ROWB + ld_seg * 16, srcA + (size_t)ld_row0 * Dn + k0 + ld_seg * 8);
            cp16(nb + 0 * MATB + ld_row1 * ROWB + ld_seg * 16, srcA + (size_t)ld_row1 * Dn + k0 + ld_seg * 8);
            cp16(nb + 1 * MATB + ld_row0 * ROWB + ld_seg * 16, srcB + (size_t)ld_row0 * Dn + k0 + ld_seg * 8);
            cp16(nb + 1 * MATB + ld_row1 * ROWB + ld_seg * 16, srcB + (size_t)ld_row1 * Dn + k0 + ld_seg * 8);
            CP_COMMIT();
            CP_WAIT(1);
        } else {
            CP_WAIT(0);
        }
        __syncthreads();

        const uint32_t baseA = sb + buf * SBUF + (uint32_t)(warp_m * 32) * ROWB + aA_lane;
        const uint32_t baseB = sb + buf * SBUF + MATB + (uint32_t)(warp_n * 64) * ROWB + aB_lane;

        #pragma unroll
        for (int ks = 0; ks < 2; ks++) {
            const uint32_t koff = (uint32_t)ks * 32;
            uint32_t af[2][4];
            #pragma unroll
            for (int i = 0; i < 2; i++)
                ldsm4(af[i], baseA + (uint32_t)(i * 16) * ROWB + koff);
            #pragma unroll
            for (int jg = 0; jg < 2; jg++) {
                uint32_t bf[2][4];
                #pragma unroll
                for (int j4 = 0; j4 < 2; j4++) {
                    const uint32_t off = (uint32_t)((jg * 2 + j4) * 16) * ROWB + koff;
                    ldsm4(bf[j4], baseB + off);
                }
                #pragma unroll
                for (int i = 0; i < 2; i++)
                    #pragma unroll
                    for (int jj = 0; jj < 4; jj++) {
                        const int j = jg * 4 + jj;
                        const uint32_t* bb = &bf[jj >> 1][(jj & 1) * 2];
                        mma16816h(acc[i][j], af[i], bb);
                    }
            }
        }
        __syncthreads();
    }

    const int mrow = i0 + warp_m * 32 + (lane >> 2);
    const int ncol = b0 + warp_n * 64 + (lane & 3) * 2;
    #pragma unroll
    for (int i = 0; i < 2; i++) {
        #pragma unroll
        for (int j = 0; j < 8; j++) {
            const int n = ncol + j * 8;
            const int m = mrow + i * 16;
            if (m < ITEMN) {
                C[(size_t)n       * ITEMN + m]     = 16.f * acc[i][j][0];
                C[(size_t)(n + 1) * ITEMN + m]     = 16.f * acc[i][j][1];
            }
            if (m + 8 < ITEMN) {
                C[(size_t)n       * ITEMN + m + 8] = 16.f * acc[i][j][2];
                C[(size_t)(n + 1) * ITEMN + m + 8] = 16.f * acc[i][j][3];
            }
        }
    }
}

// =============================================================================
// launch — no device symbols passed as kernel args.
// =============================================================================
extern "C" void kernel_launch(void* const* d_in, const int* in_sizes, int n_in,
                              void* d_out, int out_size) {
    const int*   item_seq   = (const int*)  d_in[0];
    /* label d_in[1] unused */
    const int*   nodes      = (const int*)  d_in[2];
    const float* hn_adj     = (const float*)d_in[3];
    const int*   alias_item = (const int*)  d_in[4];
    const int*   alias_cate = (const int*)  d_in[5];
    const float* embedding  = (const float*)d_in[6];
    const int*   item_cates = (const int*)  d_in[7];
    const float* w_edge     = (const float*)d_in[8];
    const float* w_node     = (const float*)d_in[9];
    const float* q1_w       = (const float*)d_in[10];
    const float* q1_b       = (const float*)d_in[11];
    const float* q2_w       = (const float*)d_in[12];
    const float* v_w        = (const float*)d_in[13];
    float* out = (float*)d_out;

    cudaFuncSetAttribute(hgnn_mma,   cudaFuncAttributeMaxDynamicSharedMemorySize, HGM_SMEM);
    cudaFuncSetAttribute(gemm3_q2,   cudaFuncAttributeMaxDynamicSharedMemorySize, SC_SMEM);
    cudaFuncSetAttribute(scores_f16, cudaFuncAttributeMaxDynamicSharedMemorySize, SCF_SMEM);

    prep_w<<<384, 256>>>(w_edge, w_node, q2_w);
    itemnorm_kernel<<<(ITEMN + 7) / 8, 256>>>(embedding, item_cates);
    hgnn_mma<<<Bn, 256, HGM_SMEM>>>(nodes, hn_adj, embedding);

    seqbuild<<<Bn * Ln / 8, 256>>>(alias_item, alias_cate);
    gemm3_q2<<<dim3(Bn * Ln / 128, 2), 256, SC_SMEM>>>();
    attn_lite<<<Bn, 256>>>(item_seq, q1_w, q1_b, v_w);

    scores_f16<<<dim3(4, ITEMP / 128), 256, SCF_SMEM>>>(out);
}

// round 15
// speedup vs baseline: 2.2760x; 1.1375x over previous
#include <cuda_runtime.h>
#include <cuda_bf16.h>
#include <cuda_fp16.h>
#include <math.h>
#include <stdint.h>

#define Bn 512
#define Ln 50
#define Nn 64
#define En 16
#define Hn 128
#define Dn 256
#define ITEMN 100000
#define ITEMP 100096
#define EPS 1e-12f

// ------------------------- scratch (no allocs allowed) -------------------------
// Device globals are ONLY referenced inside device code (never host kernel args).
__device__ float g_nodes_h[Bn * Nn * Hn];
__device__ float g_seq_f32[25600 * 256];
__device__ __half g_seq_f16[25600 * 256];
__device__ float g_q2[25600 * 256];
__device__ __half g_wet_hi[128 * 128], g_wet_lo[128 * 128];   // w_edge^T fp16 hi/lo
__device__ __half g_wnt_hi[128 * 128], g_wnt_lo[128 * 128];   // w_node^T fp16 hi/lo
__device__ __half g_q2t_f16[256 * 256];                       // q2_w^T fp16 single
__device__ __half g_so_f16[Bn * Dn];                          // fp16 single
__device__ __half g_item_f16[(size_t)ITEMP * Dn];             // fp16 single

// ============================= PTX helpers =============================
__device__ __forceinline__ uint32_t smem_u32(const void* p) {
    uint32_t a;
    asm("{ .reg .u64 t; cvta.to.shared.u64 t, %1; cvt.u32.u64 %0, t; }" : "=r"(a) : "l"(p));
    return a;
}
__device__ __forceinline__ void cp16(uint32_t dst, const void* src) {
    asm volatile("cp.async.cg.shared.global [%0], [%1], 16;" :: "r"(dst), "l"(src));
}
#define CP_COMMIT() asm volatile("cp.async.commit_group;" ::: "memory")
#define CP_WAIT(n)  asm volatile("cp.async.wait_group %0;" :: "n"(n) : "memory")

__device__ __forceinline__ void ldsm4(uint32_t* r, uint32_t addr) {
    asm volatile("ldmatrix.sync.aligned.m8n8.x4.shared.b16 {%0,%1,%2,%3}, [%4];"
                 : "=r"(r[0]), "=r"(r[1]), "=r"(r[2]), "=r"(r[3]) : "r"(addr));
}
__device__ __forceinline__ void mma16816h(float* d, const uint32_t* a, const uint32_t* b) {
    asm volatile(
        "mma.sync.aligned.m16n8k16.row.col.f32.f16.f16.f32 "
        "{%0,%1,%2,%3}, {%4,%5,%6,%7}, {%8,%9}, {%0,%1,%2,%3};"
        : "+f"(d[0]), "+f"(d[1]), "+f"(d[2]), "+f"(d[3])
        : "r"(a[0]), "r"(a[1]), "r"(a[2]), "r"(a[3]), "r"(b[0]), "r"(b[1]));
}
__device__ __forceinline__ void sthilo_h(__half* hi, __half* lo, size_t idx, float v) {
    __half h = __float2half_rn(v);
    hi[idx] = h;
    lo[idx] = __float2half_rn(v - __half2float(h));
}

// =============================================================================
// hgnn_mma: fused per-batch GNN, fp16 2-term HMMA GEMMs.
// Smem map (bytes):
//  A (activations) [4 kc][64 rows x 80B fp16] : 0     .. 20480
//  EAGG            [4 kc][16 rows x 80B fp16] : 20480 .. 25600
//  EH fp32 [16 x 132]                         : 25600 .. 34048
//  W dbl-buf [2][hi/lo][128 x 80B fp16]       : 34048 .. 75008
//  ADJ fp32 [64 x 16]                         : 75008 .. 79104
//  deg_e, deg_n, idx                          : 79104 .. 79680
// =============================================================================
#define ACH 5120
#define ECH 1280
#define HG_A(kc)       ((kc) * ACH)
#define HG_EAGG(kc)    (20480 + (kc) * ECH)
#define HG_EH          25600
#define HG_W(buf, mat) (34048 + (buf) * 20480 + (mat) * 10240)
#define HG_ADJ         75008
#define HG_DEGE        79104
#define HG_DEGN        79168
#define HG_IDX         79424
#define HGM_SMEM       79872

__device__ __forceinline__ void hg_load_wchunk(uint32_t sb, int buf,
    const __half* Whi, const __half* Wlo, int kc, int t) {
    #pragma unroll
    for (int h = 0; h < 2; h++) {
        const int e = h * 256 + t;      // 0..511 = 128 rows x 4 segs
        const int row = e >> 2, seg = e & 3;
        cp16(sb + HG_W(buf, 0) + row * 80 + seg * 16,
             Whi + (size_t)row * 128 + kc * 32 + seg * 8);
        cp16(sb + HG_W(buf, 1) + row * 80 + seg * 16,
             Wlo + (size_t)row * 128 + kc * 32 + seg * 8);
    }
}

__global__ void __launch_bounds__(256, 2)
hgnn_mma(const int* __restrict__ nodes, const float* __restrict__ hn_adj,
         const float* __restrict__ embedding) {
    extern __shared__ char smx[];
    const uint32_t sb = smem_u32(smx);
    float* s_adj  = (float*)(smx + HG_ADJ);
    float* s_eh   = (float*)(smx + HG_EH);
    float* s_dege = (float*)(smx + HG_DEGE);
    float* s_degn = (float*)(smx + HG_DEGN);
    int*   s_idx  = (int*)(smx + HG_IDX);

    const int b = blockIdx.x;
    const int t = threadIdx.x;
    const int lane = t & 31, wid = t >> 5;

    {
        const float* adjb = hn_adj + (size_t)b * Nn * En;
        for (int i = t; i < Nn * En; i += 256) s_adj[i] = adjb[i];
        if (t < Nn) s_idx[t] = nodes[b * Nn + t];
    }
    __syncthreads();

    if (t < En) {
        float s = 0.f;
        #pragma unroll 8
        for (int n = 0; n < Nn; n++) s += s_adj[n * En + t];
        s_dege[t] = fmaxf(s, 1.0f);
    }
    if (t >= 32 && t < 32 + Nn) {
        const int n = t - 32;
        float s = 0.f;
        #pragma unroll
        for (int e = 0; e < En; e++) s += s_adj[n * En + e];
        s_degn[n] = fmaxf(s, 1.0f);
    }

    // init: n_h = l2norm(embedding[nodes]) -> A region fp16
    for (int n = wid; n < Nn; n += 8) {
        const float4 v = ((const float4*)(embedding + (size_t)s_idx[n] * Hn))[lane];
        float ss = v.x * v.x + v.y * v.y + v.z * v.z + v.w * v.w;
        #pragma unroll
        for (int o = 16; o > 0; o >>= 1) ss += __shfl_xor_sync(0xffffffffu, ss, o);
        const float inv = 1.0f / fmaxf(sqrtf(ss), EPS);
        const int chunk = lane >> 3;
        const int c = (lane & 7) * 4;
        char* dst = smx + HG_A(chunk) + n * 80 + c * 2;
        *(__half2*)(dst)     = __floats2half2_rn(v.x * inv, v.y * inv);
        *(__half2*)(dst + 4) = __floats2half2_rn(v.z * inv, v.w * inv);
    }
    __syncthreads();

    const uint32_t aA_lane = (uint32_t)((lane & 15) * 80 + (lane >> 4) * 16);
    const uint32_t aB_lane = (uint32_t)(((lane & 7) + ((lane >> 4) & 1) * 8) * 80
                                        + ((lane >> 3) & 1) * 16);
    const int m2 = wid & 1, n2 = wid >> 1;   // GEMM2 warp tiling

    for (int step = 0; step < 2; step++) {
        // ---- agg_e: reads A fp16, writes EAGG fp16
        {
            const int d = t & 127;
            const int ch = d >> 5, co = (d & 31) * 2;
            const char* ap = smx + HG_A(ch) + co;
            for (int e = t >> 7; e < En; e += 2) {
                float acc = 0.f;
                #pragma unroll 8
                for (int n = 0; n < Nn; n++)
                    acc += s_adj[n * En + e] * __half2float(*(const __half*)(ap + n * 80));
                *(__half*)(smx + HG_EAGG(ch) + e * 80 + co) =
                    __float2half_rn(acc / s_dege[e]);
            }
        }
        hg_load_wchunk(sb, 0, g_wet_hi, g_wet_lo, 0, t);
        CP_COMMIT();
        __syncthreads();

        // ---- GEMM1: e_h[16,128] = eagg . w_edge^T (2-term fp16 HMMA)
        {
            float acc1[2][4];
            #pragma unroll
            for (int j = 0; j < 2; j++)
                #pragma unroll
                for (int r = 0; r < 4; r++) acc1[j][r] = 0.f;

            for (int kc = 0; kc < 4; kc++) {
                const int buf = kc & 1;
                if (kc < 3) {
                    hg_load_wchunk(sb, buf ^ 1, g_wet_hi, g_wet_lo, kc + 1, t);
                    CP_COMMIT();
                    CP_WAIT(1);
                } else {
                    CP_WAIT(0);
                }
                __syncthreads();
                const uint32_t baseA = sb + HG_EAGG(kc) + aA_lane;
                const uint32_t baseB = sb + HG_W(buf, 0) + (uint32_t)(wid * 16) * 80 + aB_lane;
                #pragma unroll
                for (int ks = 0; ks < 2; ks++) {
                    const uint32_t koff = (uint32_t)ks * 32;
                    uint32_t ah[4], bh4[4], bl4[4];
                    ldsm4(ah, baseA + koff);
                    ldsm4(bh4, baseB + koff);
                    ldsm4(bl4, baseB + 10240 + koff);
                    #pragma unroll
                    for (int jj = 0; jj < 2; jj++) {
                        mma16816h(acc1[jj], ah, &bh4[jj * 2]);
                        mma16816h(acc1[jj], ah, &bl4[jj * 2]);
                    }
                }
                __syncthreads();
            }
            const int r0 = lane >> 2;
            const int colb = wid * 16 + (lane & 3) * 2;
            #pragma unroll
            for (int jj = 0; jj < 2; jj++) {
                const int col = colb + jj * 8;
                *(float2*)&s_eh[r0 * 132 + col]       = make_float2(acc1[jj][0], acc1[jj][1]);
                *(float2*)&s_eh[(r0 + 8) * 132 + col] = make_float2(acc1[jj][2], acc1[jj][3]);
            }
        }
        __syncthreads();

        // prefetch GEMM2 weight chunk 0 (overlaps agg_n)
        hg_load_wchunk(sb, 0, g_wnt_hi, g_wnt_lo, 0, t);
        CP_COMMIT();

        // ---- agg_n: reads s_eh fp32, writes A region fp16 (overwrites n_h)
        {
            const int d = t & 127;
            const int ch = d >> 5, co = (d & 31) * 2;
            for (int n = t >> 7; n < Nn; n += 2) {
                float acc = 0.f;
                #pragma unroll
                for (int e = 0; e < En; e++) acc += s_adj[n * En + e] * s_eh[e * 132 + d];
                *(__half*)(smx + HG_A(ch) + n * 80 + co) =
                    __float2half_rn(acc / s_degn[n]);
            }
        }
        __syncthreads();

        // ---- GEMM2: n_h[64,128] = nagg . w_node^T (2-term fp16), in-place epilogue
        {
            float acc2[2][4][4];
            #pragma unroll
            for (int i = 0; i < 2; i++)
                #pragma unroll
                for (int j = 0; j < 4; j++)
                    #pragma unroll
                    for (int r = 0; r < 4; r++) acc2[i][j][r] = 0.f;

            for (int kc = 0; kc < 4; kc++) {
                const int buf = kc & 1;
                if (kc < 3) {
                    hg_load_wchunk(sb, buf ^ 1, g_wnt_hi, g_wnt_lo, kc + 1, t);
                    CP_COMMIT();
                    CP_WAIT(1);
                } else {
                    CP_WAIT(0);
                }
                __syncthreads();
                const uint32_t baseA = sb + HG_A(kc) + (uint32_t)(m2 * 32) * 80 + aA_lane;
                const uint32_t baseB = sb + HG_W(buf, 0) + (uint32_t)(n2 * 32) * 80 + aB_lane;
                #pragma unroll
                for (int ks = 0; ks < 2; ks++) {
                    const uint32_t koff = (uint32_t)ks * 32;
                    uint32_t ah[2][4], bh4[2][4], bl4[2][4];
                    #pragma unroll
                    for (int i = 0; i < 2; i++)
                        ldsm4(ah[i], baseA + (uint32_t)(i * 16) * 80 + koff);
                    #pragma unroll
                    for (int j4 = 0; j4 < 2; j4++) {
                        ldsm4(bh4[j4], baseB + (uint32_t)(j4 * 16) * 80 + koff);
                        ldsm4(bl4[j4], baseB + 10240 + (uint32_t)(j4 * 16) * 80 + koff);
                    }
                    #pragma unroll
                    for (int i = 0; i < 2; i++)
                        #pragma unroll
                        for (int jj = 0; jj < 4; jj++) {
                            const uint32_t* bh = &bh4[jj >> 1][(jj & 1) * 2];
                            const uint32_t* bl = &bl4[jj >> 1][(jj & 1) * 2];
                            mma16816h(acc2[i][jj], ah[i], bh);
                            mma16816h(acc2[i][jj], ah[i], bl);
                        }
                }
                __syncthreads();
            }
            // epilogue: write n_h fp16 back into A region (chunk = n2)
            #pragma unroll
            for (int i = 0; i < 2; i++)
                #pragma unroll
                for (int jj = 0; jj < 4; jj++) {
                    const int r = m2 * 32 + 16 * i + (lane >> 2);
                    const int c = jj * 8 + (lane & 3) * 2;   // col within chunk n2
                    char* base = smx + HG_A(n2);
                    *(__half2*)(base + r * 80 + c * 2) =
                        __floats2half2_rn(acc2[i][jj][0], acc2[i][jj][1]);
                    *(__half2*)(base + (r + 8) * 80 + c * 2) =
                        __floats2half2_rn(acc2[i][jj][2], acc2[i][jj][3]);
                }
        }
        __syncthreads();
    }

    // final: g_nodes_h fp32 from fp16
    for (int f = t; f < Nn * Hn; f += 256) {
        const int n = f >> 7, d = f & 127;
        const int ch = d >> 5, co = (d & 31) * 2;
        g_nodes_h[(size_t)b * Nn * Hn + f] =
            __half2float(*(const __half*)(smx + HG_A(ch) + n * 80 + co));
    }
}

// =============================================================================
// prep_w: transpose + split weights: wet/wnt fp16 hi/lo, q2t fp16 single
// =============================================================================
__global__ void __launch_bounds__(256)
prep_w(const float* __restrict__ w_edge, const float* __restrict__ w_node,
       const float* __restrict__ q2_w) {
    const int idx = blockIdx.x * 256 + threadIdx.x;
    if (idx < 16384) {
        const int k = idx >> 7, n = idx & 127;
        sthilo_h(g_wet_hi, g_wet_lo, (size_t)n * 128 + k, w_edge[idx]);
    } else if (idx < 32768) {
        const int i2 = idx - 16384;
        const int k = i2 >> 7, n = i2 & 127;
        sthilo_h(g_wnt_hi, g_wnt_lo, (size_t)n * 128 + k, w_node[i2]);
    } else if (idx < 98304) {
        const int i2 = idx - 32768;
        const int k = i2 >> 8, n = i2 & 255;
        g_q2t_f16[(size_t)n * 256 + k] = __float2half_rn(q2_w[i2]);
    }
}

// =============================================================================
// seqbuild: l2norm(concat) -> fp32 + fp16 single
// =============================================================================
__global__ void __launch_bounds__(256)
seqbuild(const int* __restrict__ alias_item, const int* __restrict__ alias_cate) {
    const int rr = blockIdx.x * 8 + (threadIdx.x >> 5);
    const int lane = threadIdx.x & 31;
    if (rr >= Bn * Ln) return;
    const int b = rr / Ln;
    const int ai = alias_item[rr];
    const int ac = alias_cate[rr];
    const float4 vi = ((const float4*)(g_nodes_h + (size_t)(b * Nn + ai) * Hn))[lane];
    const float4 vc = ((const float4*)(g_nodes_h + (size_t)(b * Nn + ac) * Hn))[lane];
    float ss = vi.x*vi.x + vi.y*vi.y + vi.z*vi.z + vi.w*vi.w
             + vc.x*vc.x + vc.y*vc.y + vc.z*vc.z + vc.w*vc.w;
    #pragma unroll
    for (int o = 16; o > 0; o >>= 1) ss += __shfl_xor_sync(0xffffffffu, ss, o);
    const float inv = 1.0f / fmaxf(sqrtf(ss), EPS);
    const float4 ni = make_float4(vi.x*inv, vi.y*inv, vi.z*inv, vi.w*inv);
    const float4 nc = make_float4(vc.x*inv, vc.y*inv, vc.z*inv, vc.w*inv);
    ((float4*)(g_seq_f32 + (size_t)rr * Dn))[lane]      = ni;
    ((float4*)(g_seq_f32 + (size_t)rr * Dn))[lane + 32] = nc;
    __half* h = g_seq_f16 + (size_t)rr * Dn;
    *(__half2*)(h + lane * 4)     = __floats2half2_rn(ni.x, ni.y);
    *(__half2*)(h + lane * 4 + 2) = __floats2half2_rn(ni.z, ni.w);
    *(__half2*)(h + 128 + lane * 4)     = __floats2half2_rn(nc.x, nc.y);
    *(__half2*)(h + 128 + lane * 4 + 2) = __floats2half2_rn(nc.z, nc.w);
}

// =============================================================================
// gemm_q2_f16: g_q2[25600,256] = seq_f16 . q2t_f16^T  (1-term fp16 HMMA)
// =============================================================================
#define ROWB 80
#define MATB (128 * ROWB)
#define QBUF (2 * MATB)
#define Q2_SMEM (2 * QBUF)

__global__ void __launch_bounds__(256, 2)
gemm_q2_f16() {
    extern __shared__ char smc[];
    const uint32_t sb = smem_u32(smc);
    const int t = threadIdx.x;
    const int w = t >> 5, lane = t & 31;
    const int m0 = blockIdx.x * 128;
    const int n0 = blockIdx.y * 128;
    const int warp_m = w & 3;
    const int warp_n = w >> 2;

    const __half* srcA = g_seq_f16 + (size_t)m0 * 256;
    const __half* srcB = g_q2t_f16 + (size_t)n0 * 256;
    const int ld_row0 = t >> 2, ld_row1 = 64 + (t >> 2), ld_seg = t & 3;

    float acc[2][8][4];
    #pragma unroll
    for (int i = 0; i < 2; i++)
        #pragma unroll
        for (int j = 0; j < 8; j++)
            #pragma unroll
            for (int r = 0; r < 4; r++) acc[i][j][r] = 0.f;

    const uint32_t aA_lane = (uint32_t)((lane & 15) * ROWB + (lane >> 4) * 16);
    const uint32_t aB_lane = (uint32_t)(((lane & 7) + ((lane >> 4) & 1) * 8) * ROWB
                                        + ((lane >> 3) & 1) * 16);

    cp16(sb + 0 * QBUF + 0 * MATB + ld_row0 * ROWB + ld_seg * 16, srcA + (size_t)ld_row0 * 256 + ld_seg * 8);
    cp16(sb + 0 * QBUF + 0 * MATB + ld_row1 * ROWB + ld_seg * 16, srcA + (size_t)ld_row1 * 256 + ld_seg * 8);
    cp16(sb + 0 * QBUF + 1 * MATB + ld_row0 * ROWB + ld_seg * 16, srcB + (size_t)ld_row0 * 256 + ld_seg * 8);
    cp16(sb + 0 * QBUF + 1 * MATB + ld_row1 * ROWB + ld_seg * 16, srcB + (size_t)ld_row1 * 256 + ld_seg * 8);
    CP_COMMIT();

    for (int kc = 0; kc < 8; kc++) {
        const int buf = kc & 1;
        if (kc < 7) {
            const int k0 = (kc + 1) * 32;
            const uint32_t nb = sb + (uint32_t)(buf ^ 1) * QBUF;
            cp16(nb + 0 * MATB + ld_row0 * ROWB + ld_seg * 16, srcA + (size_t)ld_row0 * 256 + k0 + ld_seg * 8);
            cp16(nb + 0 * MATB + ld_row1 * ROWB + ld_seg * 16, srcA + (size_t)ld_row1 * 256 + k0 + ld_seg * 8);
            cp16(nb + 1 * MATB + ld_row0 * ROWB + ld_seg * 16, srcB + (size_t)ld_row0 * 256 + k0 + ld_seg * 8);
            cp16(nb + 1 * MATB + ld_row1 * ROWB + ld_seg * 16, srcB + (size_t)ld_row1 * 256 + k0 + ld_seg * 8);
            CP_COMMIT();
            CP_WAIT(1);
        } else {
            CP_WAIT(0);
        }
        __syncthreads();

        const uint32_t baseA = sb + buf * QBUF + (uint32_t)(warp_m * 32) * ROWB + aA_lane;
        const uint32_t baseB = sb + buf * QBUF + MATB + (uint32_t)(warp_n * 64) * ROWB + aB_lane;

        #pragma unroll
        for (int ks = 0; ks < 2; ks++) {
            const uint32_t koff = (uint32_t)ks * 32;
            uint32_t af[2][4];
            #pragma unroll
            for (int i = 0; i < 2; i++)
                ldsm4(af[i], baseA + (uint32_t)(i * 16) * ROWB + koff);
            #pragma unroll
            for (int jg = 0; jg < 2; jg++) {
                uint32_t bf[2][4];
                #pragma unroll
                for (int j4 = 0; j4 < 2; j4++) {
                    const uint32_t off = (uint32_t)((jg * 2 + j4) * 16) * ROWB + koff;
                    ldsm4(bf[j4], baseB + off);
                }
                #pragma unroll
                for (int i = 0; i < 2; i++)
                    #pragma unroll
                    for (int jj = 0; jj < 4; jj++) {
                        const int j = jg * 4 + jj;
                        mma16816h(acc[i][j], af[i], &bf[jj >> 1][(jj & 1) * 2]);
                    }
            }
        }
        __syncthreads();
    }

    // row-major epilogue into g_q2
    const int mrow = m0 + warp_m * 32 + (lane >> 2);
    const int ncol = n0 + warp_n * 64 + (lane & 3) * 2;
    #pragma unroll
    for (int i = 0; i < 2; i++) {
        #pragma unroll
        for (int j = 0; j < 8; j++) {
            const int m = mrow + i * 16;
            const int n = ncol + j * 8;
            *(float2*)(g_q2 + (size_t)m * 256 + n)       = make_float2(acc[i][j][0], acc[i][j][1]);
            *(float2*)(g_q2 + (size_t)(m + 8) * 256 + n) = make_float2(acc[i][j][2], acc[i][j][3]);
        }
    }
}

// =============================================================================
// attn_lite (R7 proven; output fp16 single)
// =============================================================================
__global__ void __launch_bounds__(256, 2)
attn_lite(const int* __restrict__ item_seq,
          const float* __restrict__ q1_w, const float* __restrict__ q1_b,
          const float* __restrict__ v_w) {
    __shared__ float s_ht[Dn];
    __shared__ float s_part[Ln * 8];
    __shared__ float s_alpha[Ln + 2];
    __shared__ float s_mask[Ln + 2];
    __shared__ float s_red[8];
    __shared__ float s_bcast;
    __shared__ int   s_last;

    const int b = blockIdx.x;
    const int t = threadIdx.x;
    const int lane = t & 31, wid = t >> 5;

    if (t < Ln) s_mask[t] = (item_seq[b * Ln + t] > 0) ? 1.0f : 0.0f;
    if (t == 0) {
        int cnt = 0;
        for (int l = 0; l < Ln; l++) cnt += (item_seq[b * Ln + l] > 0) ? 1 : 0;
        s_last = max(cnt - 1, 0);
    }
    __syncthreads();
    s_ht[t] = g_seq_f32[((size_t)b * Ln + s_last) * Dn + t];
    __syncthreads();

    float q1v = 0.f;
    #pragma unroll 4
    for (int d = 0; d < Dn; d++) q1v += s_ht[d] * q1_w[d * Dn + t];
    q1v += q1_b[t];

    const float vw = v_w[t];
    for (int l = 0; l < Ln; l++) {
        const float x = q1v + g_q2[((size_t)b * Ln + l) * Dn + t];
        float c = vw / (1.0f + expf(-x));
        #pragma unroll
        for (int o = 16; o > 0; o >>= 1) c += __shfl_xor_sync(0xffffffffu, c, o);
        if (lane == 0) s_part[l * 8 + wid] = c;
    }
    __syncthreads();
    if (t < Ln) {
        float a = 0.f;
        #pragma unroll
        for (int w = 0; w < 8; w++) a += s_part[t * 8 + w];
        s_alpha[t] = a * s_mask[t];
    }
    __syncthreads();

    float outacc = 0.f;
    #pragma unroll 5
    for (int l = 0; l < Ln; l++)
        outacc += s_alpha[l] * g_seq_f32[((size_t)b * Ln + l) * Dn + t];

    float ss = outacc * outacc;
    #pragma unroll
    for (int o = 16; o > 0; o >>= 1) ss += __shfl_xor_sync(0xffffffffu, ss, o);
    if (lane == 0) s_red[wid] = ss;
    __syncthreads();
    if (t == 0) {
        float a = 0.f;
        #pragma unroll
        for (int w = 0; w < 8; w++) a += s_red[w];
        s_bcast = a;
    }
    __syncthreads();
    const float inv = 1.0f / fmaxf(sqrtf(s_bcast), EPS);
    g_so_f16[(size_t)b * Dn + t] = __float2half_rn(outacc * inv);
}

// =============================================================================
// itemnorm: fp16 single output (R13 proven)
// =============================================================================
__global__ void __launch_bounds__(256)
itemnorm_kernel(const float* __restrict__ embedding, const int* __restrict__ item_cates) {
    const int i = blockIdx.x * 8 + (threadIdx.x >> 5);
    const int lane = threadIdx.x & 31;
    if (i >= ITEMN) return;
    const int c = item_cates[i];
    const float4 vi = ((const float4*)(embedding + (size_t)i * Hn))[lane];
    const float4 vc = ((const float4*)(embedding + (size_t)c * Hn))[lane];
    float ss = vi.x*vi.x + vi.y*vi.y + vi.z*vi.z + vi.w*vi.w
             + vc.x*vc.x + vc.y*vc.y + vc.z*vc.z + vc.w*vc.w;
    #pragma unroll
    for (int o = 16; o > 0; o >>= 1) ss += __shfl_xor_sync(0xffffffffu, ss, o);
    const float inv = 1.0f / fmaxf(sqrtf(ss), EPS);
    __half* dst = g_item_f16 + (size_t)i * Dn;
    *(__half2*)(dst + lane * 4)     = __floats2half2_rn(vi.x * inv, vi.y * inv);
    *(__half2*)(dst + lane * 4 + 2) = __floats2half2_rn(vi.z * inv, vi.w * inv);
    *(__half2*)(dst + 128 + lane * 4)     = __floats2half2_rn(vc.x * inv, vc.y * inv);
    *(__half2*)(dst + 128 + lane * 4 + 2) = __floats2half2_rn(vc.z * inv, vc.w * inv);
}

// =============================================================================
// scores: pure fp16 x fp16 (R14 PROVEN)
// =============================================================================
#define SBUF (2 * MATB)
#define SCF_SMEM (2 * SBUF)

__global__ void __launch_bounds__(256, 2)
scores_f16(float* __restrict__ C) {
    extern __shared__ char smc[];
    const uint32_t sb = smem_u32(smc);

    const int t = threadIdx.x;
    const int w = t >> 5, lane = t & 31;
    const int b0 = blockIdx.x * 128;
    const int i0 = blockIdx.y * 128;
    const int warp_m = w & 3;
    const int warp_n = w >> 2;

    const __half* srcA = g_item_f16 + (size_t)i0 * Dn;
    const __half* srcB = g_so_f16 + (size_t)b0 * Dn;
    const int ld_row0 = t >> 2, ld_row1 = 64 + (t >> 2), ld_seg = t & 3;

    float acc[2][8][4];
    #pragma unroll
    for (int i = 0; i < 2; i++)
        #pragma unroll
        for (int j = 0; j < 8; j++)
            #pragma unroll
            for (int r = 0; r < 4; r++) acc[i][j][r] = 0.f;

    const uint32_t aA_lane = (uint32_t)((lane & 15) * ROWB + (lane >> 4) * 16);
    const uint32_t aB_lane = (uint32_t)(((lane & 7) + ((lane >> 4) & 1) * 8) * ROWB
                                        + ((lane >> 3) & 1) * 16);

    cp16(sb + 0 * SBUF + 0 * MATB + ld_row0 * ROWB + ld_seg * 16, srcA + (size_t)ld_row0 * Dn + ld_seg * 8);
    cp16(sb + 0 * SBUF + 0 * MATB + ld_row1 * ROWB + ld_seg * 16, srcA + (size_t)ld_row1 * Dn + ld_seg * 8);
    cp16(sb + 0 * SBUF + 1 * MATB + ld_row0 * ROWB + ld_seg * 16, srcB + (size_t)ld_row0 * Dn + ld_seg * 8);
    cp16(sb + 0 * SBUF + 1 * MATB + ld_row1 * ROWB + ld_seg * 16, srcB + (size_t)ld_row1 * Dn + ld_seg * 8);
    CP_COMMIT();

    for (int kc = 0; kc < 8; kc++) {
        const int buf = kc & 1;
        if (kc < 7) {
            const int k0 = (kc + 1) * 32;
            const uint32_t nb = sb + (uint32_t)(buf ^ 1) * SBUF;
            cp16(nb + 0 * MATB + ld_row0 * ROWB + ld_seg * 16, srcA + (size_t)ld_row0 * Dn + k0 + ld_seg * 8);
            cp16(nb + 0 * MATB + ld_row1 * ROWB + ld_seg * 16, srcA + (size_t)ld_row1 * Dn + k0 + ld_seg * 8);
            cp16(nb + 1 * MATB + ld_row0 * ROWB + ld_seg * 16, srcB + (size_t)ld_row0 * Dn + k0 + ld_seg * 8);
            cp16(nb + 1 * MATB + ld_row1 * ROWB + ld_seg * 16, srcB + (size_t)ld_row1 * Dn + k0 + ld_seg * 8);
            CP_COMMIT();
            CP_WAIT(1);
        } else {
            CP_WAIT(0);
        }
        __syncthreads();

        const uint32_t baseA = sb + buf * SBUF + (uint32_t)(warp_m * 32) * ROWB + aA_lane;
        const uint32_t baseB = sb + buf * SBUF + MATB + (uint32_t)(warp_n * 64) * ROWB + aB_lane;

        #pragma unroll
        for (int ks = 0; ks < 2; ks++) {
            const uint32_t koff = (uint32_t)ks * 32;
            uint32_t af[2][4];
            #pragma unroll
            for (int i = 0; i < 2; i++)
                ldsm4(af[i], baseA + (uint32_t)(i * 16) * ROWB + koff);
            #pragma unroll
            for (int jg = 0; jg < 2; jg++) {
                uint32_t bf[2][4];
                #pragma unroll
                for (int j4 = 0; j4 < 2; j4++) {
                    const uint32_t off = (uint32_t)((jg * 2 + j4) * 16) * ROWB + koff;
                    ldsm4(bf[j4], baseB + off);
                }
                #pragma unroll
                for (int i = 0; i < 2; i++)
                    #pragma unroll
                    for (int jj = 0; jj < 4; jj++) {
                        const int j = jg * 4 + jj;
                        mma16816h(acc[i][j], af[i], &bf[jj >> 1][(jj & 1) * 2]);
                    }
            }
        }
        __syncthreads();
    }

    const int mrow = i0 + warp_m * 32 + (lane >> 2);
    const int ncol = b0 + warp_n * 64 + (lane & 3) * 2;
    #pragma unroll
    for (int i = 0; i < 2; i++) {
        #pragma unroll
        for (int j = 0; j < 8; j++) {
            const int n = ncol + j * 8;
            const int m = mrow + i * 16;
            if (m < ITEMN) {
                C[(size_t)n       * ITEMN + m]     = 16.f * acc[i][j][0];
                C[(size_t)(n + 1) * ITEMN + m]     = 16.f * acc[i][j][1];
            }
            if (m + 8 < ITEMN) {
                C[(size_t)n       * ITEMN + m + 8] = 16.f * acc[i][j][2];
                C[(size_t)(n + 1) * ITEMN + m + 8] = 16.f * acc[i][j][3];
            }
        }
    }
}

// =============================================================================
// launch — no device symbols passed as kernel args.
// =============================================================================
extern "C" void kernel_launch(void* const* d_in, const int* in_sizes, int n_in,
                              void* d_out, int out_size) {
    const int*   item_seq   = (const int*)  d_in[0];
    /* label d_in[1] unused */
    const int*   nodes      = (const int*)  d_in[2];
    const float* hn_adj     = (const float*)d_in[3];
    const int*   alias_item = (const int*)  d_in[4];
    const int*   alias_cate = (const int*)  d_in[5];
    const float* embedding  = (const float*)d_in[6];
    const int*   item_cates = (const int*)  d_in[7];
    const float* w_edge     = (const float*)d_in[8];
    const float* w_node     = (const float*)d_in[9];
    const float* q1_w       = (const float*)d_in[10];
    const float* q1_b       = (const float*)d_in[11];
    const float* q2_w       = (const float*)d_in[12];
    const float* v_w        = (const float*)d_in[13];
    float* out = (float*)d_out;

    cudaFuncSetAttribute(hgnn_mma,    cudaFuncAttributeMaxDynamicSharedMemorySize, HGM_SMEM);
    cudaFuncSetAttribute(gemm_q2_f16, cudaFuncAttributeMaxDynamicSharedMemorySize, Q2_SMEM);
    cudaFuncSetAttribute(scores_f16,  cudaFuncAttributeMaxDynamicSharedMemorySize, SCF_SMEM);

    prep_w<<<384, 256>>>(w_edge, w_node, q2_w);
    itemnorm_kernel<<<(ITEMN + 7) / 8, 256>>>(embedding, item_cates);
    hgnn_mma<<<Bn, 256, HGM_SMEM>>>(nodes, hn_adj, embedding);

    seqbuild<<<Bn * Ln / 8, 256>>>(alias_item, alias_cate);
    gemm_q2_f16<<<dim3(Bn * Ln / 128, 2), 256, Q2_SMEM>>>();
    attn_lite<<<Bn, 256>>>(item_seq, q1_w, q1_b, v_w);

    scores_f16<<<dim3(4, ITEMP / 128), 256, SCF_SMEM>>>(out);
}

// round 16
// speedup vs baseline: 2.4877x; 1.0931x over previous
#include <cuda_runtime.h>
#include <cuda_bf16.h>
#include <cuda_fp16.h>
#include <math.h>
#include <stdint.h>

#define Bn 512
#define Ln 50
#define Nn 64
#define En 16
#define Hn 128
#define Dn 256
#define ITEMN 100000
#define ITEMP 100096
#define EPS 1e-12f

// ------------------------- scratch (no allocs allowed) -------------------------
// Device globals are ONLY referenced inside device code (never host kernel args).
__device__ float g_nodes_h[Bn * Nn * Hn];
__device__ float g_seq_f32[25600 * 256];
__device__ __half g_seq_f16[25600 * 256];
__device__ float g_q2[25600 * 256];
__device__ __half g_wet_hi[128 * 128], g_wet_lo[128 * 128];   // w_edge^T fp16 hi/lo
__device__ __half g_wnt_hi[128 * 128], g_wnt_lo[128 * 128];   // w_node^T fp16 hi/lo
__device__ __half g_q2t_f16[256 * 256];                       // q2_w^T fp16 single
__device__ __half g_so_f16[Bn * Dn];                          // fp16 single
__device__ __half g_item_f16[(size_t)ITEMP * Dn];             // fp16 single

// ============================= PTX helpers =============================
__device__ __forceinline__ uint32_t smem_u32(const void* p) {
    uint32_t a;
    asm("{ .reg .u64 t; cvta.to.shared.u64 t, %1; cvt.u32.u64 %0, t; }" : "=r"(a) : "l"(p));
    return a;
}
__device__ __forceinline__ void cp16(uint32_t dst, const void* src) {
    asm volatile("cp.async.cg.shared.global [%0], [%1], 16;" :: "r"(dst), "l"(src));
}
#define CP_COMMIT() asm volatile("cp.async.commit_group;" ::: "memory")
#define CP_WAIT(n)  asm volatile("cp.async.wait_group %0;" :: "n"(n) : "memory")

__device__ __forceinline__ void ldsm4(uint32_t* r, uint32_t addr) {
    asm volatile("ldmatrix.sync.aligned.m8n8.x4.shared.b16 {%0,%1,%2,%3}, [%4];"
                 : "=r"(r[0]), "=r"(r[1]), "=r"(r[2]), "=r"(r[3]) : "r"(addr));
}
__device__ __forceinline__ void mma16816h(float* d, const uint32_t* a, const uint32_t* b) {
    asm volatile(
        "mma.sync.aligned.m16n8k16.row.col.f32.f16.f16.f32 "
        "{%0,%1,%2,%3}, {%4,%5,%6,%7}, {%8,%9}, {%0,%1,%2,%3};"
        : "+f"(d[0]), "+f"(d[1]), "+f"(d[2]), "+f"(d[3])
        : "r"(a[0]), "r"(a[1]), "r"(a[2]), "r"(a[3]), "r"(b[0]), "r"(b[1]));
}
__device__ __forceinline__ void sthilo_h(__half* hi, __half* lo, size_t idx, float v) {
    __half h = __float2half_rn(v);
    hi[idx] = h;
    lo[idx] = __float2half_rn(v - __half2float(h));
}

// =============================================================================
// hgnn_mma: fused per-batch GNN, fp16 2-term HMMA GEMMs (R15 PROVEN),
// aggs with 4-way accumulator ILP.
// =============================================================================
#define ACH 5120
#define ECH 1280
#define HG_A(kc)       ((kc) * ACH)
#define HG_EAGG(kc)    (20480 + (kc) * ECH)
#define HG_EH          25600
#define HG_W(buf, mat) (34048 + (buf) * 20480 + (mat) * 10240)
#define HG_ADJ         75008
#define HG_DEGE        79104
#define HG_DEGN        79168
#define HG_IDX         79424
#define HGM_SMEM       79872

__device__ __forceinline__ void hg_load_wchunk(uint32_t sb, int buf,
    const __half* Whi, const __half* Wlo, int kc, int t) {
    #pragma unroll
    for (int h = 0; h < 2; h++) {
        const int e = h * 256 + t;
        const int row = e >> 2, seg = e & 3;
        cp16(sb + HG_W(buf, 0) + row * 80 + seg * 16,
             Whi + (size_t)row * 128 + kc * 32 + seg * 8);
        cp16(sb + HG_W(buf, 1) + row * 80 + seg * 16,
             Wlo + (size_t)row * 128 + kc * 32 + seg * 8);
    }
}

__global__ void __launch_bounds__(256, 2)
hgnn_mma(const int* __restrict__ nodes, const float* __restrict__ hn_adj,
         const float* __restrict__ embedding) {
    extern __shared__ char smx[];
    const uint32_t sb = smem_u32(smx);
    float* s_adj  = (float*)(smx + HG_ADJ);
    float* s_eh   = (float*)(smx + HG_EH);
    float* s_dege = (float*)(smx + HG_DEGE);
    float* s_degn = (float*)(smx + HG_DEGN);
    int*   s_idx  = (int*)(smx + HG_IDX);

    const int b = blockIdx.x;
    const int t = threadIdx.x;
    const int lane = t & 31, wid = t >> 5;

    {
        const float* adjb = hn_adj + (size_t)b * Nn * En;
        for (int i = t; i < Nn * En; i += 256) s_adj[i] = adjb[i];
        if (t < Nn) s_idx[t] = nodes[b * Nn + t];
    }
    __syncthreads();

    if (t < En) {
        float s = 0.f;
        #pragma unroll 8
        for (int n = 0; n < Nn; n++) s += s_adj[n * En + t];
        s_dege[t] = fmaxf(s, 1.0f);
    }
    if (t >= 32 && t < 32 + Nn) {
        const int n = t - 32;
        float s = 0.f;
        #pragma unroll
        for (int e = 0; e < En; e++) s += s_adj[n * En + e];
        s_degn[n] = fmaxf(s, 1.0f);
    }

    // init: n_h = l2norm(embedding[nodes]) -> A region fp16
    for (int n = wid; n < Nn; n += 8) {
        const float4 v = ((const float4*)(embedding + (size_t)s_idx[n] * Hn))[lane];
        float ss = v.x * v.x + v.y * v.y + v.z * v.z + v.w * v.w;
        #pragma unroll
        for (int o = 16; o > 0; o >>= 1) ss += __shfl_xor_sync(0xffffffffu, ss, o);
        const float inv = 1.0f / fmaxf(sqrtf(ss), EPS);
        const int chunk = lane >> 3;
        const int c = (lane & 7) * 4;
        char* dst = smx + HG_A(chunk) + n * 80 + c * 2;
        *(__half2*)(dst)     = __floats2half2_rn(v.x * inv, v.y * inv);
        *(__half2*)(dst + 4) = __floats2half2_rn(v.z * inv, v.w * inv);
    }
    __syncthreads();

    const uint32_t aA_lane = (uint32_t)((lane & 15) * 80 + (lane >> 4) * 16);
    const uint32_t aB_lane = (uint32_t)(((lane & 7) + ((lane >> 4) & 1) * 8) * 80
                                        + ((lane >> 3) & 1) * 16);
    const int m2 = wid & 1, n2 = wid >> 1;

    for (int step = 0; step < 2; step++) {
        // ---- agg_e: 4-way acc ILP
        {
            const int d = t & 127;
            const int ch = d >> 5, co = (d & 31) * 2;
            const char* ap = smx + HG_A(ch) + co;
            for (int e = t >> 7; e < En; e += 2) {
                float a0 = 0.f, a1 = 0.f, a2 = 0.f, a3 = 0.f;
                #pragma unroll 4
                for (int n = 0; n < Nn; n += 4) {
                    a0 += s_adj[(n + 0) * En + e] * __half2float(*(const __half*)(ap + (n + 0) * 80));
                    a1 += s_adj[(n + 1) * En + e] * __half2float(*(const __half*)(ap + (n + 1) * 80));
                    a2 += s_adj[(n + 2) * En + e] * __half2float(*(const __half*)(ap + (n + 2) * 80));
                    a3 += s_adj[(n + 3) * En + e] * __half2float(*(const __half*)(ap + (n + 3) * 80));
                }
                const float acc = (a0 + a1) + (a2 + a3);
                *(__half*)(smx + HG_EAGG(ch) + e * 80 + co) =
                    __float2half_rn(acc / s_dege[e]);
            }
        }
        hg_load_wchunk(sb, 0, g_wet_hi, g_wet_lo, 0, t);
        CP_COMMIT();
        __syncthreads();

        // ---- GEMM1: e_h[16,128] = eagg . w_edge^T (2-term fp16 HMMA)
        {
            float acc1[2][4];
            #pragma unroll
            for (int j = 0; j < 2; j++)
                #pragma unroll
                for (int r = 0; r < 4; r++) acc1[j][r] = 0.f;

            for (int kc = 0; kc < 4; kc++) {
                const int buf = kc & 1;
                if (kc < 3) {
                    hg_load_wchunk(sb, buf ^ 1, g_wet_hi, g_wet_lo, kc + 1, t);
                    CP_COMMIT();
                    CP_WAIT(1);
                } else {
                    CP_WAIT(0);
                }
                __syncthreads();
                const uint32_t baseA = sb + HG_EAGG(kc) + aA_lane;
                const uint32_t baseB = sb + HG_W(buf, 0) + (uint32_t)(wid * 16) * 80 + aB_lane;
                #pragma unroll
                for (int ks = 0; ks < 2; ks++) {
                    const uint32_t koff = (uint32_t)ks * 32;
                    uint32_t ah[4], bh4[4], bl4[4];
                    ldsm4(ah, baseA + koff);
                    ldsm4(bh4, baseB + koff);
                    ldsm4(bl4, baseB + 10240 + koff);
                    #pragma unroll
                    for (int jj = 0; jj < 2; jj++) {
                        mma16816h(acc1[jj], ah, &bh4[jj * 2]);
                        mma16816h(acc1[jj], ah, &bl4[jj * 2]);
                    }
                }
                __syncthreads();
            }
            const int r0 = lane >> 2;
            const int colb = wid * 16 + (lane & 3) * 2;
            #pragma unroll
            for (int jj = 0; jj < 2; jj++) {
                const int col = colb + jj * 8;
                *(float2*)&s_eh[r0 * 132 + col]       = make_float2(acc1[jj][0], acc1[jj][1]);
                *(float2*)&s_eh[(r0 + 8) * 132 + col] = make_float2(acc1[jj][2], acc1[jj][3]);
            }
        }
        __syncthreads();

        // prefetch GEMM2 weight chunk 0 (overlaps agg_n)
        hg_load_wchunk(sb, 0, g_wnt_hi, g_wnt_lo, 0, t);
        CP_COMMIT();

        // ---- agg_n: 4-way acc ILP
        {
            const int d = t & 127;
            const int ch = d >> 5, co = (d & 31) * 2;
            for (int n = t >> 7; n < Nn; n += 2) {
                float a0 = 0.f, a1 = 0.f, a2 = 0.f, a3 = 0.f;
                #pragma unroll
                for (int e = 0; e < En; e += 4) {
                    a0 += s_adj[n * En + e + 0] * s_eh[(e + 0) * 132 + d];
                    a1 += s_adj[n * En + e + 1] * s_eh[(e + 1) * 132 + d];
                    a2 += s_adj[n * En + e + 2] * s_eh[(e + 2) * 132 + d];
                    a3 += s_adj[n * En + e + 3] * s_eh[(e + 3) * 132 + d];
                }
                const float acc = (a0 + a1) + (a2 + a3);
                *(__half*)(smx + HG_A(ch) + n * 80 + co) =
                    __float2half_rn(acc / s_degn[n]);
            }
        }
        __syncthreads();

        // ---- GEMM2: n_h[64,128] = nagg . w_node^T (2-term fp16), in-place epilogue
        {
            float acc2[2][4][4];
            #pragma unroll
            for (int i = 0; i < 2; i++)
                #pragma unroll
                for (int j = 0; j < 4; j++)
                    #pragma unroll
                    for (int r = 0; r < 4; r++) acc2[i][j][r] = 0.f;

            for (int kc = 0; kc < 4; kc++) {
                const int buf = kc & 1;
                if (kc < 3) {
                    hg_load_wchunk(sb, buf ^ 1, g_wnt_hi, g_wnt_lo, kc + 1, t);
                    CP_COMMIT();
                    CP_WAIT(1);
                } else {
                    CP_WAIT(0);
                }
                __syncthreads();
                const uint32_t baseA = sb + HG_A(kc) + (uint32_t)(m2 * 32) * 80 + aA_lane;
                const uint32_t baseB = sb + HG_W(buf, 0) + (uint32_t)(n2 * 32) * 80 + aB_lane;
                #pragma unroll
                for (int ks = 0; ks < 2; ks++) {
                    const uint32_t koff = (uint32_t)ks * 32;
                    uint32_t ah[2][4], bh4[2][4], bl4[2][4];
                    #pragma unroll
                    for (int i = 0; i < 2; i++)
                        ldsm4(ah[i], baseA + (uint32_t)(i * 16) * 80 + koff);
                    #pragma unroll
                    for (int j4 = 0; j4 < 2; j4++) {
                        ldsm4(bh4[j4], baseB + (uint32_t)(j4 * 16) * 80 + koff);
                        ldsm4(bl4[j4], baseB + 10240 + (uint32_t)(j4 * 16) * 80 + koff);
                    }
                    #pragma unroll
                    for (int i = 0; i < 2; i++)
                        #pragma unroll
                        for (int jj = 0; jj < 4; jj++) {
                            const uint32_t* bh = &bh4[jj >> 1][(jj & 1) * 2];
                            const uint32_t* bl = &bl4[jj >> 1][(jj & 1) * 2];
                            mma16816h(acc2[i][jj], ah[i], bh);
                            mma16816h(acc2[i][jj], ah[i], bl);
                        }
                }
                __syncthreads();
            }
            #pragma unroll
            for (int i = 0; i < 2; i++)
                #pragma unroll
                for (int jj = 0; jj < 4; jj++) {
                    const int r = m2 * 32 + 16 * i + (lane >> 2);
                    const int c = jj * 8 + (lane & 3) * 2;
                    char* base = smx + HG_A(n2);
                    *(__half2*)(base + r * 80 + c * 2) =
                        __floats2half2_rn(acc2[i][jj][0], acc2[i][jj][1]);
                    *(__half2*)(base + (r + 8) * 80 + c * 2) =
                        __floats2half2_rn(acc2[i][jj][2], acc2[i][jj][3]);
                }
        }
        __syncthreads();
    }

    for (int f = t; f < Nn * Hn; f += 256) {
        const int n = f >> 7, d = f & 127;
        const int ch = d >> 5, co = (d & 31) * 2;
        g_nodes_h[(size_t)b * Nn * Hn + f] =
            __half2float(*(const __half*)(smx + HG_A(ch) + n * 80 + co));
    }
}

// =============================================================================
// prep_w (R15 proven)
// =============================================================================
__global__ void __launch_bounds__(256)
prep_w(const float* __restrict__ w_edge, const float* __restrict__ w_node,
       const float* __restrict__ q2_w) {
    const int idx = blockIdx.x * 256 + threadIdx.x;
    if (idx < 16384) {
        const int k = idx >> 7, n = idx & 127;
        sthilo_h(g_wet_hi, g_wet_lo, (size_t)n * 128 + k, w_edge[idx]);
    } else if (idx < 32768) {
        const int i2 = idx - 16384;
        const int k = i2 >> 7, n = i2 & 127;
        sthilo_h(g_wnt_hi, g_wnt_lo, (size_t)n * 128 + k, w_node[i2]);
    } else if (idx < 98304) {
        const int i2 = idx - 32768;
        const int k = i2 >> 8, n = i2 & 255;
        g_q2t_f16[(size_t)n * 256 + k] = __float2half_rn(q2_w[i2]);
    }
}

// =============================================================================
// seqbuild (R15 proven)
// =============================================================================
__global__ void __launch_bounds__(256)
seqbuild(const int* __restrict__ alias_item, const int* __restrict__ alias_cate) {
    const int rr = blockIdx.x * 8 + (threadIdx.x >> 5);
    const int lane = threadIdx.x & 31;
    if (rr >= Bn * Ln) return;
    const int b = rr / Ln;
    const int ai = alias_item[rr];
    const int ac = alias_cate[rr];
    const float4 vi = ((const float4*)(g_nodes_h + (size_t)(b * Nn + ai) * Hn))[lane];
    const float4 vc = ((const float4*)(g_nodes_h + (size_t)(b * Nn + ac) * Hn))[lane];
    float ss = vi.x*vi.x + vi.y*vi.y + vi.z*vi.z + vi.w*vi.w
             + vc.x*vc.x + vc.y*vc.y + vc.z*vc.z + vc.w*vc.w;
    #pragma unroll
    for (int o = 16; o > 0; o >>= 1) ss += __shfl_xor_sync(0xffffffffu, ss, o);
    const float inv = 1.0f / fmaxf(sqrtf(ss), EPS);
    const float4 ni = make_float4(vi.x*inv, vi.y*inv, vi.z*inv, vi.w*inv);
    const float4 nc = make_float4(vc.x*inv, vc.y*inv, vc.z*inv, vc.w*inv);
    ((float4*)(g_seq_f32 + (size_t)rr * Dn))[lane]      = ni;
    ((float4*)(g_seq_f32 + (size_t)rr * Dn))[lane + 32] = nc;
    __half* h = g_seq_f16 + (size_t)rr * Dn;
    *(__half2*)(h + lane * 4)     = __floats2half2_rn(ni.x, ni.y);
    *(__half2*)(h + lane * 4 + 2) = __floats2half2_rn(ni.z, ni.w);
    *(__half2*)(h + 128 + lane * 4)     = __floats2half2_rn(nc.x, nc.y);
    *(__half2*)(h + 128 + lane * 4 + 2) = __floats2half2_rn(nc.z, nc.w);
}

// =============================================================================
// gemm_q2_f16 (R15 proven, 1-term fp16)
// =============================================================================
#define ROWB 80
#define MATB (128 * ROWB)
#define QBUF (2 * MATB)
#define Q2_SMEM (2 * QBUF)

__global__ void __launch_bounds__(256, 2)
gemm_q2_f16() {
    extern __shared__ char smc[];
    const uint32_t sb = smem_u32(smc);
    const int t = threadIdx.x;
    const int w = t >> 5, lane = t & 31;
    const int m0 = blockIdx.x * 128;
    const int n0 = blockIdx.y * 128;
    const int warp_m = w & 3;
    const int warp_n = w >> 2;

    const __half* srcA = g_seq_f16 + (size_t)m0 * 256;
    const __half* srcB = g_q2t_f16 + (size_t)n0 * 256;
    const int ld_row0 = t >> 2, ld_row1 = 64 + (t >> 2), ld_seg = t & 3;

    float acc[2][8][4];
    #pragma unroll
    for (int i = 0; i < 2; i++)
        #pragma unroll
        for (int j = 0; j < 8; j++)
            #pragma unroll
            for (int r = 0; r < 4; r++) acc[i][j][r] = 0.f;

    const uint32_t aA_lane = (uint32_t)((lane & 15) * ROWB + (lane >> 4) * 16);
    const uint32_t aB_lane = (uint32_t)(((lane & 7) + ((lane >> 4) & 1) * 8) * ROWB
                                        + ((lane >> 3) & 1) * 16);

    cp16(sb + 0 * QBUF + 0 * MATB + ld_row0 * ROWB + ld_seg * 16, srcA + (size_t)ld_row0 * 256 + ld_seg * 8);
    cp16(sb + 0 * QBUF + 0 * MATB + ld_row1 * ROWB + ld_seg * 16, srcA + (size_t)ld_row1 * 256 + ld_seg * 8);
    cp16(sb + 0 * QBUF + 1 * MATB + ld_row0 * ROWB + ld_seg * 16, srcB + (size_t)ld_row0 * 256 + ld_seg * 8);
    cp16(sb + 0 * QBUF + 1 * MATB + ld_row1 * ROWB + ld_seg * 16, srcB + (size_t)ld_row1 * 256 + ld_seg * 8);
    CP_COMMIT();

    for (int kc = 0; kc < 8; kc++) {
        const int buf = kc & 1;
        if (kc < 7) {
            const int k0 = (kc + 1) * 32;
            const uint32_t nb = sb + (uint32_t)(buf ^ 1) * QBUF;
            cp16(nb + 0 * MATB + ld_row0 * ROWB + ld_seg * 16, srcA + (size_t)ld_row0 * 256 + k0 + ld_seg * 8);
            cp16(nb + 0 * MATB + ld_row1 * ROWB + ld_seg * 16, srcA + (size_t)ld_row1 * 256 + k0 + ld_seg * 8);
            cp16(nb + 1 * MATB + ld_row0 * ROWB + ld_seg * 16, srcB + (size_t)ld_row0 * 256 + k0 + ld_seg * 8);
            cp16(nb + 1 * MATB + ld_row1 * ROWB + ld_seg * 16, srcB + (size_t)ld_row1 * 256 + k0 + ld_seg * 8);
            CP_COMMIT();
            CP_WAIT(1);
        } else {
            CP_WAIT(0);
        }
        __syncthreads();

        const uint32_t baseA = sb + buf * QBUF + (uint32_t)(warp_m * 32) * ROWB + aA_lane;
        const uint32_t baseB = sb + buf * QBUF + MATB + (uint32_t)(warp_n * 64) * ROWB + aB_lane;

        #pragma unroll
        for (int ks = 0; ks < 2; ks++) {
            const uint32_t koff = (uint32_t)ks * 32;
            uint32_t af[2][4];
            #pragma unroll
            for (int i = 0; i < 2; i++)
                ldsm4(af[i], baseA + (uint32_t)(i * 16) * ROWB + koff);
            #pragma unroll
            for (int jg = 0; jg < 2; jg++) {
                uint32_t bf[2][4];
                #pragma unroll
                for (int j4 = 0; j4 < 2; j4++) {
                    const uint32_t off = (uint32_t)((jg * 2 + j4) * 16) * ROWB + koff;
                    ldsm4(bf[j4], baseB + off);
                }
                #pragma unroll
                for (int i = 0; i < 2; i++)
                    #pragma unroll
                    for (int jj = 0; jj < 4; jj++) {
                        const int j = jg * 4 + jj;
                        mma16816h(acc[i][j], af[i], &bf[jj >> 1][(jj & 1) * 2]);
                    }
            }
        }
        __syncthreads();
    }

    const int mrow = m0 + warp_m * 32 + (lane >> 2);
    const int ncol = n0 + warp_n * 64 + (lane & 3) * 2;
    #pragma unroll
    for (int i = 0; i < 2; i++) {
        #pragma unroll
        for (int j = 0; j < 8; j++) {
            const int m = mrow + i * 16;
            const int n = ncol + j * 8;
            *(float2*)(g_q2 + (size_t)m * 256 + n)       = make_float2(acc[i][j][0], acc[i][j][1]);
            *(float2*)(g_q2 + (size_t)(m + 8) * 256 + n) = make_float2(acc[i][j][2], acc[i][j][3]);
        }
    }
}

// =============================================================================
// attn_lite (R7 proven; q1 with 4-way acc ILP)
// =============================================================================
__global__ void __launch_bounds__(256, 2)
attn_lite(const int* __restrict__ item_seq,
          const float* __restrict__ q1_w, const float* __restrict__ q1_b,
          const float* __restrict__ v_w) {
    __shared__ float s_ht[Dn];
    __shared__ float s_part[Ln * 8];
    __shared__ float s_alpha[Ln + 2];
    __shared__ float s_mask[Ln + 2];
    __shared__ float s_red[8];
    __shared__ float s_bcast;
    __shared__ int   s_last;

    const int b = blockIdx.x;
    const int t = threadIdx.x;
    const int lane = t & 31, wid = t >> 5;

    if (t < Ln) s_mask[t] = (item_seq[b * Ln + t] > 0) ? 1.0f : 0.0f;
    if (t == 0) {
        int cnt = 0;
        for (int l = 0; l < Ln; l++) cnt += (item_seq[b * Ln + l] > 0) ? 1 : 0;
        s_last = max(cnt - 1, 0);
    }
    __syncthreads();
    s_ht[t] = g_seq_f32[((size_t)b * Ln + s_last) * Dn + t];
    __syncthreads();

    float q1v;
    {
        float a0 = 0.f, a1 = 0.f, a2 = 0.f, a3 = 0.f;
        #pragma unroll 4
        for (int d = 0; d < Dn; d += 4) {
            a0 += s_ht[d + 0] * q1_w[(d + 0) * Dn + t];
            a1 += s_ht[d + 1] * q1_w[(d + 1) * Dn + t];
            a2 += s_ht[d + 2] * q1_w[(d + 2) * Dn + t];
            a3 += s_ht[d + 3] * q1_w[(d + 3) * Dn + t];
        }
        q1v = (a0 + a1) + (a2 + a3) + q1_b[t];
    }

    const float vw = v_w[t];
    for (int l = 0; l < Ln; l++) {
        const float x = q1v + g_q2[((size_t)b * Ln + l) * Dn + t];
        float c = vw / (1.0f + expf(-x));
        #pragma unroll
        for (int o = 16; o > 0; o >>= 1) c += __shfl_xor_sync(0xffffffffu, c, o);
        if (lane == 0) s_part[l * 8 + wid] = c;
    }
    __syncthreads();
    if (t < Ln) {
        float a = 0.f;
        #pragma unroll
        for (int w = 0; w < 8; w++) a += s_part[t * 8 + w];
        s_alpha[t] = a * s_mask[t];
    }
    __syncthreads();

    float outacc = 0.f;
    #pragma unroll 5
    for (int l = 0; l < Ln; l++)
        outacc += s_alpha[l] * g_seq_f32[((size_t)b * Ln + l) * Dn + t];

    float ss = outacc * outacc;
    #pragma unroll
    for (int o = 16; o > 0; o >>= 1) ss += __shfl_xor_sync(0xffffffffu, ss, o);
    if (lane == 0) s_red[wid] = ss;
    __syncthreads();
    if (t == 0) {
        float a = 0.f;
        #pragma unroll
        for (int w = 0; w < 8; w++) a += s_red[w];
        s_bcast = a;
    }
    __syncthreads();
    const float inv = 1.0f / fmaxf(sqrtf(s_bcast), EPS);
    g_so_f16[(size_t)b * Dn + t] = __float2half_rn(outacc * inv);
}

// =============================================================================
// itemnorm: fp16 single output (R13 proven)
// =============================================================================
__global__ void __launch_bounds__(256)
itemnorm_kernel(const float* __restrict__ embedding, const int* __restrict__ item_cates) {
    const int i = blockIdx.x * 8 + (threadIdx.x >> 5);
    const int lane = threadIdx.x & 31;
    if (i >= ITEMN) return;
    const int c = item_cates[i];
    const float4 vi = ((const float4*)(embedding + (size_t)i * Hn))[lane];
    const float4 vc = ((const float4*)(embedding + (size_t)c * Hn))[lane];
    float ss = vi.x*vi.x + vi.y*vi.y + vi.z*vi.z + vi.w*vi.w
             + vc.x*vc.x + vc.y*vc.y + vc.z*vc.z + vc.w*vc.w;
    #pragma unroll
    for (int o = 16; o > 0; o >>= 1) ss += __shfl_xor_sync(0xffffffffu, ss, o);
    const float inv = 1.0f / fmaxf(sqrtf(ss), EPS);
    __half* dst = g_item_f16 + (size_t)i * Dn;
    *(__half2*)(dst + lane * 4)     = __floats2half2_rn(vi.x * inv, vi.y * inv);
    *(__half2*)(dst + lane * 4 + 2) = __floats2half2_rn(vi.z * inv, vi.w * inv);
    *(__half2*)(dst + 128 + lane * 4)     = __floats2half2_rn(vc.x * inv, vc.y * inv);
    *(__half2*)(dst + 128 + lane * 4 + 2) = __floats2half2_rn(vc.z * inv, vc.w * inv);
}

// =============================================================================
// scores: pure fp16 x fp16, 3-stage cp.async pipeline.
// =============================================================================
#define SBUF (2 * MATB)
#define SCF_SMEM (3 * SBUF)    // 61440

__device__ __forceinline__ void sc_load_chunk(uint32_t nb, const __half* srcA,
    const __half* srcB, int k0, int ld_row0, int ld_row1, int ld_seg) {
    cp16(nb + 0 * MATB + ld_row0 * ROWB + ld_seg * 16, srcA + (size_t)ld_row0 * Dn + k0 + ld_seg * 8);
    cp16(nb + 0 * MATB + ld_row1 * ROWB + ld_seg * 16, srcA + (size_t)ld_row1 * Dn + k0 + ld_seg * 8);
    cp16(nb + 1 * MATB + ld_row0 * ROWB + ld_seg * 16, srcB + (size_t)ld_row0 * Dn + k0 + ld_seg * 8);
    cp16(nb + 1 * MATB + ld_row1 * ROWB + ld_seg * 16, srcB + (size_t)ld_row1 * Dn + k0 + ld_seg * 8);
}

__global__ void __launch_bounds__(256, 2)
scores_f16(float* __restrict__ C) {
    extern __shared__ char smc[];
    const uint32_t sb = smem_u32(smc);

    const int t = threadIdx.x;
    const int w = t >> 5, lane = t & 31;
    const int b0 = blockIdx.x * 128;
    const int i0 = blockIdx.y * 128;
    const int warp_m = w & 3;
    const int warp_n = w >> 2;

    const __half* srcA = g_item_f16 + (size_t)i0 * Dn;
    const __half* srcB = g_so_f16 + (size_t)b0 * Dn;
    const int ld_row0 = t >> 2, ld_row1 = 64 + (t >> 2), ld_seg = t & 3;

    float acc[2][8][4];
    #pragma unroll
    for (int i = 0; i < 2; i++)
        #pragma unroll
        for (int j = 0; j < 8; j++)
            #pragma unroll
            for (int r = 0; r < 4; r++) acc[i][j][r] = 0.f;

    const uint32_t aA_lane = (uint32_t)((lane & 15) * ROWB + (lane >> 4) * 16);
    const uint32_t aB_lane = (uint32_t)(((lane & 7) + ((lane >> 4) & 1) * 8) * ROWB
                                        + ((lane >> 3) & 1) * 16);

    // prefetch chunks 0,1 -> bufs 0,1 (separate commit groups)
    sc_load_chunk(sb + 0 * SBUF, srcA, srcB, 0, ld_row0, ld_row1, ld_seg);
    CP_COMMIT();
    sc_load_chunk(sb + 1 * SBUF, srcA, srcB, 32, ld_row0, ld_row1, ld_seg);
    CP_COMMIT();

    int bufk = 0;               // buffer of chunk kc
    for (int kc = 0; kc < 8; kc++) {
        if (kc < 6) {
            const int nbuf = (bufk + 2) % 3;
            sc_load_chunk(sb + (uint32_t)nbuf * SBUF, srcA, srcB, (kc + 2) * 32,
                          ld_row0, ld_row1, ld_seg);
            CP_COMMIT();
            CP_WAIT(2);
        } else if (kc == 6) {
            CP_WAIT(1);
        } else {
            CP_WAIT(0);
        }
        __syncthreads();

        const uint32_t baseA = sb + (uint32_t)bufk * SBUF + (uint32_t)(warp_m * 32) * ROWB + aA_lane;
        const uint32_t baseB = sb + (uint32_t)bufk * SBUF + MATB + (uint32_t)(warp_n * 64) * ROWB + aB_lane;

        #pragma unroll
        for (int ks = 0; ks < 2; ks++) {
            const uint32_t koff = (uint32_t)ks * 32;
            uint32_t af[2][4];
            #pragma unroll
            for (int i = 0; i < 2; i++)
                ldsm4(af[i], baseA + (uint32_t)(i * 16) * ROWB + koff);
            #pragma unroll
            for (int jg = 0; jg < 2; jg++) {
                uint32_t bf[2][4];
                #pragma unroll
                for (int j4 = 0; j4 < 2; j4++) {
                    const uint32_t off = (uint32_t)((jg * 2 + j4) * 16) * ROWB + koff;
                    ldsm4(bf[j4], baseB + off);
                }
                #pragma unroll
                for (int i = 0; i < 2; i++)
                    #pragma unroll
                    for (int jj = 0; jj < 4; jj++) {
                        const int j = jg * 4 + jj;
                        mma16816h(acc[i][j], af[i], &bf[jj >> 1][(jj & 1) * 2]);
                    }
            }
        }
        __syncthreads();
        bufk = (bufk + 1) % 3;
    }

    const int mrow = i0 + warp_m * 32 + (lane >> 2);
    const int ncol = b0 + warp_n * 64 + (lane & 3) * 2;
    #pragma unroll
    for (int i = 0; i < 2; i++) {
        #pragma unroll
        for (int j = 0; j < 8; j++) {
            const int n = ncol + j * 8;
            const int m = mrow + i * 16;
            if (m < ITEMN) {
                C[(size_t)n       * ITEMN + m]     = 16.f * acc[i][j][0];
                C[(size_t)(n + 1) * ITEMN + m]     = 16.f * acc[i][j][1];
            }
            if (m + 8 < ITEMN) {
                C[(size_t)n       * ITEMN + m + 8] = 16.f * acc[i][j][2];
                C[(size_t)(n + 1) * ITEMN + m + 8] = 16.f * acc[i][j][3];
            }
        }
    }
}

// =============================================================================
// launch — no device symbols passed as kernel args.
// =============================================================================
extern "C" void kernel_launch(void* const* d_in, const int* in_sizes, int n_in,
                              void* d_out, int out_size) {
    const int*   item_seq   = (const int*)  d_in[0];
    /* label d_in[1] unused */
    const int*   nodes      = (const int*)  d_in[2];
    const float* hn_adj     = (const float*)d_in[3];
    const int*   alias_item = (const int*)  d_in[4];
    const int*   alias_cate = (const int*)  d_in[5];
    const float* embedding  = (const float*)d_in[6];
    const int*   item_cates = (const int*)  d_in[7];
    const float* w_edge     = (const float*)d_in[8];
    const float* w_node     = (const float*)d_in[9];
    const float* q1_w       = (const float*)d_in[10];
    const float* q1_b       = (const float*)d_in[11];
    const float* q2_w       = (const float*)d_in[12];
    const float* v_w        = (const float*)d_in[13];
    float* out = (float*)d_out;

    cudaFuncSetAttribute(hgnn_mma,    cudaFuncAttributeMaxDynamicSharedMemorySize, HGM_SMEM);
    cudaFuncSetAttribute(gemm_q2_f16, cudaFuncAttributeMaxDynamicSharedMemorySize, Q2_SMEM);
    cudaFuncSetAttribute(scores_f16,  cudaFuncAttributeMaxDynamicSharedMemorySize, SCF_SMEM);

    prep_w<<<384, 256>>>(w_edge, w_node, q2_w);
    itemnorm_kernel<<<(ITEMN + 7) / 8, 256>>>(embedding, item_cates);
    hgnn_mma<<<Bn, 256, HGM_SMEM>>>(nodes, hn_adj, embedding);

    seqbuild<<<Bn * Ln / 8, 256>>>(alias_item, alias_cate);
    gemm_q2_f16<<<dim3(Bn * Ln / 128, 2), 256, Q2_SMEM>>>();
    attn_lite<<<Bn, 256>>>(item_seq, q1_w, q1_b, v_w);

    scores_f16<<<dim3(4, ITEMP / 128), 256, SCF_SMEM>>>(out);
}

// round 17
// speedup vs baseline: 2.4934x; 1.0023x over previous
#include <cuda_runtime.h>
#include <cuda_bf16.h>
#include <cuda_fp16.h>
#include <math.h>
#include <stdint.h>

#define Bn 512
#define Ln 50
#define Nn 64
#define En 16
#define Hn 128
#define Dn 256
#define ITEMN 100000
#define ITEMP 100096
#define EPS 1e-12f

// ------------------------- scratch (no allocs allowed) -------------------------
// Device globals are ONLY referenced inside device code (never host kernel args).
__device__ float g_nodes_h[Bn * Nn * Hn];
__device__ float g_seq_f32[25600 * 256];
__device__ __half g_seq_f16[25600 * 256];
__device__ float g_q2[25600 * 256];
__device__ __half g_wet_f16[128 * 128];                       // w_edge^T fp16
__device__ __half g_wnt_f16[128 * 128];                       // w_node^T fp16
__device__ __half g_q2t_f16[256 * 256];                       // q2_w^T fp16
__device__ __half g_so_f16[Bn * Dn];
__device__ __half g_item_f16[(size_t)ITEMP * Dn];

// ============================= PTX helpers =============================
__device__ __forceinline__ uint32_t smem_u32(const void* p) {
    uint32_t a;
    asm("{ .reg .u64 t; cvta.to.shared.u64 t, %1; cvt.u32.u64 %0, t; }" : "=r"(a) : "l"(p));
    return a;
}
__device__ __forceinline__ void cp16(uint32_t dst, const void* src) {
    asm volatile("cp.async.cg.shared.global [%0], [%1], 16;" :: "r"(dst), "l"(src));
}
#define CP_COMMIT() asm volatile("cp.async.commit_group;" ::: "memory")
#define CP_WAIT(n)  asm volatile("cp.async.wait_group %0;" :: "n"(n) : "memory")

__device__ __forceinline__ void ldsm4(uint32_t* r, uint32_t addr) {
    asm volatile("ldmatrix.sync.aligned.m8n8.x4.shared.b16 {%0,%1,%2,%3}, [%4];"
                 : "=r"(r[0]), "=r"(r[1]), "=r"(r[2]), "=r"(r[3]) : "r"(addr));
}
__device__ __forceinline__ void mma16816h(float* d, const uint32_t* a, const uint32_t* b) {
    asm volatile(
        "mma.sync.aligned.m16n8k16.row.col.f32.f16.f16.f32 "
        "{%0,%1,%2,%3}, {%4,%5,%6,%7}, {%8,%9}, {%0,%1,%2,%3};"
        : "+f"(d[0]), "+f"(d[1]), "+f"(d[2]), "+f"(d[3])
        : "r"(a[0]), "r"(a[1]), "r"(a[2]), "r"(a[3]), "r"(b[0]), "r"(b[1]));
}

// =============================================================================
// hgnn_mma: fused per-batch GNN, 1-term fp16 HMMA GEMMs, resident full-K weight.
// Smem map (bytes):
//  A (activations) [4 kc][64 x 80B fp16] : 0     .. 20480
//  EAGG            [4 kc][16 x 80B fp16] : 20480 .. 25600
//  EH fp32 [16 x 132]                    : 25600 .. 34048
//  W resident [4 kc][128 x 80B fp16]     : 34048 .. 75008
//  ADJ fp32 [64 x 16]                    : 75008 .. 79104
//  deg_e, deg_n, idx                     : 79104 .. 79680
// =============================================================================
#define ACH 5120
#define ECH 1280
#define HG_A(kc)     ((kc) * ACH)
#define HG_EAGG(kc)  (20480 + (kc) * ECH)
#define HG_EH        25600
#define HG_W(kc)     (34048 + (kc) * 10240)
#define HG_ADJ       75008
#define HG_DEGE      79104
#define HG_DEGN      79168
#define HG_IDX       79424
#define HGM_SMEM     79872

__device__ __forceinline__ void hg_load_wfull(uint32_t sb, const __half* W, int t) {
    #pragma unroll
    for (int h = 0; h < 8; h++) {
        const int e = h * 256 + t;                  // 0..2047
        const int kc = e >> 9;
        const int row = (e & 511) >> 2, seg = e & 3;
        cp16(sb + HG_W(kc) + row * 80 + seg * 16,
             W + (size_t)row * 128 + kc * 32 + seg * 8);
    }
}

__global__ void __launch_bounds__(256, 2)
hgnn_mma(const int* __restrict__ nodes, const float* __restrict__ hn_adj,
         const float* __restrict__ embedding) {
    extern __shared__ char smx[];
    const uint32_t sb = smem_u32(smx);
    float* s_adj  = (float*)(smx + HG_ADJ);
    float* s_eh   = (float*)(smx + HG_EH);
    float* s_dege = (float*)(smx + HG_DEGE);
    float* s_degn = (float*)(smx + HG_DEGN);
    int*   s_idx  = (int*)(smx + HG_IDX);

    const int b = blockIdx.x;
    const int t = threadIdx.x;
    const int lane = t & 31, wid = t >> 5;

    {
        const float* adjb = hn_adj + (size_t)b * Nn * En;
        for (int i = t; i < Nn * En; i += 256) s_adj[i] = adjb[i];
        if (t < Nn) s_idx[t] = nodes[b * Nn + t];
    }
    __syncthreads();

    if (t < En) {
        float s = 0.f;
        #pragma unroll 8
        for (int n = 0; n < Nn; n++) s += s_adj[n * En + t];
        s_dege[t] = fmaxf(s, 1.0f);
    }
    if (t >= 32 && t < 32 + Nn) {
        const int n = t - 32;
        float s = 0.f;
        #pragma unroll
        for (int e = 0; e < En; e++) s += s_adj[n * En + e];
        s_degn[n] = fmaxf(s, 1.0f);
    }

    // init: n_h = l2norm(embedding[nodes]) -> A region fp16
    for (int n = wid; n < Nn; n += 8) {
        const float4 v = ((const float4*)(embedding + (size_t)s_idx[n] * Hn))[lane];
        float ss = v.x * v.x + v.y * v.y + v.z * v.z + v.w * v.w;
        #pragma unroll
        for (int o = 16; o > 0; o >>= 1) ss += __shfl_xor_sync(0xffffffffu, ss, o);
        const float inv = 1.0f / fmaxf(sqrtf(ss), EPS);
        const int chunk = lane >> 3;
        const int c = (lane & 7) * 4;
        char* dst = smx + HG_A(chunk) + n * 80 + c * 2;
        *(__half2*)(dst)     = __floats2half2_rn(v.x * inv, v.y * inv);
        *(__half2*)(dst + 4) = __floats2half2_rn(v.z * inv, v.w * inv);
    }
    __syncthreads();

    const uint32_t aA_lane = (uint32_t)((lane & 15) * 80 + (lane >> 4) * 16);
    const uint32_t aB_lane = (uint32_t)(((lane & 7) + ((lane >> 4) & 1) * 8) * 80
                                        + ((lane >> 3) & 1) * 16);
    const int m2 = wid & 1, n2 = wid >> 1;

    for (int step = 0; step < 2; step++) {
        // issue full wet load; overlap with agg_e
        hg_load_wfull(sb, g_wet_f16, t);
        CP_COMMIT();

        // ---- agg_e: 4-way acc ILP (reads A, writes EAGG)
        {
            const int d = t & 127;
            const int ch = d >> 5, co = (d & 31) * 2;
            const char* ap = smx + HG_A(ch) + co;
            for (int e = t >> 7; e < En; e += 2) {
                float a0 = 0.f, a1 = 0.f, a2 = 0.f, a3 = 0.f;
                #pragma unroll 4
                for (int n = 0; n < Nn; n += 4) {
                    a0 += s_adj[(n + 0) * En + e] * __half2float(*(const __half*)(ap + (n + 0) * 80));
                    a1 += s_adj[(n + 1) * En + e] * __half2float(*(const __half*)(ap + (n + 1) * 80));
                    a2 += s_adj[(n + 2) * En + e] * __half2float(*(const __half*)(ap + (n + 2) * 80));
                    a3 += s_adj[(n + 3) * En + e] * __half2float(*(const __half*)(ap + (n + 3) * 80));
                }
                const float acc = (a0 + a1) + (a2 + a3);
                *(__half*)(smx + HG_EAGG(ch) + e * 80 + co) =
                    __float2half_rn(acc / s_dege[e]);
            }
        }
        CP_WAIT(0);
        __syncthreads();

        // ---- GEMM1: e_h[16,128] = eagg . w_edge^T (1-term, no inner barriers)
        {
            float acc1[2][4];
            #pragma unroll
            for (int j = 0; j < 2; j++)
                #pragma unroll
                for (int r = 0; r < 4; r++) acc1[j][r] = 0.f;

            #pragma unroll
            for (int kc = 0; kc < 4; kc++) {
                const uint32_t baseA = sb + HG_EAGG(kc) + aA_lane;
                const uint32_t baseB = sb + HG_W(kc) + (uint32_t)(wid * 16) * 80 + aB_lane;
                #pragma unroll
                for (int ks = 0; ks < 2; ks++) {
                    const uint32_t koff = (uint32_t)ks * 32;
                    uint32_t ah[4], bh4[4];
                    ldsm4(ah, baseA + koff);
                    ldsm4(bh4, baseB + koff);
                    #pragma unroll
                    for (int jj = 0; jj < 2; jj++)
                        mma16816h(acc1[jj], ah, &bh4[jj * 2]);
                }
            }
            const int r0 = lane >> 2;
            const int colb = wid * 16 + (lane & 3) * 2;
            #pragma unroll
            for (int jj = 0; jj < 2; jj++) {
                const int col = colb + jj * 8;
                *(float2*)&s_eh[r0 * 132 + col]       = make_float2(acc1[jj][0], acc1[jj][1]);
                *(float2*)&s_eh[(r0 + 8) * 132 + col] = make_float2(acc1[jj][2], acc1[jj][3]);
            }
        }
        __syncthreads();

        // issue full wnt load (W reads of GEMM1 done, synced); overlap with agg_n
        hg_load_wfull(sb, g_wnt_f16, t);
        CP_COMMIT();

        // ---- agg_n: 4-way acc ILP (reads s_eh, writes A region)
        {
            const int d = t & 127;
            const int ch = d >> 5, co = (d & 31) * 2;
            for (int n = t >> 7; n < Nn; n += 2) {
                float a0 = 0.f, a1 = 0.f, a2 = 0.f, a3 = 0.f;
                #pragma unroll
                for (int e = 0; e < En; e += 4) {
                    a0 += s_adj[n * En + e + 0] * s_eh[(e + 0) * 132 + d];
                    a1 += s_adj[n * En + e + 1] * s_eh[(e + 1) * 132 + d];
                    a2 += s_adj[n * En + e + 2] * s_eh[(e + 2) * 132 + d];
                    a3 += s_adj[n * En + e + 3] * s_eh[(e + 3) * 132 + d];
                }
                const float acc = (a0 + a1) + (a2 + a3);
                *(__half*)(smx + HG_A(ch) + n * 80 + co) =
                    __float2half_rn(acc / s_degn[n]);
            }
        }
        CP_WAIT(0);
        __syncthreads();

        // ---- GEMM2: n_h[64,128] = nagg . w_node^T (1-term, no inner barriers)
        {
            float acc2[2][4][4];
            #pragma unroll
            for (int i = 0; i < 2; i++)
                #pragma unroll
                for (int j = 0; j < 4; j++)
                    #pragma unroll
                    for (int r = 0; r < 4; r++) acc2[i][j][r] = 0.f;

            #pragma unroll
            for (int kc = 0; kc < 4; kc++) {
                const uint32_t baseA = sb + HG_A(kc) + (uint32_t)(m2 * 32) * 80 + aA_lane;
                const uint32_t baseB = sb + HG_W(kc) + (uint32_t)(n2 * 32) * 80 + aB_lane;
                #pragma unroll
                for (int ks = 0; ks < 2; ks++) {
                    const uint32_t koff = (uint32_t)ks * 32;
                    uint32_t ah[2][4], bh4[2][4];
                    #pragma unroll
                    for (int i = 0; i < 2; i++)
                        ldsm4(ah[i], baseA + (uint32_t)(i * 16) * 80 + koff);
                    #pragma unroll
                    for (int j4 = 0; j4 < 2; j4++)
                        ldsm4(bh4[j4], baseB + (uint32_t)(j4 * 16) * 80 + koff);
                    #pragma unroll
                    for (int i = 0; i < 2; i++)
                        #pragma unroll
                        for (int jj = 0; jj < 4; jj++)
                            mma16816h(acc2[i][jj], ah[i], &bh4[jj >> 1][(jj & 1) * 2]);
                }
            }
            __syncthreads();   // all A reads done before in-place overwrite
            #pragma unroll
            for (int i = 0; i < 2; i++)
                #pragma unroll
                for (int jj = 0; jj < 4; jj++) {
                    const int r = m2 * 32 + 16 * i + (lane >> 2);
                    const int c = jj * 8 + (lane & 3) * 2;
                    char* base = smx + HG_A(n2);
                    *(__half2*)(base + r * 80 + c * 2) =
                        __floats2half2_rn(acc2[i][jj][0], acc2[i][jj][1]);
                    *(__half2*)(base + (r + 8) * 80 + c * 2) =
                        __floats2half2_rn(acc2[i][jj][2], acc2[i][jj][3]);
                }
        }
        __syncthreads();
    }

    for (int f = t; f < Nn * Hn; f += 256) {
        const int n = f >> 7, d = f & 127;
        const int ch = d >> 5, co = (d & 31) * 2;
        g_nodes_h[(size_t)b * Nn * Hn + f] =
            __half2float(*(const __half*)(smx + HG_A(ch) + n * 80 + co));
    }
}

// =============================================================================
// prep_w: transpose weights to fp16 single
// =============================================================================
__global__ void __launch_bounds__(256)
prep_w(const float* __restrict__ w_edge, const float* __restrict__ w_node,
       const float* __restrict__ q2_w) {
    const int idx = blockIdx.x * 256 + threadIdx.x;
    if (idx < 16384) {
        const int k = idx >> 7, n = idx & 127;
        g_wet_f16[(size_t)n * 128 + k] = __float2half_rn(w_edge[idx]);
    } else if (idx < 32768) {
        const int i2 = idx - 16384;
        const int k = i2 >> 7, n = i2 & 127;
        g_wnt_f16[(size_t)n * 128 + k] = __float2half_rn(w_node[i2]);
    } else if (idx < 98304) {
        const int i2 = idx - 32768;
        const int k = i2 >> 8, n = i2 & 255;
        g_q2t_f16[(size_t)n * 256 + k] = __float2half_rn(q2_w[i2]);
    }
}

// =============================================================================
// seqbuild (R15 proven)
// =============================================================================
__global__ void __launch_bounds__(256)
seqbuild(const int* __restrict__ alias_item, const int* __restrict__ alias_cate) {
    const int rr = blockIdx.x * 8 + (threadIdx.x >> 5);
    const int lane = threadIdx.x & 31;
    if (rr >= Bn * Ln) return;
    const int b = rr / Ln;
    const int ai = alias_item[rr];
    const int ac = alias_cate[rr];
    const float4 vi = ((const float4*)(g_nodes_h + (size_t)(b * Nn + ai) * Hn))[lane];
    const float4 vc = ((const float4*)(g_nodes_h + (size_t)(b * Nn + ac) * Hn))[lane];
    float ss = vi.x*vi.x + vi.y*vi.y + vi.z*vi.z + vi.w*vi.w
             + vc.x*vc.x + vc.y*vc.y + vc.z*vc.z + vc.w*vc.w;
    #pragma unroll
    for (int o = 16; o > 0; o >>= 1) ss += __shfl_xor_sync(0xffffffffu, ss, o);
    const float inv = 1.0f / fmaxf(sqrtf(ss), EPS);
    const float4 ni = make_float4(vi.x*inv, vi.y*inv, vi.z*inv, vi.w*inv);
    const float4 nc = make_float4(vc.x*inv, vc.y*inv, vc.z*inv, vc.w*inv);
    ((float4*)(g_seq_f32 + (size_t)rr * Dn))[lane]      = ni;
    ((float4*)(g_seq_f32 + (size_t)rr * Dn))[lane + 32] = nc;
    __half* h = g_seq_f16 + (size_t)rr * Dn;
    *(__half2*)(h + lane * 4)     = __floats2half2_rn(ni.x, ni.y);
    *(__half2*)(h + lane * 4 + 2) = __floats2half2_rn(ni.z, ni.w);
    *(__half2*)(h + 128 + lane * 4)     = __floats2half2_rn(nc.x, nc.y);
    *(__half2*)(h + 128 + lane * 4 + 2) = __floats2half2_rn(nc.z, nc.w);
}

// =============================================================================
// gemm_q2_f16 (R15 proven, 1-term fp16)
// =============================================================================
#define ROWB 80
#define MATB (128 * ROWB)
#define QBUF (2 * MATB)
#define Q2_SMEM (2 * QBUF)

__global__ void __launch_bounds__(256, 2)
gemm_q2_f16() {
    extern __shared__ char smc[];
    const uint32_t sb = smem_u32(smc);
    const int t = threadIdx.x;
    const int w = t >> 5, lane = t & 31;
    const int m0 = blockIdx.x * 128;
    const int n0 = blockIdx.y * 128;
    const int warp_m = w & 3;
    const int warp_n = w >> 2;

    const __half* srcA = g_seq_f16 + (size_t)m0 * 256;
    const __half* srcB = g_q2t_f16 + (size_t)n0 * 256;
    const int ld_row0 = t >> 2, ld_row1 = 64 + (t >> 2), ld_seg = t & 3;

    float acc[2][8][4];
    #pragma unroll
    for (int i = 0; i < 2; i++)
        #pragma unroll
        for (int j = 0; j < 8; j++)
            #pragma unroll
            for (int r = 0; r < 4; r++) acc[i][j][r] = 0.f;

    const uint32_t aA_lane = (uint32_t)((lane & 15) * ROWB + (lane >> 4) * 16);
    const uint32_t aB_lane = (uint32_t)(((lane & 7) + ((lane >> 4) & 1) * 8) * ROWB
                                        + ((lane >> 3) & 1) * 16);

    cp16(sb + 0 * QBUF + 0 * MATB + ld_row0 * ROWB + ld_seg * 16, srcA + (size_t)ld_row0 * 256 + ld_seg * 8);
    cp16(sb + 0 * QBUF + 0 * MATB + ld_row1 * ROWB + ld_seg * 16, srcA + (size_t)ld_row1 * 256 + ld_seg * 8);
    cp16(sb + 0 * QBUF + 1 * MATB + ld_row0 * ROWB + ld_seg * 16, srcB + (size_t)ld_row0 * 256 + ld_seg * 8);
    cp16(sb + 0 * QBUF + 1 * MATB + ld_row1 * ROWB + ld_seg * 16, srcB + (size_t)ld_row1 * 256 + ld_seg * 8);
    CP_COMMIT();

    for (int kc = 0; kc < 8; kc++) {
        const int buf = kc & 1;
        if (kc < 7) {
            const int k0 = (kc + 1) * 32;
            const uint32_t nb = sb + (uint32_t)(buf ^ 1) * QBUF;
            cp16(nb + 0 * MATB + ld_row0 * ROWB + ld_seg * 16, srcA + (size_t)ld_row0 * 256 + k0 + ld_seg * 8);
            cp16(nb + 0 * MATB + ld_row1 * ROWB + ld_seg * 16, srcA + (size_t)ld_row1 * 256 + k0 + ld_seg * 8);
            cp16(nb + 1 * MATB + ld_row0 * ROWB + ld_seg * 16, srcB + (size_t)ld_row0 * 256 + k0 + ld_seg * 8);
            cp16(nb + 1 * MATB + ld_row1 * ROWB + ld_seg * 16, srcB + (size_t)ld_row1 * 256 + k0 + ld_seg * 8);
            CP_COMMIT();
            CP_WAIT(1);
        } else {
            CP_WAIT(0);
        }
        __syncthreads();

        const uint32_t baseA = sb + buf * QBUF + (uint32_t)(warp_m * 32) * ROWB + aA_lane;
        const uint32_t baseB = sb + buf * QBUF + MATB + (uint32_t)(warp_n * 64) * ROWB + aB_lane;

        #pragma unroll
        for (int ks = 0; ks < 2; ks++) {
            const uint32_t koff = (uint32_t)ks * 32;
            uint32_t af[2][4];
            #pragma unroll
            for (int i = 0; i < 2; i++)
                ldsm4(af[i], baseA + (uint32_t)(i * 16) * ROWB + koff);
            #pragma unroll
            for (int jg = 0; jg < 2; jg++) {
                uint32_t bf[2][4];
                #pragma unroll
                for (int j4 = 0; j4 < 2; j4++) {
                    const uint32_t off = (uint32_t)((jg * 2 + j4) * 16) * ROWB + koff;
                    ldsm4(bf[j4], baseB + off);
                }
                #pragma unroll
                for (int i = 0; i < 2; i++)
                    #pragma unroll
                    for (int jj = 0; jj < 4; jj++) {
                        const int j = jg * 4 + jj;
                        mma16816h(acc[i][j], af[i], &bf[jj >> 1][(jj & 1) * 2]);
                    }
            }
        }
        __syncthreads();
    }

    const int mrow = m0 + warp_m * 32 + (lane >> 2);
    const int ncol = n0 + warp_n * 64 + (lane & 3) * 2;
    #pragma unroll
    for (int i = 0; i < 2; i++) {
        #pragma unroll
        for (int j = 0; j < 8; j++) {
            const int m = mrow + i * 16;
            const int n = ncol + j * 8;
            *(float2*)(g_q2 + (size_t)m * 256 + n)       = make_float2(acc[i][j][0], acc[i][j][1]);
            *(float2*)(g_q2 + (size_t)(m + 8) * 256 + n) = make_float2(acc[i][j][2], acc[i][j][3]);
        }
    }
}

// =============================================================================
// attn_lite (R16 proven)
// =============================================================================
__global__ void __launch_bounds__(256, 2)
attn_lite(const int* __restrict__ item_seq,
          const float* __restrict__ q1_w, const float* __restrict__ q1_b,
          const float* __restrict__ v_w) {
    __shared__ float s_ht[Dn];
    __shared__ float s_part[Ln * 8];
    __shared__ float s_alpha[Ln + 2];
    __shared__ float s_mask[Ln + 2];
    __shared__ float s_red[8];
    __shared__ float s_bcast;
    __shared__ int   s_last;

    const int b = blockIdx.x;
    const int t = threadIdx.x;
    const int lane = t & 31, wid = t >> 5;

    if (t < Ln) s_mask[t] = (item_seq[b * Ln + t] > 0) ? 1.0f : 0.0f;
    if (t == 0) {
        int cnt = 0;
        for (int l = 0; l < Ln; l++) cnt += (item_seq[b * Ln + l] > 0) ? 1 : 0;
        s_last = max(cnt - 1, 0);
    }
    __syncthreads();
    s_ht[t] = g_seq_f32[((size_t)b * Ln + s_last) * Dn + t];
    __syncthreads();

    float q1v;
    {
        float a0 = 0.f, a1 = 0.f, a2 = 0.f, a3 = 0.f;
        #pragma unroll 4
        for (int d = 0; d < Dn; d += 4) {
            a0 += s_ht[d + 0] * q1_w[(d + 0) * Dn + t];
            a1 += s_ht[d + 1] * q1_w[(d + 1) * Dn + t];
            a2 += s_ht[d + 2] * q1_w[(d + 2) * Dn + t];
            a3 += s_ht[d + 3] * q1_w[(d + 3) * Dn + t];
        }
        q1v = (a0 + a1) + (a2 + a3) + q1_b[t];
    }

    const float vw = v_w[t];
    for (int l = 0; l < Ln; l++) {
        const float x = q1v + g_q2[((size_t)b * Ln + l) * Dn + t];
        float c = vw / (1.0f + expf(-x));
        #pragma unroll
        for (int o = 16; o > 0; o >>= 1) c += __shfl_xor_sync(0xffffffffu, c, o);
        if (lane == 0) s_part[l * 8 + wid] = c;
    }
    __syncthreads();
    if (t < Ln) {
        float a = 0.f;
        #pragma unroll
        for (int w = 0; w < 8; w++) a += s_part[t * 8 + w];
        s_alpha[t] = a * s_mask[t];
    }
    __syncthreads();

    float outacc = 0.f;
    #pragma unroll 5
    for (int l = 0; l < Ln; l++)
        outacc += s_alpha[l] * g_seq_f32[((size_t)b * Ln + l) * Dn + t];

    float ss = outacc * outacc;
    #pragma unroll
    for (int o = 16; o > 0; o >>= 1) ss += __shfl_xor_sync(0xffffffffu, ss, o);
    if (lane == 0) s_red[wid] = ss;
    __syncthreads();
    if (t == 0) {
        float a = 0.f;
        #pragma unroll
        for (int w = 0; w < 8; w++) a += s_red[w];
        s_bcast = a;
    }
    __syncthreads();
    const float inv = 1.0f / fmaxf(sqrtf(s_bcast), EPS);
    g_so_f16[(size_t)b * Dn + t] = __float2half_rn(outacc * inv);
}

// =============================================================================
// itemnorm: fp16 single output (R13 proven)
// =============================================================================
__global__ void __launch_bounds__(256)
itemnorm_kernel(const float* __restrict__ embedding, const int* __restrict__ item_cates) {
    const int i = blockIdx.x * 8 + (threadIdx.x >> 5);
    const int lane = threadIdx.x & 31;
    if (i >= ITEMN) return;
    const int c = item_cates[i];
    const float4 vi = ((const float4*)(embedding + (size_t)i * Hn))[lane];
    const float4 vc = ((const float4*)(embedding + (size_t)c * Hn))[lane];
    float ss = vi.x*vi.x + vi.y*vi.y + vi.z*vi.z + vi.w*vi.w
             + vc.x*vc.x + vc.y*vc.y + vc.z*vc.z + vc.w*vc.w;
    #pragma unroll
    for (int o = 16; o > 0; o >>= 1) ss += __shfl_xor_sync(0xffffffffu, ss, o);
    const float inv = 1.0f / fmaxf(sqrtf(ss), EPS);
    __half* dst = g_item_f16 + (size_t)i * Dn;
    *(__half2*)(dst + lane * 4)     = __floats2half2_rn(vi.x * inv, vi.y * inv);
    *(__half2*)(dst + lane * 4 + 2) = __floats2half2_rn(vi.z * inv, vi.w * inv);
    *(__half2*)(dst + 128 + lane * 4)     = __floats2half2_rn(vc.x * inv, vc.y * inv);
    *(__half2*)(dst + 128 + lane * 4 + 2) = __floats2half2_rn(vc.z * inv, vc.w * inv);
}

// =============================================================================
// scores: pure fp16 x fp16, 3-stage pipeline, smem-staged coalesced C stores.
// =============================================================================
#define SBUF (2 * MATB)
#define SCF_SMEM (3 * SBUF)    // 61440 >= 64*132*4 staging

__device__ __forceinline__ void sc_load_chunk(uint32_t nb, const __half* srcA,
    const __half* srcB, int k0, int ld_row0, int ld_row1, int ld_seg) {
    cp16(nb + 0 * MATB + ld_row0 * ROWB + ld_seg * 16, srcA + (size_t)ld_row0 * Dn + k0 + ld_seg * 8);
    cp16(nb + 0 * MATB + ld_row1 * ROWB + ld_seg * 16, srcA + (size_t)ld_row1 * Dn + k0 + ld_seg * 8);
    cp16(nb + 1 * MATB + ld_row0 * ROWB + ld_seg * 16, srcB + (size_t)ld_row0 * Dn + k0 + ld_seg * 8);
    cp16(nb + 1 * MATB + ld_row1 * ROWB + ld_seg * 16, srcB + (size_t)ld_row1 * Dn + k0 + ld_seg * 8);
}

__global__ void __launch_bounds__(256, 2)
scores_f16(float* __restrict__ C) {
    extern __shared__ char smc[];
    const uint32_t sb = smem_u32(smc);

    const int t = threadIdx.x;
    const int w = t >> 5, lane = t & 31;
    const int b0 = blockIdx.x * 128;
    const int i0 = blockIdx.y * 128;
    const int warp_m = w & 3;
    const int warp_n = w >> 2;

    const __half* srcA = g_item_f16 + (size_t)i0 * Dn;
    const __half* srcB = g_so_f16 + (size_t)b0 * Dn;
    const int ld_row0 = t >> 2, ld_row1 = 64 + (t >> 2), ld_seg = t & 3;

    float acc[2][8][4];
    #pragma unroll
    for (int i = 0; i < 2; i++)
        #pragma unroll
        for (int j = 0; j < 8; j++)
            #pragma unroll
            for (int r = 0; r < 4; r++) acc[i][j][r] = 0.f;

    const uint32_t aA_lane = (uint32_t)((lane & 15) * ROWB + (lane >> 4) * 16);
    const uint32_t aB_lane = (uint32_t)(((lane & 7) + ((lane >> 4) & 1) * 8) * ROWB
                                        + ((lane >> 3) & 1) * 16);

    sc_load_chunk(sb + 0 * SBUF, srcA, srcB, 0, ld_row0, ld_row1, ld_seg);
    CP_COMMIT();
    sc_load_chunk(sb + 1 * SBUF, srcA, srcB, 32, ld_row0, ld_row1, ld_seg);
    CP_COMMIT();

    int bufk = 0;
    for (int kc = 0; kc < 8; kc++) {
        if (kc < 6) {
            const int nbuf = (bufk + 2) % 3;
            sc_load_chunk(sb + (uint32_t)nbuf * SBUF, srcA, srcB, (kc + 2) * 32,
                          ld_row0, ld_row1, ld_seg);
            CP_COMMIT();
            CP_WAIT(2);
        } else if (kc == 6) {
            CP_WAIT(1);
        } else {
            CP_WAIT(0);
        }
        __syncthreads();

        const uint32_t baseA = sb + (uint32_t)bufk * SBUF + (uint32_t)(warp_m * 32) * ROWB + aA_lane;
        const uint32_t baseB = sb + (uint32_t)bufk * SBUF + MATB + (uint32_t)(warp_n * 64) * ROWB + aB_lane;

        #pragma unroll
        for (int ks = 0; ks < 2; ks++) {
            const uint32_t koff = (uint32_t)ks * 32;
            uint32_t af[2][4];
            #pragma unroll
            for (int i = 0; i < 2; i++)
                ldsm4(af[i], baseA + (uint32_t)(i * 16) * ROWB + koff);
            #pragma unroll
            for (int jg = 0; jg < 2; jg++) {
                uint32_t bf[2][4];
                #pragma unroll
                for (int j4 = 0; j4 < 2; j4++) {
                    const uint32_t off = (uint32_t)((jg * 2 + j4) * 16) * ROWB + koff;
                    ldsm4(bf[j4], baseB + off);
                }
                #pragma unroll
                for (int i = 0; i < 2; i++)
                    #pragma unroll
                    for (int jj = 0; jj < 4; jj++) {
                        const int j = jg * 4 + jj;
                        mma16816h(acc[i][j], af[i], &bf[jj >> 1][(jj & 1) * 2]);
                    }
            }
        }
        __syncthreads();
        bufk = (bufk + 1) % 3;
    }

    // epilogue: stage C tile through smem in 2 halves (64 batch rows), write
    // fully-coalesced float4 rows.
    float* s_c = (float*)smc;   // 64 x 132 floats = 33792 B
    #pragma unroll
    for (int h = 0; h < 2; h++) {
        if (warp_n == h) {
            #pragma unroll
            for (int i = 0; i < 2; i++)
                #pragma unroll
                for (int j = 0; j < 8; j++) {
                    const int nl = (lane & 3) * 2 + j * 8;
                    const int ml = warp_m * 32 + (lane >> 2) + i * 16;
                    s_c[nl * 132 + ml]           = 16.f * acc[i][j][0];
                    s_c[(nl + 1) * 132 + ml]     = 16.f * acc[i][j][1];
                    s_c[nl * 132 + ml + 8]       = 16.f * acc[i][j][2];
                    s_c[(nl + 1) * 132 + ml + 8] = 16.f * acc[i][j][3];
                }
        }
        __syncthreads();
        for (int it = t; it < 64 * 32; it += 256) {
            const int r = it >> 5, c4 = (it & 31) * 4;
            if (i0 + c4 < ITEMN) {
                const float4 v = *(const float4*)&s_c[r * 132 + c4];
                *(float4*)(C + (size_t)(b0 + h * 64 + r) * ITEMN + i0 + c4) = v;
            }
        }
        __syncthreads();
    }
}

// =============================================================================
// launch — no device symbols passed as kernel args.
// =============================================================================
extern "C" void kernel_launch(void* const* d_in, const int* in_sizes, int n_in,
                              void* d_out, int out_size) {
    const int*   item_seq   = (const int*)  d_in[0];
    /* label d_in[1] unused */
    const int*   nodes      = (const int*)  d_in[2];
    const float* hn_adj     = (const float*)d_in[3];
    const int*   alias_item = (const int*)  d_in[4];
    const int*   alias_cate = (const int*)  d_in[5];
    const float* embedding  = (const float*)d_in[6];
    const int*   item_cates = (const int*)  d_in[7];
    const float* w_edge     = (const float*)d_in[8];
    const float* w_node     = (const float*)d_in[9];
    const float* q1_w       = (const float*)d_in[10];
    const float* q1_b       = (const float*)d_in[11];
    const float* q2_w       = (const float*)d_in[12];
    const float* v_w        = (const float*)d_in[13];
    float* out = (float*)d_out;

    cudaFuncSetAttribute(hgnn_mma,    cudaFuncAttributeMaxDynamicSharedMemorySize, HGM_SMEM);
    cudaFuncSetAttribute(gemm_q2_f16, cudaFuncAttributeMaxDynamicSharedMemorySize, Q2_SMEM);
    cudaFuncSetAttribute(scores_f16,  cudaFuncAttributeMaxDynamicSharedMemorySize, SCF_SMEM);

    prep_w<<<384, 256>>>(w_edge, w_node, q2_w);
    itemnorm_kernel<<<(ITEMN + 7) / 8, 256>>>(embedding, item_cates);
    hgnn_mma<<<Bn, 256, HGM_SMEM>>>(nodes, hn_adj, embedding);

    seqbuild<<<Bn * Ln / 8, 256>>>(alias_item, alias_cate);
    gemm_q2_f16<<<dim3(Bn * Ln / 128, 2), 256, Q2_SMEM>>>();
    attn_lite<<<Bn, 256>>>(item_seq, q1_w, q1_b, v_w);

    scores_f16<<<dim3(4, ITEMP / 128), 256, SCF_SMEM>>>(out);
}